// round 11
// baseline (speedup 1.0000x reference)
#include <cuda_runtime.h>
#include <cuda_bf16.h>
#include <math_constants.h>
#include <cstdint>

// Problem constants
#define Bc   32
#define Sc   511
#define Tc   512
#define Dc   512
#define Hc   8
#define HDc  64
#define Lc   4
#define PDc  32
#define FDc  448     // D - 2*PD
#define DFFc 2048
#define Mc   (Bc*Tc) // 16384 tokens
#define QP   1536    // qkv combined pitch
#define KSP  2048    // split K/V pitch: [Khi 512 | Klo 512 | Vhi 512 | Vlo 512]

// ---------------- scratch (device globals; no allocation allowed) ----------
__device__ float g_x   [Mc*Dc];
__device__ float g_att [Mc*Dc];
__device__ float g_tmp [Mc*Dc];
__device__ float g_ff  [Mc*DFFc];      // doubles as qkv buffer [Mc][1536]
__device__ float g_ksp [Mc*KSP];       // pre-split K/V hi-lo planes
__device__ float g_wqkv[Lc*Dc*QP];
__device__ float g_bqkv[Lc*QP];

// ---------------- weight packing --------------------------------------------
__global__ __launch_bounds__(512)
void pack_qkv_kernel(const float* __restrict__ Wq, const float* __restrict__ Wk,
                     const float* __restrict__ Wv, float* __restrict__ Wqkv)
{
    int lk = blockIdx.x;
    int j  = threadIdx.x;
    size_t src = (size_t)lk*Dc + j;
    size_t dst = (size_t)lk*QP + j;
    Wqkv[dst        ] = Wq[src];
    Wqkv[dst + Dc   ] = Wk[src];
    Wqkv[dst + 2*Dc ] = Wv[src];
}
__global__ __launch_bounds__(512)
void pack_bqkv_kernel(const float* __restrict__ bq, const float* __restrict__ bk,
                      const float* __restrict__ bv, float* __restrict__ bqkv)
{
    int l = blockIdx.x;
    int j = threadIdx.x;
    bqkv[l*QP + j       ] = bq[l*Dc + j];
    bqkv[l*QP + j + Dc  ] = bk[l*Dc + j];
    bqkv[l*QP + j + 2*Dc] = bv[l*Dc + j];
}

// ---------------- embedding + positional encoding ---------------------------
__global__ void embed_kernel(const float* __restrict__ runs,
                             const float* __restrict__ wickets,
                             const float* __restrict__ overs,
                             const int*   __restrict__ batters,
                             const int*   __restrict__ bowlers,
                             const float* __restrict__ pemb,
                             const float* __restrict__ Wf,
                             const float* __restrict__ bf,
                             const float* __restrict__ qtok,
                             float* __restrict__ x)
{
    int bt = blockIdx.x;
    int b  = bt / Tc;
    int t  = bt % Tc;
    int j  = threadIdx.x;

    float val;
    if (t < Sc) {
        if (j < FDc) {
            float r = runs   [b*Sc + t];
            float w = wickets[b*Sc + t];
            float o = overs  [b*Sc + t];
            val = r*Wf[j] + w*Wf[FDc + j] + o*Wf[2*FDc + j] + bf[j];
        } else if (j < FDc + PDc) {
            val = pemb[batters[b*Sc + t]*PDc + (j - FDc)];
        } else {
            val = pemb[bowlers[b*Sc + t]*PDc + (j - FDc - PDc)];
        }
    } else {
        val = qtok[j];
    }
    int   i2  = j & ~1;
    float dv  = expf((float)i2 * -0.0179889460390111f);
    float ang = (float)t * dv;
    val += (j & 1) ? cosf(ang) : sinf(ang);
    x[(b*Tc + t)*Dc + j] = val;
}

// ---------------- helpers -----------------------------------------------------
__device__ __forceinline__ uint32_t smem_u32(const void* p) {
    return (uint32_t)__cvta_generic_to_shared(p);
}
#define MMA_TF32(ACC, A0,A1,A2,A3, B0,B1) \
    asm volatile( \
        "mma.sync.aligned.m16n8k8.row.col.f32.tf32.tf32.f32 " \
        "{%0,%1,%2,%3}, {%4,%5,%6,%7}, {%8,%9}, {%0,%1,%2,%3};\n" \
        : "+f"((ACC)[0]), "+f"((ACC)[1]), "+f"((ACC)[2]), "+f"((ACC)[3]) \
        : "r"(A0), "r"(A1), "r"(A2), "r"(A3), "r"(B0), "r"(B1))
__device__ __forceinline__ uint32_t tf32_hi(float v) {
    uint32_t r; asm("cvt.rna.tf32.f32 %0, %1;" : "=r"(r) : "f"(v)); return r;
}
__device__ __forceinline__ void tf32_split(float v, uint32_t& hi, uint32_t& lo) {
    hi = tf32_hi(v);
    lo = tf32_hi(v - __uint_as_float(hi));
}

// ---------------- tf32 tensor-core GEMM, 3-stage cp.async, 1 sync/chunk ------
// EPI: 0 = bias only, 1 = bias + exact GELU,
//      2 = bias + additionally write pre-split hi/lo planes for K/V columns
#define TBM 128
#define TBN 128
#define TBK 32
#define AST 36
#define BST 136
#define TG_ST 3
#define TGEMM_SMEM ((TG_ST*TBM*AST + TG_ST*32*BST)*4)

__device__ __forceinline__ void tg_load_stage(
    const float* __restrict__ A, const float* __restrict__ W,
    float* __restrict__ As, float* __restrict__ Bs,
    int bm, int bn, int k0, int K, int N, int tid)
{
    int ar = tid >> 3, aq = tid & 7;
    const float* ap = A + (size_t)(bm*TBM + ar)*K + k0 + aq*4;
    uint32_t ad = smem_u32(As + ar*AST + aq*4);
    #pragma unroll
    for (int i = 0; i < 4; i++) {
        asm volatile("cp.async.cg.shared.global [%0], [%1], 16;\n"
                     :: "r"(ad + i*32*AST*4), "l"(ap + (size_t)i*32*K));
    }
    int br = tid >> 5, bq = tid & 31;
    const float* bp = W + (size_t)(k0 + br)*N + bn*TBN + bq*4;
    uint32_t bd = smem_u32(Bs + br*BST + bq*4);
    #pragma unroll
    for (int i = 0; i < 4; i++) {
        asm volatile("cp.async.cg.shared.global [%0], [%1], 16;\n"
                     :: "r"(bd + i*8*BST*4), "l"(bp + (size_t)i*8*N));
    }
    asm volatile("cp.async.commit_group;\n");
}

__device__ __forceinline__ void ksp_store2(float* __restrict__ ksp,
                                           int row, int c, float va, float vb)
{
    // c in [512, 1536): K columns [512,1024), V columns [1024,1536)
    int cl = c - Dc;
    int hi_off = (cl < 512) ? cl        : cl + 512;
    int lo_off = (cl < 512) ? cl + 512  : cl + 1024;
    uint32_t ha, la, hb, lb;
    tf32_split(va, ha, la);
    tf32_split(vb, hb, lb);
    float2 hv; hv.x = __uint_as_float(ha); hv.y = __uint_as_float(hb);
    float2 lv; lv.x = __uint_as_float(la); lv.y = __uint_as_float(lb);
    size_t base = (size_t)row*KSP;
    *(float2*)&ksp[base + hi_off] = hv;
    *(float2*)&ksp[base + lo_off] = lv;
}

template<int EPI>
__global__ __launch_bounds__(256, 2)
void tgemm_kernel(const float* __restrict__ A, const float* __restrict__ W,
                  const float* __restrict__ bias, float* __restrict__ C,
                  int M, int N, int K, float* __restrict__ ksp)
{
    extern __shared__ float sm[];
    float* As = sm;
    float* Bs = sm + TG_ST*TBM*AST;

    int tid = threadIdx.x;
    int bm = blockIdx.y, bn = blockIdx.x;
    int w = tid >> 5, lane = tid & 31;
    int gid = lane >> 2, tig = lane & 3;
    int wm = w >> 2, wn = w & 3;

    float acc[4][4][4];
    #pragma unroll
    for (int i = 0; i < 4; i++)
        #pragma unroll
        for (int j = 0; j < 4; j++)
            #pragma unroll
            for (int r = 0; r < 4; r++) acc[i][j][r] = 0.f;

    int nkt = K / TBK;
    tg_load_stage(A, W, As, Bs, bm, bn, 0, K, N, tid);
    if (nkt > 1)
        tg_load_stage(A, W, As + TBM*AST, Bs + 32*BST, bm, bn, TBK, K, N, tid);

    for (int kt = 0; kt < nkt; ++kt) {
        if (kt + 1 < nkt) asm volatile("cp.async.wait_group 1;\n");
        else              asm volatile("cp.async.wait_group 0;\n");
        __syncthreads();
        if (kt + 2 < nkt) {
            int nxt = (kt + 2) % TG_ST;
            tg_load_stage(A, W, As + nxt*TBM*AST, Bs + nxt*32*BST,
                          bm, bn, (kt+2)*TBK, K, N, tid);
        }

        const float* Asc = As + (kt % TG_ST)*TBM*AST;
        const float* Bsc = Bs + (kt % TG_ST)*32*BST;

        #pragma unroll
        for (int kc = 0; kc < 4; ++kc) {
            uint32_t a[4][4], b[4][2];
            #pragma unroll
            for (int i = 0; i < 4; i++) {
                int r0 = wm*64 + 16*i + gid;
                a[i][0] = __float_as_uint(Asc[(r0    )*AST + kc*8 + tig    ]);
                a[i][1] = __float_as_uint(Asc[(r0 + 8)*AST + kc*8 + tig    ]);
                a[i][2] = __float_as_uint(Asc[(r0    )*AST + kc*8 + tig + 4]);
                a[i][3] = __float_as_uint(Asc[(r0 + 8)*AST + kc*8 + tig + 4]);
            }
            #pragma unroll
            for (int j = 0; j < 4; j++) {
                int c0 = wn*32 + 8*j + gid;
                b[j][0] = __float_as_uint(Bsc[(kc*8 + tig    )*BST + c0]);
                b[j][1] = __float_as_uint(Bsc[(kc*8 + tig + 4)*BST + c0]);
            }
            #pragma unroll
            for (int i = 0; i < 4; i++)
                #pragma unroll
                for (int j = 0; j < 4; j++)
                    MMA_TF32(acc[i][j], a[i][0], a[i][1], a[i][2], a[i][3],
                             b[j][0], b[j][1]);
        }
    }

    #pragma unroll
    for (int i = 0; i < 4; i++) {
        int r = bm*TBM + wm*64 + 16*i + gid;
        #pragma unroll
        for (int j = 0; j < 4; j++) {
            int c = bn*TBN + wn*32 + 8*j + 2*tig;
            float bx = bias[c], by = bias[c+1];
            float v0 = acc[i][j][0] + bx;
            float v1 = acc[i][j][1] + by;
            float v2 = acc[i][j][2] + bx;
            float v3 = acc[i][j][3] + by;
            if (EPI == 1) {
                v0 = 0.5f*v0*(1.0f + erff(v0*0.70710678118654752f));
                v1 = 0.5f*v1*(1.0f + erff(v1*0.70710678118654752f));
                v2 = 0.5f*v2*(1.0f + erff(v2*0.70710678118654752f));
                v3 = 0.5f*v3*(1.0f + erff(v3*0.70710678118654752f));
            }
            float2 p0; p0.x = v0; p0.y = v1;
            float2 p1; p1.x = v2; p1.y = v3;
            *(float2*)&C[(size_t)r*N + c]       = p0;
            *(float2*)&C[(size_t)(r+8)*N + c]   = p1;
            if (EPI == 2 && c >= Dc) {
                ksp_store2(ksp, r,   c, v0, v1);
                ksp_store2(ksp, r+8, c, v2, v3);
            }
        }
    }
}

// ---------------- fused attention v7: pre-split K/V planes -------------------
// 32 q rows/block, grid (16,H,B), 256 threads, 64-key chunks, single pass.
// K/V staging is pure float4 copies from g_ksp (splits done in QKV epilogue).
#define ATTN7_SMEM (27072*4)

__global__ __launch_bounds__(256)
void attn7_kernel(const float* __restrict__ qkv, const float* __restrict__ ksp,
                  const int* __restrict__ batters, const int* __restrict__ bowlers,
                  const float* __restrict__ rec_s, const float* __restrict__ bow_s,
                  const float* __restrict__ bat_s, int layer,
                  float* __restrict__ Og)
{
    extern __shared__ float sm[];
    float* Qhi = sm;
    float* Qlo = sm + 2176;
    float* Khi = sm + 4352;
    float* Klo = sm + 8704;
    float* Vhi = sm + 13056;
    float* Vlo = sm + 17664;
    float* Phi = sm + 22272;
    float* Plo = sm + 24448;
    float* Mp  = sm + 26624;
    float* Sp  = sm + 26752;
    int*   ib  = (int*)(sm + 26880);
    int* bowQ = ib;       int* batQ = ib + 32;
    int* bowK = ib + 64;  int* batK = ib + 128;

    int qt = blockIdx.x, h = blockIdx.y, b = blockIdx.z;
    int tid = threadIdx.x;
    int q0 = qt*32;
    int w = tid >> 5, lane = tid & 31;
    int gid = lane >> 2, tig = lane & 3;
    int mi = w >> 2, nq = w & 3;
    int r1 = mi*16 + gid, r2 = r1 + 8;

    const float* Q = qkv;

    // stage Q split hi/lo (once)
    #pragma unroll
    for (int it = 0; it < 2; ++it) {
        int idx = tid + it*256;
        int q = idx >> 4, d4 = idx & 15;
        float4 v = *(const float4*)&Q[(size_t)(b*Tc + q0 + q)*QP + h*HDc + d4*4];
        uint32_t h0,l0,h1,l1,h2,l2,h3,l3;
        tf32_split(v.x, h0, l0); tf32_split(v.y, h1, l1);
        tf32_split(v.z, h2, l2); tf32_split(v.w, h3, l3);
        float4 hv, lv;
        hv.x = __uint_as_float(h0); hv.y = __uint_as_float(h1);
        hv.z = __uint_as_float(h2); hv.w = __uint_as_float(h3);
        lv.x = __uint_as_float(l0); lv.y = __uint_as_float(l1);
        lv.z = __uint_as_float(l2); lv.w = __uint_as_float(l3);
        *(float4*)&Qhi[q*68 + d4*4] = hv;
        *(float4*)&Qlo[q*68 + d4*4] = lv;
    }
    if (tid < 32) {
        int qg = q0 + tid;
        bowQ[tid] = (qg < Sc) ? bowlers[b*Sc + qg] : -1;
        batQ[tid] = (qg < Sc) ? batters[b*Sc + qg] : -1;
    }

    int ktmax = (q0 + 32 + 63) >> 6;
    const float scl  = 0.125f;
    const float recw = rec_s[layer];
    const float boww = bow_s[layer];
    const float batw = bat_s[layer];

    int qg1 = q0 + r1, qg2 = q0 + r2;

    float oacc[2][4] = {{0,0,0,0},{0,0,0,0}};
    float mrun1 = -1e30f, mrun2 = -1e30f;
    float srun1 = 0.f,    srun2 = 0.f;

    for (int kt = 0; kt < ktmax; ++kt) {
        int k0 = kt << 6;

        // ---- stage K hi/lo: pure copies ----
        #pragma unroll
        for (int it = 0; it < 4; ++it) {
            int idx = tid + it*256;
            int kk = idx >> 4, d4 = idx & 15;
            size_t rb = (size_t)(b*Tc + k0 + kk)*KSP + h*HDc + d4*4;
            *(float4*)&Khi[kk*68 + d4*4] = *(const float4*)&ksp[rb];
            *(float4*)&Klo[kk*68 + d4*4] = *(const float4*)&ksp[rb + 512];
        }
        if (tid < 64) {
            int kg = k0 + tid;
            bowK[tid] = (kg < Sc) ? bowlers[b*Sc + kg] : -2;
            batK[tid] = (kg < Sc) ? batters[b*Sc + kg] : -2;
        }
        __syncthreads();   // S1: K staged; all warps past prev AV

        // ---- score MMA ----
        float acc[2][4] = {{0,0,0,0},{0,0,0,0}};
        #pragma unroll
        for (int kc = 0; kc < 8; ++kc) {
            int ra = r1*68 + kc*8 + tig;
            uint32_t ah0 = __float_as_uint(Qhi[ra]);
            uint32_t ah1 = __float_as_uint(Qhi[ra + 8*68]);
            uint32_t ah2 = __float_as_uint(Qhi[ra + 4]);
            uint32_t ah3 = __float_as_uint(Qhi[ra + 8*68 + 4]);
            uint32_t al0 = __float_as_uint(Qlo[ra]);
            uint32_t al1 = __float_as_uint(Qlo[ra + 8*68]);
            uint32_t al2 = __float_as_uint(Qlo[ra + 4]);
            uint32_t al3 = __float_as_uint(Qlo[ra + 8*68 + 4]);
            #pragma unroll
            for (int j = 0; j < 2; ++j) {
                int rb = (nq*16 + j*8 + gid)*68 + kc*8 + tig;
                uint32_t bh0 = __float_as_uint(Khi[rb]);
                uint32_t bh1 = __float_as_uint(Khi[rb + 4]);
                uint32_t bl0 = __float_as_uint(Klo[rb]);
                uint32_t bl1 = __float_as_uint(Klo[rb + 4]);
                MMA_TF32(acc[j], ah0, ah1, ah2, ah3, bl0, bl1);
                MMA_TF32(acc[j], al0, al1, al2, al3, bh0, bh1);
                MMA_TF32(acc[j], ah0, ah1, ah2, ah3, bh0, bh1);
            }
        }

        // ---- stage V hi/lo: pure copies (V buffers free after S1) ----
        #pragma unroll
        for (int it = 0; it < 4; ++it) {
            int idx = tid + it*256;
            int kk = idx >> 4, d4 = idx & 15;
            size_t rb = (size_t)(b*Tc + k0 + kk)*KSP + h*HDc + d4*4;
            *(float4*)&Vhi[kk*72 + d4*4] = *(const float4*)&ksp[rb + 1024];
            *(float4*)&Vlo[kk*72 + d4*4] = *(const float4*)&ksp[rb + 1536];
        }

        // ---- score epilogue: scale + bias + causal ----
        float sv[2][4];
        int bq1 = bowQ[r1], aq1 = batQ[r1];
        int bq2 = bowQ[r2], aq2 = batQ[r2];
        #pragma unroll
        for (int j = 0; j < 2; ++j) {
            int kl = nq*16 + j*8 + 2*tig;
            int kg = k0 + kl;
            float s00 = acc[j][0]*scl, s01 = acc[j][1]*scl;
            float s10 = acc[j][2]*scl, s11 = acc[j][3]*scl;
            if (h == 0) {
                s00 += recw * (float)kg     * (1.0f/512.0f);
                s01 += recw * (float)(kg+1) * (1.0f/512.0f);
                s10 += recw * (float)kg     * (1.0f/512.0f);
                s11 += recw * (float)(kg+1) * (1.0f/512.0f);
            } else if (h == 1) {
                int k1b = bowK[kl], k2b = bowK[kl+1];
                if (qg1 == Sc || kg   == Sc || bq1 == k1b) s00 += boww;
                if (qg1 == Sc || kg+1 == Sc || bq1 == k2b) s01 += boww;
                if (qg2 == Sc || kg   == Sc || bq2 == k1b) s10 += boww;
                if (qg2 == Sc || kg+1 == Sc || bq2 == k2b) s11 += boww;
            } else if (h == 2) {
                int k1a = batK[kl], k2a = batK[kl+1];
                if (qg1 == Sc || kg   == Sc || aq1 == k1a) s00 += batw;
                if (qg1 == Sc || kg+1 == Sc || aq1 == k2a) s01 += batw;
                if (qg2 == Sc || kg   == Sc || aq2 == k1a) s10 += batw;
                if (qg2 == Sc || kg+1 == Sc || aq2 == k2a) s11 += batw;
            }
            if (kg   > qg1) s00 = -1e30f;
            if (kg+1 > qg1) s01 = -1e30f;
            if (kg   > qg2) s10 = -1e30f;
            if (kg+1 > qg2) s11 = -1e30f;
            sv[j][0] = s00; sv[j][1] = s01; sv[j][2] = s10; sv[j][3] = s11;
        }

        // ---- chunk row-max ----
        float rm1 = fmaxf(fmaxf(sv[0][0], sv[0][1]), fmaxf(sv[1][0], sv[1][1]));
        float rm2 = fmaxf(fmaxf(sv[0][2], sv[0][3]), fmaxf(sv[1][2], sv[1][3]));
        rm1 = fmaxf(rm1, __shfl_xor_sync(0xffffffffu, rm1, 1));
        rm1 = fmaxf(rm1, __shfl_xor_sync(0xffffffffu, rm1, 2));
        rm2 = fmaxf(rm2, __shfl_xor_sync(0xffffffffu, rm2, 1));
        rm2 = fmaxf(rm2, __shfl_xor_sync(0xffffffffu, rm2, 2));
        if (tig == 0) { Mp[r1*4 + nq] = rm1; Mp[r2*4 + nq] = rm2; }
        __syncthreads();   // S2a: Mp visible + V staging complete

        float4 m4a = *(const float4*)&Mp[r1*4];
        float4 m4b = *(const float4*)&Mp[r2*4];
        float mc1 = fmaxf(fmaxf(m4a.x, m4a.y), fmaxf(m4a.z, m4a.w));
        float mc2 = fmaxf(fmaxf(m4b.x, m4b.y), fmaxf(m4b.z, m4b.w));
        float mnew1 = fmaxf(mrun1, mc1);
        float mnew2 = fmaxf(mrun2, mc2);
        float f1 = __expf(mrun1 - mnew1);
        float f2 = __expf(mrun2 - mnew2);

        // ---- exp, write P split hi/lo, partial sums ----
        float ps1 = 0.f, ps2 = 0.f;
        #pragma unroll
        for (int j = 0; j < 2; ++j) {
            int col = nq*16 + j*8 + 2*tig;
            float e00 = __expf(sv[j][0] - mnew1);
            float e01 = __expf(sv[j][1] - mnew1);
            float e10 = __expf(sv[j][2] - mnew2);
            float e11 = __expf(sv[j][3] - mnew2);
            ps1 += e00 + e01;
            ps2 += e10 + e11;
            uint32_t h0,l0,h1,l1;
            tf32_split(e00, h0, l0); tf32_split(e01, h1, l1);
            float2 hv, lv;
            hv.x = __uint_as_float(h0); hv.y = __uint_as_float(h1);
            lv.x = __uint_as_float(l0); lv.y = __uint_as_float(l1);
            *(float2*)&Phi[r1*68 + col] = hv;
            *(float2*)&Plo[r1*68 + col] = lv;
            tf32_split(e10, h0, l0); tf32_split(e11, h1, l1);
            hv.x = __uint_as_float(h0); hv.y = __uint_as_float(h1);
            lv.x = __uint_as_float(l0); lv.y = __uint_as_float(l1);
            *(float2*)&Phi[r2*68 + col] = hv;
            *(float2*)&Plo[r2*68 + col] = lv;
        }
        ps1 += __shfl_xor_sync(0xffffffffu, ps1, 1);
        ps1 += __shfl_xor_sync(0xffffffffu, ps1, 2);
        ps2 += __shfl_xor_sync(0xffffffffu, ps2, 1);
        ps2 += __shfl_xor_sync(0xffffffffu, ps2, 2);
        if (tig == 0) { Sp[r1*4 + nq] = ps1; Sp[r2*4 + nq] = ps2; }

        oacc[0][0] *= f1; oacc[0][1] *= f1; oacc[1][0] *= f1; oacc[1][1] *= f1;
        oacc[0][2] *= f2; oacc[0][3] *= f2; oacc[1][2] *= f2; oacc[1][3] *= f2;
        mrun1 = mnew1; mrun2 = mnew2;
        __syncthreads();   // S2b: P + Sp visible

        float4 s4a = *(const float4*)&Sp[r1*4];
        float4 s4b = *(const float4*)&Sp[r2*4];
        srun1 = srun1*f1 + (s4a.x + s4a.y + s4a.z + s4a.w);
        srun2 = srun2*f2 + (s4b.x + s4b.y + s4b.z + s4b.w);

        // ---- AV MMA (unnormalized) ----
        #pragma unroll
        for (int kc = 0; kc < 8; ++kc) {
            int pa1 = r1*68 + kc*8 + tig;
            int pa2 = r2*68 + kc*8 + tig;
            uint32_t ah0 = __float_as_uint(Phi[pa1]);
            uint32_t ah1 = __float_as_uint(Phi[pa2]);
            uint32_t ah2 = __float_as_uint(Phi[pa1 + 4]);
            uint32_t ah3 = __float_as_uint(Phi[pa2 + 4]);
            uint32_t al0 = __float_as_uint(Plo[pa1]);
            uint32_t al1 = __float_as_uint(Plo[pa2]);
            uint32_t al2 = __float_as_uint(Plo[pa1 + 4]);
            uint32_t al3 = __float_as_uint(Plo[pa2 + 4]);
            #pragma unroll
            for (int j = 0; j < 2; ++j) {
                int n0 = (nq*2 + j)*8;
                int vb0 = (kc*8 + tig    )*72 + n0 + gid;
                int vb1 = (kc*8 + tig + 4)*72 + n0 + gid;
                uint32_t bh0 = __float_as_uint(Vhi[vb0]);
                uint32_t bh1 = __float_as_uint(Vhi[vb1]);
                uint32_t bl0 = __float_as_uint(Vlo[vb0]);
                uint32_t bl1 = __float_as_uint(Vlo[vb1]);
                MMA_TF32(oacc[j], ah0, ah1, ah2, ah3, bl0, bl1);
                MMA_TF32(oacc[j], al0, al1, al2, al3, bh0, bh1);
                MMA_TF32(oacc[j], ah0, ah1, ah2, ah3, bh0, bh1);
            }
        }
    }

    float inv1 = 1.0f / srun1;
    float inv2 = 1.0f / srun2;
    #pragma unroll
    for (int j = 0; j < 2; ++j) {
        int col = (nq*2 + j)*8 + 2*tig;
        float2 o1; o1.x = oacc[j][0]*inv1; o1.y = oacc[j][1]*inv1;
        float2 o2; o2.x = oacc[j][2]*inv2; o2.y = oacc[j][3]*inv2;
        *(float2*)&Og[(size_t)(b*Tc + q0 + r1)*Dc + h*HDc + col] = o1;
        *(float2*)&Og[(size_t)(b*Tc + q0 + r2)*Dc + h*HDc + col] = o2;
    }
}

// ---------------- residual add + LayerNorm: warp-per-token -------------------
__global__ __launch_bounds__(256)
void add_ln_kernel(float* __restrict__ x, const float* __restrict__ r,
                   const float* __restrict__ g, const float* __restrict__ be)
{
    int w = threadIdx.x >> 5;
    int lane = threadIdx.x & 31;
    size_t tok = (size_t)blockIdx.x*8 + w;
    float* xr = x + tok*Dc;
    const float* rr = r + tok*Dc;

    float4 v[4];
    float s = 0.f, s2 = 0.f;
    #pragma unroll
    for (int i = 0; i < 4; ++i) {
        int c = (lane + i*32)*4;
        float4 xv = *(const float4*)&xr[c];
        float4 rv = *(const float4*)&rr[c];
        xv.x += rv.x; xv.y += rv.y; xv.z += rv.z; xv.w += rv.w;
        v[i] = xv;
        s  += xv.x + xv.y + xv.z + xv.w;
        s2 += xv.x*xv.x + xv.y*xv.y + xv.z*xv.z + xv.w*xv.w;
    }
    #pragma unroll
    for (int o = 16; o; o >>= 1) {
        s  += __shfl_xor_sync(0xffffffffu, s,  o);
        s2 += __shfl_xor_sync(0xffffffffu, s2, o);
    }
    float mu  = s * (1.0f/512.0f);
    float var = s2 * (1.0f/512.0f) - mu*mu;
    float rs  = rsqrtf(var + 1e-5f);
    #pragma unroll
    for (int i = 0; i < 4; ++i) {
        int c = (lane + i*32)*4;
        float4 gv = *(const float4*)&g[c];
        float4 bv = *(const float4*)&be[c];
        float4 y;
        y.x = (v[i].x - mu)*rs*gv.x + bv.x;
        y.y = (v[i].y - mu)*rs*gv.y + bv.y;
        y.z = (v[i].z - mu)*rs*gv.z + bv.z;
        y.w = (v[i].w - mu)*rs*gv.w + bv.w;
        *(float4*)&xr[c] = y;
    }
}

// ---------------- output head: out[b] = x[b, T-1] @ Wout + bout -------------
__global__ __launch_bounds__(512)
void out_kernel(const float* __restrict__ x, const float* __restrict__ Wout,
                const float* __restrict__ bout, float* __restrict__ out)
{
    int b = blockIdx.x;
    int n = threadIdx.x;
    __shared__ float xs[512];
    xs[n] = x[(size_t)(b*Tc + Tc - 1)*Dc + n];
    __syncthreads();
    float acc = bout[n];
    #pragma unroll 8
    for (int d = 0; d < Dc; ++d)
        acc += xs[d] * Wout[(size_t)d*Dc + n];
    out[b*Dc + n] = acc;
}

// ---------------- launcher ---------------------------------------------------
extern "C" void kernel_launch(void* const* d_in, const int* in_sizes, int n_in,
                              void* d_out, int out_size)
{
    const float* runs    = (const float*)d_in[0];
    const float* wickets = (const float*)d_in[1];
    const float* overs   = (const float*)d_in[2];
    const int*   batters = (const int*)  d_in[3];
    const int*   bowlers = (const int*)  d_in[4];
    const float* pemb    = (const float*)d_in[5];
    const float* Wf      = (const float*)d_in[6];
    const float* bf      = (const float*)d_in[7];
    const float* qtok    = (const float*)d_in[8];
    const float* Wq      = (const float*)d_in[9];
    const float* bq      = (const float*)d_in[10];
    const float* Wk      = (const float*)d_in[11];
    const float* bk      = (const float*)d_in[12];
    const float* Wv      = (const float*)d_in[13];
    const float* bv      = (const float*)d_in[14];
    const float* Wo      = (const float*)d_in[15];
    const float* bo      = (const float*)d_in[16];
    const float* rec_s   = (const float*)d_in[17];
    const float* bow_s   = (const float*)d_in[18];
    const float* bat_s   = (const float*)d_in[19];
    const float* W1      = (const float*)d_in[20];
    const float* b1      = (const float*)d_in[21];
    const float* W2      = (const float*)d_in[22];
    const float* b2      = (const float*)d_in[23];
    const float* g1      = (const float*)d_in[24];
    const float* be1     = (const float*)d_in[25];
    const float* g2      = (const float*)d_in[26];
    const float* be2     = (const float*)d_in[27];
    const float* Wout    = (const float*)d_in[28];
    const float* bout    = (const float*)d_in[29];
    float* out = (float*)d_out;

    float *x_, *att_, *tmp_, *ff_, *ksp_, *wqkv_, *bqkv_;
    cudaGetSymbolAddress((void**)&x_,    g_x);
    cudaGetSymbolAddress((void**)&att_,  g_att);
    cudaGetSymbolAddress((void**)&tmp_,  g_tmp);
    cudaGetSymbolAddress((void**)&ff_,   g_ff);
    cudaGetSymbolAddress((void**)&ksp_,  g_ksp);
    cudaGetSymbolAddress((void**)&wqkv_, g_wqkv);
    cudaGetSymbolAddress((void**)&bqkv_, g_bqkv);

    cudaFuncSetAttribute(attn7_kernel,
                         cudaFuncAttributeMaxDynamicSharedMemorySize, ATTN7_SMEM);
    cudaFuncSetAttribute(tgemm_kernel<0>,
                         cudaFuncAttributeMaxDynamicSharedMemorySize, TGEMM_SMEM);
    cudaFuncSetAttribute(tgemm_kernel<1>,
                         cudaFuncAttributeMaxDynamicSharedMemorySize, TGEMM_SMEM);
    cudaFuncSetAttribute(tgemm_kernel<2>,
                         cudaFuncAttributeMaxDynamicSharedMemorySize, TGEMM_SMEM);

    pack_qkv_kernel<<<Lc*Dc, 512>>>(Wq, Wk, Wv, wqkv_);
    pack_bqkv_kernel<<<Lc, 512>>>(bq, bk, bv, bqkv_);

    embed_kernel<<<Bc*Tc, 512>>>(runs, wickets, overs, batters, bowlers,
                                 pemb, Wf, bf, qtok, x_);

    dim3 g512 (Dc/TBN,   Mc/TBM);   // (4, 128)
    dim3 gQKV (QP/TBN,   Mc/TBM);   // (12, 128)
    dim3 g2048(DFFc/TBN, Mc/TBM);   // (16, 128)
    dim3 gattn(16, Hc, Bc);

    for (int l = 0; l < Lc; ++l) {
        tgemm_kernel<2><<<gQKV, 256, TGEMM_SMEM>>>(x_, wqkv_ + (size_t)l*Dc*QP,
                                                   bqkv_ + l*QP, ff_, Mc, QP, Dc, ksp_);

        attn7_kernel<<<gattn, 256, ATTN7_SMEM>>>(ff_, ksp_, batters, bowlers,
                                                 rec_s, bow_s, bat_s, l, att_);

        tgemm_kernel<0><<<g512, 256, TGEMM_SMEM>>>(att_, Wo + (size_t)l*Dc*Dc,
                                                   bo + l*Dc, tmp_, Mc, Dc, Dc, nullptr);
        add_ln_kernel<<<Mc/8, 256>>>(x_, tmp_, g1 + l*Dc, be1 + l*Dc);

        tgemm_kernel<1><<<g2048, 256, TGEMM_SMEM>>>(x_, W1 + (size_t)l*Dc*DFFc,
                                                    b1 + l*DFFc, ff_, Mc, DFFc, Dc, nullptr);
        tgemm_kernel<0><<<g512, 256, TGEMM_SMEM>>>(ff_, W2 + (size_t)l*DFFc*Dc,
                                                   b2 + l*Dc, tmp_, Mc, Dc, DFFc, nullptr);
        add_ln_kernel<<<Mc/8, 256>>>(x_, tmp_, g2 + l*Dc, be2 + l*Dc);
    }

    out_kernel<<<Bc, 512>>>(x_, Wout, bout, out);
}

// round 12
// speedup vs baseline: 1.0067x; 1.0067x over previous
#include <cuda_runtime.h>
#include <cuda_bf16.h>
#include <math_constants.h>
#include <cstdint>

// Problem constants
#define Bc   32
#define Sc   511
#define Tc   512
#define Dc   512
#define Hc   8
#define HDc  64
#define Lc   4
#define PDc  32
#define FDc  448     // D - 2*PD
#define DFFc 2048
#define Mc   (Bc*Tc) // 16384 tokens
#define QP   1536    // qkv combined pitch

// ---------------- scratch (device globals; no allocation allowed) ----------
__device__ float g_x   [Mc*Dc];
__device__ float g_att [Mc*Dc];
__device__ float g_tmp [Mc*Dc];
__device__ float g_ff  [Mc*DFFc];      // doubles as qkv buffer [Mc][1536]
__device__ float g_wqkv[Lc*Dc*QP];
__device__ float g_bqkv[Lc*QP];

// ---------------- weight packing --------------------------------------------
__global__ __launch_bounds__(512)
void pack_qkv_kernel(const float* __restrict__ Wq, const float* __restrict__ Wk,
                     const float* __restrict__ Wv, float* __restrict__ Wqkv)
{
    int lk = blockIdx.x;
    int j  = threadIdx.x;
    size_t src = (size_t)lk*Dc + j;
    size_t dst = (size_t)lk*QP + j;
    Wqkv[dst        ] = Wq[src];
    Wqkv[dst + Dc   ] = Wk[src];
    Wqkv[dst + 2*Dc ] = Wv[src];
}
__global__ __launch_bounds__(512)
void pack_bqkv_kernel(const float* __restrict__ bq, const float* __restrict__ bk,
                      const float* __restrict__ bv, float* __restrict__ bqkv)
{
    int l = blockIdx.x;
    int j = threadIdx.x;
    bqkv[l*QP + j       ] = bq[l*Dc + j];
    bqkv[l*QP + j + Dc  ] = bk[l*Dc + j];
    bqkv[l*QP + j + 2*Dc] = bv[l*Dc + j];
}

// ---------------- embedding + positional encoding ---------------------------
__global__ void embed_kernel(const float* __restrict__ runs,
                             const float* __restrict__ wickets,
                             const float* __restrict__ overs,
                             const int*   __restrict__ batters,
                             const int*   __restrict__ bowlers,
                             const float* __restrict__ pemb,
                             const float* __restrict__ Wf,
                             const float* __restrict__ bf,
                             const float* __restrict__ qtok,
                             float* __restrict__ x)
{
    int bt = blockIdx.x;
    int b  = bt / Tc;
    int t  = bt % Tc;
    int j  = threadIdx.x;

    float val;
    if (t < Sc) {
        if (j < FDc) {
            float r = runs   [b*Sc + t];
            float w = wickets[b*Sc + t];
            float o = overs  [b*Sc + t];
            val = r*Wf[j] + w*Wf[FDc + j] + o*Wf[2*FDc + j] + bf[j];
        } else if (j < FDc + PDc) {
            val = pemb[batters[b*Sc + t]*PDc + (j - FDc)];
        } else {
            val = pemb[bowlers[b*Sc + t]*PDc + (j - FDc - PDc)];
        }
    } else {
        val = qtok[j];
    }
    int   i2  = j & ~1;
    float dv  = expf((float)i2 * -0.0179889460390111f);
    float ang = (float)t * dv;
    val += (j & 1) ? cosf(ang) : sinf(ang);
    x[(b*Tc + t)*Dc + j] = val;
}

// ---------------- helpers -----------------------------------------------------
__device__ __forceinline__ uint32_t smem_u32(const void* p) {
    return (uint32_t)__cvta_generic_to_shared(p);
}
#define MMA_TF32(ACC, A0,A1,A2,A3, B0,B1) \
    asm volatile( \
        "mma.sync.aligned.m16n8k8.row.col.f32.tf32.tf32.f32 " \
        "{%0,%1,%2,%3}, {%4,%5,%6,%7}, {%8,%9}, {%0,%1,%2,%3};\n" \
        : "+f"((ACC)[0]), "+f"((ACC)[1]), "+f"((ACC)[2]), "+f"((ACC)[3]) \
        : "r"(A0), "r"(A1), "r"(A2), "r"(A3), "r"(B0), "r"(B1))
__device__ __forceinline__ uint32_t tf32_hi(float v) {
    uint32_t r; asm("cvt.rna.tf32.f32 %0, %1;" : "=r"(r) : "f"(v)); return r;
}
__device__ __forceinline__ void tf32_split(float v, uint32_t& hi, uint32_t& lo) {
    hi = tf32_hi(v);
    lo = tf32_hi(v - __uint_as_float(hi));
}

// ---------------- tf32 tensor-core GEMM v2 -----------------------------------
// 128x128 CTA tile, 128 threads = 4 warps (2x2), warp tile 64x64.
// 3-stage cp.async, single barrier per chunk. LDS:MMA ratio 1:1.
#define TBM 128
#define TBN 128
#define TBK 32
#define AST 36
#define BST 136
#define TG_ST 3
#define TGEMM_SMEM ((TG_ST*TBM*AST + TG_ST*32*BST)*4)

__device__ __forceinline__ void tg_load_stage(
    const float* __restrict__ A, const float* __restrict__ W,
    float* __restrict__ As, float* __restrict__ Bs,
    int bm, int bn, int k0, int K, int N, int tid)
{
    // A tile: 128x32 fp32 -> 1024 float4s, 8 per thread (128 threads)
    #pragma unroll
    for (int it = 0; it < 8; it++) {
        int idx = tid + it*128;
        int ar = idx >> 3, aq = idx & 7;
        const float* ap = A + (size_t)(bm*TBM + ar)*K + k0 + aq*4;
        uint32_t ad = smem_u32(As + ar*AST + aq*4);
        asm volatile("cp.async.cg.shared.global [%0], [%1], 16;\n"
                     :: "r"(ad), "l"(ap));
    }
    // B tile: 32x128 fp32 -> 1024 float4s, 8 per thread
    #pragma unroll
    for (int it = 0; it < 8; it++) {
        int idx = tid + it*128;
        int br = idx >> 5, bq = idx & 31;
        const float* bp = W + (size_t)(k0 + br)*N + bn*TBN + bq*4;
        uint32_t bd = smem_u32(Bs + br*BST + bq*4);
        asm volatile("cp.async.cg.shared.global [%0], [%1], 16;\n"
                     :: "r"(bd), "l"(bp));
    }
    asm volatile("cp.async.commit_group;\n");
}

template<int EPI>
__global__ __launch_bounds__(128, 2)
void tgemm_kernel(const float* __restrict__ A, const float* __restrict__ W,
                  const float* __restrict__ bias, float* __restrict__ C,
                  int M, int N, int K)
{
    extern __shared__ float sm[];
    float* As = sm;                         // [3][128*AST]
    float* Bs = sm + TG_ST*TBM*AST;         // [3][32*BST]

    int tid = threadIdx.x;
    int bm = blockIdx.y, bn = blockIdx.x;
    int w = tid >> 5, lane = tid & 31;
    int gid = lane >> 2, tig = lane & 3;
    int wm = w >> 1, wn = w & 1;            // 2x2 warp grid, warp tile 64x64

    float acc[4][8][4];
    #pragma unroll
    for (int i = 0; i < 4; i++)
        #pragma unroll
        for (int j = 0; j < 8; j++)
            #pragma unroll
            for (int r = 0; r < 4; r++) acc[i][j][r] = 0.f;

    int nkt = K / TBK;
    tg_load_stage(A, W, As, Bs, bm, bn, 0, K, N, tid);
    if (nkt > 1)
        tg_load_stage(A, W, As + TBM*AST, Bs + 32*BST, bm, bn, TBK, K, N, tid);

    for (int kt = 0; kt < nkt; ++kt) {
        if (kt + 1 < nkt) asm volatile("cp.async.wait_group 1;\n");
        else              asm volatile("cp.async.wait_group 0;\n");
        __syncthreads();
        if (kt + 2 < nkt) {
            int nxt = (kt + 2) % TG_ST;
            tg_load_stage(A, W, As + nxt*TBM*AST, Bs + nxt*32*BST,
                          bm, bn, (kt+2)*TBK, K, N, tid);
        }

        const float* Asc = As + (kt % TG_ST)*TBM*AST;
        const float* Bsc = Bs + (kt % TG_ST)*32*BST;

        #pragma unroll
        for (int kc = 0; kc < 4; ++kc) {
            uint32_t a[4][4], b[8][2];
            #pragma unroll
            for (int i = 0; i < 4; i++) {
                int r0 = wm*64 + 16*i + gid;
                a[i][0] = __float_as_uint(Asc[(r0    )*AST + kc*8 + tig    ]);
                a[i][1] = __float_as_uint(Asc[(r0 + 8)*AST + kc*8 + tig    ]);
                a[i][2] = __float_as_uint(Asc[(r0    )*AST + kc*8 + tig + 4]);
                a[i][3] = __float_as_uint(Asc[(r0 + 8)*AST + kc*8 + tig + 4]);
            }
            #pragma unroll
            for (int j = 0; j < 8; j++) {
                int c0 = wn*64 + 8*j + gid;
                b[j][0] = __float_as_uint(Bsc[(kc*8 + tig    )*BST + c0]);
                b[j][1] = __float_as_uint(Bsc[(kc*8 + tig + 4)*BST + c0]);
            }
            #pragma unroll
            for (int i = 0; i < 4; i++)
                #pragma unroll
                for (int j = 0; j < 8; j++)
                    MMA_TF32(acc[i][j], a[i][0], a[i][1], a[i][2], a[i][3],
                             b[j][0], b[j][1]);
        }
    }

    #pragma unroll
    for (int i = 0; i < 4; i++) {
        int r = bm*TBM + wm*64 + 16*i + gid;
        #pragma unroll
        for (int j = 0; j < 8; j++) {
            int c = bn*TBN + wn*64 + 8*j + 2*tig;
            float bx = bias[c], by = bias[c+1];
            float v0 = acc[i][j][0] + bx;
            float v1 = acc[i][j][1] + by;
            float v2 = acc[i][j][2] + bx;
            float v3 = acc[i][j][3] + by;
            if (EPI == 1) {
                v0 = 0.5f*v0*(1.0f + erff(v0*0.70710678118654752f));
                v1 = 0.5f*v1*(1.0f + erff(v1*0.70710678118654752f));
                v2 = 0.5f*v2*(1.0f + erff(v2*0.70710678118654752f));
                v3 = 0.5f*v3*(1.0f + erff(v3*0.70710678118654752f));
            }
            float2 p0; p0.x = v0; p0.y = v1;
            float2 p1; p1.x = v2; p1.y = v3;
            *(float2*)&C[(size_t)r*N + c]       = p0;
            *(float2*)&C[(size_t)(r+8)*N + c]   = p1;
        }
    }
}

// ---------------- fused attention v6: online softmax + staged hi/lo ----------
#define ATTN6_SMEM (27072*4)

__global__ __launch_bounds__(256)
void attn6_kernel(const float* __restrict__ qkv,
                  const int* __restrict__ batters, const int* __restrict__ bowlers,
                  const float* __restrict__ rec_s, const float* __restrict__ bow_s,
                  const float* __restrict__ bat_s, int layer,
                  float* __restrict__ Og)
{
    extern __shared__ float sm[];
    float* Qhi = sm;
    float* Qlo = sm + 2176;
    float* Khi = sm + 4352;
    float* Klo = sm + 8704;
    float* Vhi = sm + 13056;
    float* Vlo = sm + 17664;
    float* Phi = sm + 22272;
    float* Plo = sm + 24448;
    float* Mp  = sm + 26624;
    float* Sp  = sm + 26752;
    int*   ib  = (int*)(sm + 26880);
    int* bowQ = ib;       int* batQ = ib + 32;
    int* bowK = ib + 64;  int* batK = ib + 128;

    int qt = blockIdx.x, h = blockIdx.y, b = blockIdx.z;
    int tid = threadIdx.x;
    int q0 = qt*32;
    int w = tid >> 5, lane = tid & 31;
    int gid = lane >> 2, tig = lane & 3;
    int mi = w >> 2, nq = w & 3;
    int r1 = mi*16 + gid, r2 = r1 + 8;

    const float* Q  = qkv;
    const float* Kg = qkv + Dc;
    const float* Vg = qkv + 2*Dc;

    #pragma unroll
    for (int it = 0; it < 2; ++it) {
        int idx = tid + it*256;
        int q = idx >> 4, d4 = idx & 15;
        float4 v = *(const float4*)&Q[(size_t)(b*Tc + q0 + q)*QP + h*HDc + d4*4];
        uint32_t h0,l0,h1,l1,h2,l2,h3,l3;
        tf32_split(v.x, h0, l0); tf32_split(v.y, h1, l1);
        tf32_split(v.z, h2, l2); tf32_split(v.w, h3, l3);
        float4 hv, lv;
        hv.x = __uint_as_float(h0); hv.y = __uint_as_float(h1);
        hv.z = __uint_as_float(h2); hv.w = __uint_as_float(h3);
        lv.x = __uint_as_float(l0); lv.y = __uint_as_float(l1);
        lv.z = __uint_as_float(l2); lv.w = __uint_as_float(l3);
        *(float4*)&Qhi[q*68 + d4*4] = hv;
        *(float4*)&Qlo[q*68 + d4*4] = lv;
    }
    if (tid < 32) {
        int qg = q0 + tid;
        bowQ[tid] = (qg < Sc) ? bowlers[b*Sc + qg] : -1;
        batQ[tid] = (qg < Sc) ? batters[b*Sc + qg] : -1;
    }

    int ktmax = (q0 + 32 + 63) >> 6;
    const float scl  = 0.125f;
    const float recw = rec_s[layer];
    const float boww = bow_s[layer];
    const float batw = bat_s[layer];

    int qg1 = q0 + r1, qg2 = q0 + r2;

    float oacc[2][4] = {{0,0,0,0},{0,0,0,0}};
    float mrun1 = -1e30f, mrun2 = -1e30f;
    float srun1 = 0.f,    srun2 = 0.f;

    for (int kt = 0; kt < ktmax; ++kt) {
        int k0 = kt << 6;

        #pragma unroll
        for (int it = 0; it < 4; ++it) {
            int idx = tid + it*256;
            int kk = idx >> 4, d4 = idx & 15;
            float4 v = *(const float4*)&Kg[(size_t)(b*Tc + k0 + kk)*QP + h*HDc + d4*4];
            uint32_t h0,l0,h1,l1,h2,l2,h3,l3;
            tf32_split(v.x, h0, l0); tf32_split(v.y, h1, l1);
            tf32_split(v.z, h2, l2); tf32_split(v.w, h3, l3);
            float4 hv, lv;
            hv.x = __uint_as_float(h0); hv.y = __uint_as_float(h1);
            hv.z = __uint_as_float(h2); hv.w = __uint_as_float(h3);
            lv.x = __uint_as_float(l0); lv.y = __uint_as_float(l1);
            lv.z = __uint_as_float(l2); lv.w = __uint_as_float(l3);
            *(float4*)&Khi[kk*68 + d4*4] = hv;
            *(float4*)&Klo[kk*68 + d4*4] = lv;
        }
        if (tid < 64) {
            int kg = k0 + tid;
            bowK[tid] = (kg < Sc) ? bowlers[b*Sc + kg] : -2;
            batK[tid] = (kg < Sc) ? batters[b*Sc + kg] : -2;
        }
        __syncthreads();

        float acc[2][4] = {{0,0,0,0},{0,0,0,0}};
        #pragma unroll
        for (int kc = 0; kc < 8; ++kc) {
            int ra = r1*68 + kc*8 + tig;
            uint32_t ah0 = __float_as_uint(Qhi[ra]);
            uint32_t ah1 = __float_as_uint(Qhi[ra + 8*68]);
            uint32_t ah2 = __float_as_uint(Qhi[ra + 4]);
            uint32_t ah3 = __float_as_uint(Qhi[ra + 8*68 + 4]);
            uint32_t al0 = __float_as_uint(Qlo[ra]);
            uint32_t al1 = __float_as_uint(Qlo[ra + 8*68]);
            uint32_t al2 = __float_as_uint(Qlo[ra + 4]);
            uint32_t al3 = __float_as_uint(Qlo[ra + 8*68 + 4]);
            #pragma unroll
            for (int j = 0; j < 2; ++j) {
                int rb = (nq*16 + j*8 + gid)*68 + kc*8 + tig;
                uint32_t bh0 = __float_as_uint(Khi[rb]);
                uint32_t bh1 = __float_as_uint(Khi[rb + 4]);
                uint32_t bl0 = __float_as_uint(Klo[rb]);
                uint32_t bl1 = __float_as_uint(Klo[rb + 4]);
                MMA_TF32(acc[j], ah0, ah1, ah2, ah3, bl0, bl1);
                MMA_TF32(acc[j], al0, al1, al2, al3, bh0, bh1);
                MMA_TF32(acc[j], ah0, ah1, ah2, ah3, bh0, bh1);
            }
        }

        #pragma unroll
        for (int it = 0; it < 4; ++it) {
            int idx = tid + it*256;
            int kk = idx >> 4, d4 = idx & 15;
            float4 v = *(const float4*)&Vg[(size_t)(b*Tc + k0 + kk)*QP + h*HDc + d4*4];
            uint32_t h0,l0,h1,l1,h2,l2,h3,l3;
            tf32_split(v.x, h0, l0); tf32_split(v.y, h1, l1);
            tf32_split(v.z, h2, l2); tf32_split(v.w, h3, l3);
            float4 hv, lv;
            hv.x = __uint_as_float(h0); hv.y = __uint_as_float(h1);
            hv.z = __uint_as_float(h2); hv.w = __uint_as_float(h3);
            lv.x = __uint_as_float(l0); lv.y = __uint_as_float(l1);
            lv.z = __uint_as_float(l2); lv.w = __uint_as_float(l3);
            *(float4*)&Vhi[kk*72 + d4*4] = hv;
            *(float4*)&Vlo[kk*72 + d4*4] = lv;
        }

        float sv[2][4];
        int bq1 = bowQ[r1], aq1 = batQ[r1];
        int bq2 = bowQ[r2], aq2 = batQ[r2];
        #pragma unroll
        for (int j = 0; j < 2; ++j) {
            int kl = nq*16 + j*8 + 2*tig;
            int kg = k0 + kl;
            float s00 = acc[j][0]*scl, s01 = acc[j][1]*scl;
            float s10 = acc[j][2]*scl, s11 = acc[j][3]*scl;
            if (h == 0) {
                s00 += recw * (float)kg     * (1.0f/512.0f);
                s01 += recw * (float)(kg+1) * (1.0f/512.0f);
                s10 += recw * (float)kg     * (1.0f/512.0f);
                s11 += recw * (float)(kg+1) * (1.0f/512.0f);
            } else if (h == 1) {
                int k1b = bowK[kl], k2b = bowK[kl+1];
                if (qg1 == Sc || kg   == Sc || bq1 == k1b) s00 += boww;
                if (qg1 == Sc || kg+1 == Sc || bq1 == k2b) s01 += boww;
                if (qg2 == Sc || kg   == Sc || bq2 == k1b) s10 += boww;
                if (qg2 == Sc || kg+1 == Sc || bq2 == k2b) s11 += boww;
            } else if (h == 2) {
                int k1a = batK[kl], k2a = batK[kl+1];
                if (qg1 == Sc || kg   == Sc || aq1 == k1a) s00 += batw;
                if (qg1 == Sc || kg+1 == Sc || aq1 == k2a) s01 += batw;
                if (qg2 == Sc || kg   == Sc || aq2 == k1a) s10 += batw;
                if (qg2 == Sc || kg+1 == Sc || aq2 == k2a) s11 += batw;
            }
            if (kg   > qg1) s00 = -1e30f;
            if (kg+1 > qg1) s01 = -1e30f;
            if (kg   > qg2) s10 = -1e30f;
            if (kg+1 > qg2) s11 = -1e30f;
            sv[j][0] = s00; sv[j][1] = s01; sv[j][2] = s10; sv[j][3] = s11;
        }

        float rm1 = fmaxf(fmaxf(sv[0][0], sv[0][1]), fmaxf(sv[1][0], sv[1][1]));
        float rm2 = fmaxf(fmaxf(sv[0][2], sv[0][3]), fmaxf(sv[1][2], sv[1][3]));
        rm1 = fmaxf(rm1, __shfl_xor_sync(0xffffffffu, rm1, 1));
        rm1 = fmaxf(rm1, __shfl_xor_sync(0xffffffffu, rm1, 2));
        rm2 = fmaxf(rm2, __shfl_xor_sync(0xffffffffu, rm2, 1));
        rm2 = fmaxf(rm2, __shfl_xor_sync(0xffffffffu, rm2, 2));
        if (tig == 0) { Mp[r1*4 + nq] = rm1; Mp[r2*4 + nq] = rm2; }
        __syncthreads();

        float4 m4a = *(const float4*)&Mp[r1*4];
        float4 m4b = *(const float4*)&Mp[r2*4];
        float mc1 = fmaxf(fmaxf(m4a.x, m4a.y), fmaxf(m4a.z, m4a.w));
        float mc2 = fmaxf(fmaxf(m4b.x, m4b.y), fmaxf(m4b.z, m4b.w));
        float mnew1 = fmaxf(mrun1, mc1);
        float mnew2 = fmaxf(mrun2, mc2);
        float f1 = __expf(mrun1 - mnew1);
        float f2 = __expf(mrun2 - mnew2);

        float ps1 = 0.f, ps2 = 0.f;
        #pragma unroll
        for (int j = 0; j < 2; ++j) {
            int col = nq*16 + j*8 + 2*tig;
            float e00 = __expf(sv[j][0] - mnew1);
            float e01 = __expf(sv[j][1] - mnew1);
            float e10 = __expf(sv[j][2] - mnew2);
            float e11 = __expf(sv[j][3] - mnew2);
            ps1 += e00 + e01;
            ps2 += e10 + e11;
            uint32_t h0,l0,h1,l1;
            tf32_split(e00, h0, l0); tf32_split(e01, h1, l1);
            float2 hv, lv;
            hv.x = __uint_as_float(h0); hv.y = __uint_as_float(h1);
            lv.x = __uint_as_float(l0); lv.y = __uint_as_float(l1);
            *(float2*)&Phi[r1*68 + col] = hv;
            *(float2*)&Plo[r1*68 + col] = lv;
            tf32_split(e10, h0, l0); tf32_split(e11, h1, l1);
            hv.x = __uint_as_float(h0); hv.y = __uint_as_float(h1);
            lv.x = __uint_as_float(l0); lv.y = __uint_as_float(l1);
            *(float2*)&Phi[r2*68 + col] = hv;
            *(float2*)&Plo[r2*68 + col] = lv;
        }
        ps1 += __shfl_xor_sync(0xffffffffu, ps1, 1);
        ps1 += __shfl_xor_sync(0xffffffffu, ps1, 2);
        ps2 += __shfl_xor_sync(0xffffffffu, ps2, 1);
        ps2 += __shfl_xor_sync(0xffffffffu, ps2, 2);
        if (tig == 0) { Sp[r1*4 + nq] = ps1; Sp[r2*4 + nq] = ps2; }

        oacc[0][0] *= f1; oacc[0][1] *= f1; oacc[1][0] *= f1; oacc[1][1] *= f1;
        oacc[0][2] *= f2; oacc[0][3] *= f2; oacc[1][2] *= f2; oacc[1][3] *= f2;
        mrun1 = mnew1; mrun2 = mnew2;
        __syncthreads();

        float4 s4a = *(const float4*)&Sp[r1*4];
        float4 s4b = *(const float4*)&Sp[r2*4];
        srun1 = srun1*f1 + (s4a.x + s4a.y + s4a.z + s4a.w);
        srun2 = srun2*f2 + (s4b.x + s4b.y + s4b.z + s4b.w);

        #pragma unroll
        for (int kc = 0; kc < 8; ++kc) {
            int pa1 = r1*68 + kc*8 + tig;
            int pa2 = r2*68 + kc*8 + tig;
            uint32_t ah0 = __float_as_uint(Phi[pa1]);
            uint32_t ah1 = __float_as_uint(Phi[pa2]);
            uint32_t ah2 = __float_as_uint(Phi[pa1 + 4]);
            uint32_t ah3 = __float_as_uint(Phi[pa2 + 4]);
            uint32_t al0 = __float_as_uint(Plo[pa1]);
            uint32_t al1 = __float_as_uint(Plo[pa2]);
            uint32_t al2 = __float_as_uint(Plo[pa1 + 4]);
            uint32_t al3 = __float_as_uint(Plo[pa2 + 4]);
            #pragma unroll
            for (int j = 0; j < 2; ++j) {
                int n0 = (nq*2 + j)*8;
                int vb0 = (kc*8 + tig    )*72 + n0 + gid;
                int vb1 = (kc*8 + tig + 4)*72 + n0 + gid;
                uint32_t bh0 = __float_as_uint(Vhi[vb0]);
                uint32_t bh1 = __float_as_uint(Vhi[vb1]);
                uint32_t bl0 = __float_as_uint(Vlo[vb0]);
                uint32_t bl1 = __float_as_uint(Vlo[vb1]);
                MMA_TF32(oacc[j], ah0, ah1, ah2, ah3, bl0, bl1);
                MMA_TF32(oacc[j], al0, al1, al2, al3, bh0, bh1);
                MMA_TF32(oacc[j], ah0, ah1, ah2, ah3, bh0, bh1);
            }
        }
    }

    float inv1 = 1.0f / srun1;
    float inv2 = 1.0f / srun2;
    #pragma unroll
    for (int j = 0; j < 2; ++j) {
        int col = (nq*2 + j)*8 + 2*tig;
        float2 o1; o1.x = oacc[j][0]*inv1; o1.y = oacc[j][1]*inv1;
        float2 o2; o2.x = oacc[j][2]*inv2; o2.y = oacc[j][3]*inv2;
        *(float2*)&Og[(size_t)(b*Tc + q0 + r1)*Dc + h*HDc + col] = o1;
        *(float2*)&Og[(size_t)(b*Tc + q0 + r2)*Dc + h*HDc + col] = o2;
    }
}

// ---------------- residual add + LayerNorm: warp-per-token -------------------
__global__ __launch_bounds__(256)
void add_ln_kernel(float* __restrict__ x, const float* __restrict__ r,
                   const float* __restrict__ g, const float* __restrict__ be)
{
    int w = threadIdx.x >> 5;
    int lane = threadIdx.x & 31;
    size_t tok = (size_t)blockIdx.x*8 + w;
    float* xr = x + tok*Dc;
    const float* rr = r + tok*Dc;

    float4 v[4];
    float s = 0.f, s2 = 0.f;
    #pragma unroll
    for (int i = 0; i < 4; ++i) {
        int c = (lane + i*32)*4;
        float4 xv = *(const float4*)&xr[c];
        float4 rv = *(const float4*)&rr[c];
        xv.x += rv.x; xv.y += rv.y; xv.z += rv.z; xv.w += rv.w;
        v[i] = xv;
        s  += xv.x + xv.y + xv.z + xv.w;
        s2 += xv.x*xv.x + xv.y*xv.y + xv.z*xv.z + xv.w*xv.w;
    }
    #pragma unroll
    for (int o = 16; o; o >>= 1) {
        s  += __shfl_xor_sync(0xffffffffu, s,  o);
        s2 += __shfl_xor_sync(0xffffffffu, s2, o);
    }
    float mu  = s * (1.0f/512.0f);
    float var = s2 * (1.0f/512.0f) - mu*mu;
    float rs  = rsqrtf(var + 1e-5f);
    #pragma unroll
    for (int i = 0; i < 4; ++i) {
        int c = (lane + i*32)*4;
        float4 gv = *(const float4*)&g[c];
        float4 bv = *(const float4*)&be[c];
        float4 y;
        y.x = (v[i].x - mu)*rs*gv.x + bv.x;
        y.y = (v[i].y - mu)*rs*gv.y + bv.y;
        y.z = (v[i].z - mu)*rs*gv.z + bv.z;
        y.w = (v[i].w - mu)*rs*gv.w + bv.w;
        *(float4*)&xr[c] = y;
    }
}

// ---------------- output head: out[b] = x[b, T-1] @ Wout + bout -------------
__global__ __launch_bounds__(512)
void out_kernel(const float* __restrict__ x, const float* __restrict__ Wout,
                const float* __restrict__ bout, float* __restrict__ out)
{
    int b = blockIdx.x;
    int n = threadIdx.x;
    __shared__ float xs[512];
    xs[n] = x[(size_t)(b*Tc + Tc - 1)*Dc + n];
    __syncthreads();
    float acc = bout[n];
    #pragma unroll 8
    for (int d = 0; d < Dc; ++d)
        acc += xs[d] * Wout[(size_t)d*Dc + n];
    out[b*Dc + n] = acc;
}

// ---------------- launcher ---------------------------------------------------
extern "C" void kernel_launch(void* const* d_in, const int* in_sizes, int n_in,
                              void* d_out, int out_size)
{
    const float* runs    = (const float*)d_in[0];
    const float* wickets = (const float*)d_in[1];
    const float* overs   = (const float*)d_in[2];
    const int*   batters = (const int*)  d_in[3];
    const int*   bowlers = (const int*)  d_in[4];
    const float* pemb    = (const float*)d_in[5];
    const float* Wf      = (const float*)d_in[6];
    const float* bf      = (const float*)d_in[7];
    const float* qtok    = (const float*)d_in[8];
    const float* Wq      = (const float*)d_in[9];
    const float* bq      = (const float*)d_in[10];
    const float* Wk      = (const float*)d_in[11];
    const float* bk      = (const float*)d_in[12];
    const float* Wv      = (const float*)d_in[13];
    const float* bv      = (const float*)d_in[14];
    const float* Wo      = (const float*)d_in[15];
    const float* bo      = (const float*)d_in[16];
    const float* rec_s   = (const float*)d_in[17];
    const float* bow_s   = (const float*)d_in[18];
    const float* bat_s   = (const float*)d_in[19];
    const float* W1      = (const float*)d_in[20];
    const float* b1      = (const float*)d_in[21];
    const float* W2      = (const float*)d_in[22];
    const float* b2      = (const float*)d_in[23];
    const float* g1      = (const float*)d_in[24];
    const float* be1     = (const float*)d_in[25];
    const float* g2      = (const float*)d_in[26];
    const float* be2     = (const float*)d_in[27];
    const float* Wout    = (const float*)d_in[28];
    const float* bout    = (const float*)d_in[29];
    float* out = (float*)d_out;

    float *x_, *att_, *tmp_, *ff_, *wqkv_, *bqkv_;
    cudaGetSymbolAddress((void**)&x_,    g_x);
    cudaGetSymbolAddress((void**)&att_,  g_att);
    cudaGetSymbolAddress((void**)&tmp_,  g_tmp);
    cudaGetSymbolAddress((void**)&ff_,   g_ff);
    cudaGetSymbolAddress((void**)&wqkv_, g_wqkv);
    cudaGetSymbolAddress((void**)&bqkv_, g_bqkv);

    cudaFuncSetAttribute(attn6_kernel,
                         cudaFuncAttributeMaxDynamicSharedMemorySize, ATTN6_SMEM);
    cudaFuncSetAttribute(tgemm_kernel<0>,
                         cudaFuncAttributeMaxDynamicSharedMemorySize, TGEMM_SMEM);
    cudaFuncSetAttribute(tgemm_kernel<1>,
                         cudaFuncAttributeMaxDynamicSharedMemorySize, TGEMM_SMEM);

    pack_qkv_kernel<<<Lc*Dc, 512>>>(Wq, Wk, Wv, wqkv_);
    pack_bqkv_kernel<<<Lc, 512>>>(bq, bk, bv, bqkv_);

    embed_kernel<<<Bc*Tc, 512>>>(runs, wickets, overs, batters, bowlers,
                                 pemb, Wf, bf, qtok, x_);

    dim3 g512 (Dc/TBN,   Mc/TBM);   // (4, 128)
    dim3 gQKV (QP/TBN,   Mc/TBM);   // (12, 128)
    dim3 g2048(DFFc/TBN, Mc/TBM);   // (16, 128)
    dim3 gattn(16, Hc, Bc);

    for (int l = 0; l < Lc; ++l) {
        tgemm_kernel<0><<<gQKV, 128, TGEMM_SMEM>>>(x_, wqkv_ + (size_t)l*Dc*QP,
                                                   bqkv_ + l*QP, ff_, Mc, QP, Dc);

        attn6_kernel<<<gattn, 256, ATTN6_SMEM>>>(ff_, batters, bowlers,
                                                 rec_s, bow_s, bat_s, l, att_);

        tgemm_kernel<0><<<g512, 128, TGEMM_SMEM>>>(att_, Wo + (size_t)l*Dc*Dc,
                                                   bo + l*Dc, tmp_, Mc, Dc, Dc);
        add_ln_kernel<<<Mc/8, 256>>>(x_, tmp_, g1 + l*Dc, be1 + l*Dc);

        tgemm_kernel<1><<<g2048, 128, TGEMM_SMEM>>>(x_, W1 + (size_t)l*Dc*DFFc,
                                                    b1 + l*DFFc, ff_, Mc, DFFc, Dc);
        tgemm_kernel<0><<<g512, 128, TGEMM_SMEM>>>(ff_, W2 + (size_t)l*DFFc*Dc,
                                                   b2 + l*Dc, tmp_, Mc, Dc, DFFc);
        add_ln_kernel<<<Mc/8, 256>>>(x_, tmp_, g2 + l*Dc, be2 + l*Dc);
    }

    out_kernel<<<Bc, 512>>>(x_, Wout, bout, out);
}

// round 13
// speedup vs baseline: 1.0606x; 1.0536x over previous
#include <cuda_runtime.h>
#include <cuda_bf16.h>
#include <math_constants.h>
#include <cstdint>

// Problem constants
#define Bc   32
#define Sc   511
#define Tc   512
#define Dc   512
#define Hc   8
#define HDc  64
#define Lc   4
#define PDc  32
#define FDc  448     // D - 2*PD
#define DFFc 2048
#define Mc   (Bc*Tc) // 16384 tokens
#define QP   1536    // qkv combined pitch

// ---------------- scratch (device globals; no allocation allowed) ----------
__device__ float g_x   [Mc*Dc];
__device__ float g_att [Mc*Dc];
__device__ float g_tmp [Mc*Dc];
__device__ float g_ff  [Mc*DFFc];      // doubles as qkv buffer [Mc][1536]
__device__ float g_wqkv[Lc*Dc*QP];
__device__ float g_bqkv[Lc*QP];

// ---------------- weight packing --------------------------------------------
__global__ __launch_bounds__(512)
void pack_qkv_kernel(const float* __restrict__ Wq, const float* __restrict__ Wk,
                     const float* __restrict__ Wv, float* __restrict__ Wqkv)
{
    int lk = blockIdx.x;
    int j  = threadIdx.x;
    size_t src = (size_t)lk*Dc + j;
    size_t dst = (size_t)lk*QP + j;
    Wqkv[dst        ] = Wq[src];
    Wqkv[dst + Dc   ] = Wk[src];
    Wqkv[dst + 2*Dc ] = Wv[src];
}
__global__ __launch_bounds__(512)
void pack_bqkv_kernel(const float* __restrict__ bq, const float* __restrict__ bk,
                      const float* __restrict__ bv, float* __restrict__ bqkv)
{
    int l = blockIdx.x;
    int j = threadIdx.x;
    bqkv[l*QP + j       ] = bq[l*Dc + j];
    bqkv[l*QP + j + Dc  ] = bk[l*Dc + j];
    bqkv[l*QP + j + 2*Dc] = bv[l*Dc + j];
}

// ---------------- embedding + positional encoding ---------------------------
__global__ void embed_kernel(const float* __restrict__ runs,
                             const float* __restrict__ wickets,
                             const float* __restrict__ overs,
                             const int*   __restrict__ batters,
                             const int*   __restrict__ bowlers,
                             const float* __restrict__ pemb,
                             const float* __restrict__ Wf,
                             const float* __restrict__ bf,
                             const float* __restrict__ qtok,
                             float* __restrict__ x)
{
    int bt = blockIdx.x;
    int b  = bt / Tc;
    int t  = bt % Tc;
    int j  = threadIdx.x;

    float val;
    if (t < Sc) {
        if (j < FDc) {
            float r = runs   [b*Sc + t];
            float w = wickets[b*Sc + t];
            float o = overs  [b*Sc + t];
            val = r*Wf[j] + w*Wf[FDc + j] + o*Wf[2*FDc + j] + bf[j];
        } else if (j < FDc + PDc) {
            val = pemb[batters[b*Sc + t]*PDc + (j - FDc)];
        } else {
            val = pemb[bowlers[b*Sc + t]*PDc + (j - FDc - PDc)];
        }
    } else {
        val = qtok[j];
    }
    int   i2  = j & ~1;
    float dv  = expf((float)i2 * -0.0179889460390111f);
    float ang = (float)t * dv;
    val += (j & 1) ? cosf(ang) : sinf(ang);
    x[(b*Tc + t)*Dc + j] = val;
}

// ---------------- helpers -----------------------------------------------------
__device__ __forceinline__ uint32_t smem_u32(const void* p) {
    return (uint32_t)__cvta_generic_to_shared(p);
}
#define MMA_TF32(ACC, A0,A1,A2,A3, B0,B1) \
    asm volatile( \
        "mma.sync.aligned.m16n8k8.row.col.f32.tf32.tf32.f32 " \
        "{%0,%1,%2,%3}, {%4,%5,%6,%7}, {%8,%9}, {%0,%1,%2,%3};\n" \
        : "+f"((ACC)[0]), "+f"((ACC)[1]), "+f"((ACC)[2]), "+f"((ACC)[3]) \
        : "r"(A0), "r"(A1), "r"(A2), "r"(A3), "r"(B0), "r"(B1))
__device__ __forceinline__ uint32_t tf32_hi(float v) {
    uint32_t r; asm("cvt.rna.tf32.f32 %0, %1;" : "=r"(r) : "f"(v)); return r;
}
__device__ __forceinline__ void tf32_split(float v, uint32_t& hi, uint32_t& lo) {
    hi = tf32_hi(v);
    lo = tf32_hi(v - __uint_as_float(hi));
}

// ---------------- tf32 tensor-core GEMM, 3-stage cp.async, 1 sync/chunk ------
// (R10 configuration: 256 threads, 8 warps 2x4, warp tile 64x32)
#define TBM 128
#define TBN 128
#define TBK 32
#define AST 36
#define BST 136
#define TG_ST 3
#define TGEMM_SMEM ((TG_ST*TBM*AST + TG_ST*32*BST)*4)

__device__ __forceinline__ void tg_load_stage(
    const float* __restrict__ A, const float* __restrict__ W,
    float* __restrict__ As, float* __restrict__ Bs,
    int bm, int bn, int k0, int K, int N, int tid)
{
    int ar = tid >> 3, aq = tid & 7;
    const float* ap = A + (size_t)(bm*TBM + ar)*K + k0 + aq*4;
    uint32_t ad = smem_u32(As + ar*AST + aq*4);
    #pragma unroll
    for (int i = 0; i < 4; i++) {
        asm volatile("cp.async.cg.shared.global [%0], [%1], 16;\n"
                     :: "r"(ad + i*32*AST*4), "l"(ap + (size_t)i*32*K));
    }
    int br = tid >> 5, bq = tid & 31;
    const float* bp = W + (size_t)(k0 + br)*N + bn*TBN + bq*4;
    uint32_t bd = smem_u32(Bs + br*BST + bq*4);
    #pragma unroll
    for (int i = 0; i < 4; i++) {
        asm volatile("cp.async.cg.shared.global [%0], [%1], 16;\n"
                     :: "r"(bd + i*8*BST*4), "l"(bp + (size_t)i*8*N));
    }
    asm volatile("cp.async.commit_group;\n");
}

template<int EPI>
__global__ __launch_bounds__(256, 2)
void tgemm_kernel(const float* __restrict__ A, const float* __restrict__ W,
                  const float* __restrict__ bias, float* __restrict__ C,
                  int M, int N, int K)
{
    extern __shared__ float sm[];
    float* As = sm;
    float* Bs = sm + TG_ST*TBM*AST;

    int tid = threadIdx.x;
    int bm = blockIdx.y, bn = blockIdx.x;
    int w = tid >> 5, lane = tid & 31;
    int gid = lane >> 2, tig = lane & 3;
    int wm = w >> 2, wn = w & 3;

    float acc[4][4][4];
    #pragma unroll
    for (int i = 0; i < 4; i++)
        #pragma unroll
        for (int j = 0; j < 4; j++)
            #pragma unroll
            for (int r = 0; r < 4; r++) acc[i][j][r] = 0.f;

    int nkt = K / TBK;
    tg_load_stage(A, W, As, Bs, bm, bn, 0, K, N, tid);
    if (nkt > 1)
        tg_load_stage(A, W, As + TBM*AST, Bs + 32*BST, bm, bn, TBK, K, N, tid);

    for (int kt = 0; kt < nkt; ++kt) {
        if (kt + 1 < nkt) asm volatile("cp.async.wait_group 1;\n");
        else              asm volatile("cp.async.wait_group 0;\n");
        __syncthreads();
        if (kt + 2 < nkt) {
            int nxt = (kt + 2) % TG_ST;
            tg_load_stage(A, W, As + nxt*TBM*AST, Bs + nxt*32*BST,
                          bm, bn, (kt+2)*TBK, K, N, tid);
        }

        const float* Asc = As + (kt % TG_ST)*TBM*AST;
        const float* Bsc = Bs + (kt % TG_ST)*32*BST;

        #pragma unroll
        for (int kc = 0; kc < 4; ++kc) {
            uint32_t a[4][4], b[4][2];
            #pragma unroll
            for (int i = 0; i < 4; i++) {
                int r0 = wm*64 + 16*i + gid;
                a[i][0] = __float_as_uint(Asc[(r0    )*AST + kc*8 + tig    ]);
                a[i][1] = __float_as_uint(Asc[(r0 + 8)*AST + kc*8 + tig    ]);
                a[i][2] = __float_as_uint(Asc[(r0    )*AST + kc*8 + tig + 4]);
                a[i][3] = __float_as_uint(Asc[(r0 + 8)*AST + kc*8 + tig + 4]);
            }
            #pragma unroll
            for (int j = 0; j < 4; j++) {
                int c0 = wn*32 + 8*j + gid;
                b[j][0] = __float_as_uint(Bsc[(kc*8 + tig    )*BST + c0]);
                b[j][1] = __float_as_uint(Bsc[(kc*8 + tig + 4)*BST + c0]);
            }
            #pragma unroll
            for (int i = 0; i < 4; i++)
                #pragma unroll
                for (int j = 0; j < 4; j++)
                    MMA_TF32(acc[i][j], a[i][0], a[i][1], a[i][2], a[i][3],
                             b[j][0], b[j][1]);
        }
    }

    #pragma unroll
    for (int i = 0; i < 4; i++) {
        int r = bm*TBM + wm*64 + 16*i + gid;
        #pragma unroll
        for (int j = 0; j < 4; j++) {
            int c = bn*TBN + wn*32 + 8*j + 2*tig;
            float bx = bias[c], by = bias[c+1];
            float v0 = acc[i][j][0] + bx;
            float v1 = acc[i][j][1] + by;
            float v2 = acc[i][j][2] + bx;
            float v3 = acc[i][j][3] + by;
            if (EPI == 1) {
                v0 = 0.5f*v0*(1.0f + erff(v0*0.70710678118654752f));
                v1 = 0.5f*v1*(1.0f + erff(v1*0.70710678118654752f));
                v2 = 0.5f*v2*(1.0f + erff(v2*0.70710678118654752f));
                v3 = 0.5f*v3*(1.0f + erff(v3*0.70710678118654752f));
            }
            float2 p0; p0.x = v0; p0.y = v1;
            float2 p1; p1.x = v2; p1.y = v3;
            *(float2*)&C[(size_t)r*N + c]       = p0;
            *(float2*)&C[(size_t)(r+8)*N + c]   = p1;
        }
    }
}

// ---------------- fused attention v8: online softmax, K tf32-hi only ---------
// 32 q rows/block, grid (16,H,B), 256 threads, 64-key chunks, single pass.
// Scores: (Qhi+Qlo) x Khi (2 MMAs). AV: full 3-term (P hi/lo x V hi/lo).
// smem floats: Qhi 0 | Qlo 2176 | Khi 4352 | Vhi 8704 | Vlo 13312 |
//              Phi 17920 | Plo 20096 | Mp 22272 | Sp 22400 | ids 22528
#define ATTN8_SMEM (22720*4)

__global__ __launch_bounds__(256)
void attn8_kernel(const float* __restrict__ qkv,
                  const int* __restrict__ batters, const int* __restrict__ bowlers,
                  const float* __restrict__ rec_s, const float* __restrict__ bow_s,
                  const float* __restrict__ bat_s, int layer,
                  float* __restrict__ Og)
{
    extern __shared__ float sm[];
    float* Qhi = sm;
    float* Qlo = sm + 2176;
    float* Khi = sm + 4352;
    float* Vhi = sm + 8704;
    float* Vlo = sm + 13312;
    float* Phi = sm + 17920;
    float* Plo = sm + 20096;
    float* Mp  = sm + 22272;
    float* Sp  = sm + 22400;
    int*   ib  = (int*)(sm + 22528);
    int* bowQ = ib;       int* batQ = ib + 32;
    int* bowK = ib + 64;  int* batK = ib + 128;

    int qt = blockIdx.x, h = blockIdx.y, b = blockIdx.z;
    int tid = threadIdx.x;
    int q0 = qt*32;
    int w = tid >> 5, lane = tid & 31;
    int gid = lane >> 2, tig = lane & 3;
    int mi = w >> 2, nq = w & 3;
    int r1 = mi*16 + gid, r2 = r1 + 8;

    const float* Q  = qkv;
    const float* Kg = qkv + Dc;
    const float* Vg = qkv + 2*Dc;

    // stage Q split hi/lo
    #pragma unroll
    for (int it = 0; it < 2; ++it) {
        int idx = tid + it*256;
        int q = idx >> 4, d4 = idx & 15;
        float4 v = *(const float4*)&Q[(size_t)(b*Tc + q0 + q)*QP + h*HDc + d4*4];
        uint32_t h0,l0,h1,l1,h2,l2,h3,l3;
        tf32_split(v.x, h0, l0); tf32_split(v.y, h1, l1);
        tf32_split(v.z, h2, l2); tf32_split(v.w, h3, l3);
        float4 hv, lv;
        hv.x = __uint_as_float(h0); hv.y = __uint_as_float(h1);
        hv.z = __uint_as_float(h2); hv.w = __uint_as_float(h3);
        lv.x = __uint_as_float(l0); lv.y = __uint_as_float(l1);
        lv.z = __uint_as_float(l2); lv.w = __uint_as_float(l3);
        *(float4*)&Qhi[q*68 + d4*4] = hv;
        *(float4*)&Qlo[q*68 + d4*4] = lv;
    }
    if (tid < 32) {
        int qg = q0 + tid;
        bowQ[tid] = (qg < Sc) ? bowlers[b*Sc + qg] : -1;
        batQ[tid] = (qg < Sc) ? batters[b*Sc + qg] : -1;
    }

    int ktmax = (q0 + 32 + 63) >> 6;
    const float scl  = 0.125f;
    const float recw = rec_s[layer];
    const float boww = bow_s[layer];
    const float batw = bat_s[layer];

    int qg1 = q0 + r1, qg2 = q0 + r2;

    float oacc[2][4] = {{0,0,0,0},{0,0,0,0}};
    float mrun1 = -1e30f, mrun2 = -1e30f;
    float srun1 = 0.f,    srun2 = 0.f;

    for (int kt = 0; kt < ktmax; ++kt) {
        int k0 = kt << 6;

        // ---- stage K (tf32-hi only: 1 cvt per element, no lo plane) ----
        #pragma unroll
        for (int it = 0; it < 4; ++it) {
            int idx = tid + it*256;
            int kk = idx >> 4, d4 = idx & 15;
            float4 v = *(const float4*)&Kg[(size_t)(b*Tc + k0 + kk)*QP + h*HDc + d4*4];
            float4 hv;
            hv.x = __uint_as_float(tf32_hi(v.x));
            hv.y = __uint_as_float(tf32_hi(v.y));
            hv.z = __uint_as_float(tf32_hi(v.z));
            hv.w = __uint_as_float(tf32_hi(v.w));
            *(float4*)&Khi[kk*68 + d4*4] = hv;
        }
        if (tid < 64) {
            int kg = k0 + tid;
            bowK[tid] = (kg < Sc) ? bowlers[b*Sc + kg] : -2;
            batK[tid] = (kg < Sc) ? batters[b*Sc + kg] : -2;
        }
        __syncthreads();   // S1: K staged; all warps past prev AV

        // ---- score MMA: (Qhi + Qlo) x Khi ----
        float acc[2][4] = {{0,0,0,0},{0,0,0,0}};
        #pragma unroll
        for (int kc = 0; kc < 8; ++kc) {
            int ra = r1*68 + kc*8 + tig;
            uint32_t ah0 = __float_as_uint(Qhi[ra]);
            uint32_t ah1 = __float_as_uint(Qhi[ra + 8*68]);
            uint32_t ah2 = __float_as_uint(Qhi[ra + 4]);
            uint32_t ah3 = __float_as_uint(Qhi[ra + 8*68 + 4]);
            uint32_t al0 = __float_as_uint(Qlo[ra]);
            uint32_t al1 = __float_as_uint(Qlo[ra + 8*68]);
            uint32_t al2 = __float_as_uint(Qlo[ra + 4]);
            uint32_t al3 = __float_as_uint(Qlo[ra + 8*68 + 4]);
            #pragma unroll
            for (int j = 0; j < 2; ++j) {
                int rb = (nq*16 + j*8 + gid)*68 + kc*8 + tig;
                uint32_t bh0 = __float_as_uint(Khi[rb]);
                uint32_t bh1 = __float_as_uint(Khi[rb + 4]);
                MMA_TF32(acc[j], al0, al1, al2, al3, bh0, bh1);
                MMA_TF32(acc[j], ah0, ah1, ah2, ah3, bh0, bh1);
            }
        }

        // ---- stage V split hi/lo ----
        #pragma unroll
        for (int it = 0; it < 4; ++it) {
            int idx = tid + it*256;
            int kk = idx >> 4, d4 = idx & 15;
            float4 v = *(const float4*)&Vg[(size_t)(b*Tc + k0 + kk)*QP + h*HDc + d4*4];
            uint32_t h0,l0,h1,l1,h2,l2,h3,l3;
            tf32_split(v.x, h0, l0); tf32_split(v.y, h1, l1);
            tf32_split(v.z, h2, l2); tf32_split(v.w, h3, l3);
            float4 hv, lv;
            hv.x = __uint_as_float(h0); hv.y = __uint_as_float(h1);
            hv.z = __uint_as_float(h2); hv.w = __uint_as_float(h3);
            lv.x = __uint_as_float(l0); lv.y = __uint_as_float(l1);
            lv.z = __uint_as_float(l2); lv.w = __uint_as_float(l3);
            *(float4*)&Vhi[kk*72 + d4*4] = hv;
            *(float4*)&Vlo[kk*72 + d4*4] = lv;
        }

        // ---- score epilogue: scale + bias + causal ----
        float sv[2][4];
        int bq1 = bowQ[r1], aq1 = batQ[r1];
        int bq2 = bowQ[r2], aq2 = batQ[r2];
        #pragma unroll
        for (int j = 0; j < 2; ++j) {
            int kl = nq*16 + j*8 + 2*tig;
            int kg = k0 + kl;
            float s00 = acc[j][0]*scl, s01 = acc[j][1]*scl;
            float s10 = acc[j][2]*scl, s11 = acc[j][3]*scl;
            if (h == 0) {
                s00 += recw * (float)kg     * (1.0f/512.0f);
                s01 += recw * (float)(kg+1) * (1.0f/512.0f);
                s10 += recw * (float)kg     * (1.0f/512.0f);
                s11 += recw * (float)(kg+1) * (1.0f/512.0f);
            } else if (h == 1) {
                int k1b = bowK[kl], k2b = bowK[kl+1];
                if (qg1 == Sc || kg   == Sc || bq1 == k1b) s00 += boww;
                if (qg1 == Sc || kg+1 == Sc || bq1 == k2b) s01 += boww;
                if (qg2 == Sc || kg   == Sc || bq2 == k1b) s10 += boww;
                if (qg2 == Sc || kg+1 == Sc || bq2 == k2b) s11 += boww;
            } else if (h == 2) {
                int k1a = batK[kl], k2a = batK[kl+1];
                if (qg1 == Sc || kg   == Sc || aq1 == k1a) s00 += batw;
                if (qg1 == Sc || kg+1 == Sc || aq1 == k2a) s01 += batw;
                if (qg2 == Sc || kg   == Sc || aq2 == k1a) s10 += batw;
                if (qg2 == Sc || kg+1 == Sc || aq2 == k2a) s11 += batw;
            }
            if (kg   > qg1) s00 = -1e30f;
            if (kg+1 > qg1) s01 = -1e30f;
            if (kg   > qg2) s10 = -1e30f;
            if (kg+1 > qg2) s11 = -1e30f;
            sv[j][0] = s00; sv[j][1] = s01; sv[j][2] = s10; sv[j][3] = s11;
        }

        // ---- chunk row-max ----
        float rm1 = fmaxf(fmaxf(sv[0][0], sv[0][1]), fmaxf(sv[1][0], sv[1][1]));
        float rm2 = fmaxf(fmaxf(sv[0][2], sv[0][3]), fmaxf(sv[1][2], sv[1][3]));
        rm1 = fmaxf(rm1, __shfl_xor_sync(0xffffffffu, rm1, 1));
        rm1 = fmaxf(rm1, __shfl_xor_sync(0xffffffffu, rm1, 2));
        rm2 = fmaxf(rm2, __shfl_xor_sync(0xffffffffu, rm2, 1));
        rm2 = fmaxf(rm2, __shfl_xor_sync(0xffffffffu, rm2, 2));
        if (tig == 0) { Mp[r1*4 + nq] = rm1; Mp[r2*4 + nq] = rm2; }
        __syncthreads();   // S2a: Mp visible + V staging complete

        float4 m4a = *(const float4*)&Mp[r1*4];
        float4 m4b = *(const float4*)&Mp[r2*4];
        float mc1 = fmaxf(fmaxf(m4a.x, m4a.y), fmaxf(m4a.z, m4a.w));
        float mc2 = fmaxf(fmaxf(m4b.x, m4b.y), fmaxf(m4b.z, m4b.w));
        float mnew1 = fmaxf(mrun1, mc1);
        float mnew2 = fmaxf(mrun2, mc2);
        float f1 = __expf(mrun1 - mnew1);
        float f2 = __expf(mrun2 - mnew2);

        // ---- exp, write P split hi/lo, partial sums ----
        float ps1 = 0.f, ps2 = 0.f;
        #pragma unroll
        for (int j = 0; j < 2; ++j) {
            int col = nq*16 + j*8 + 2*tig;
            float e00 = __expf(sv[j][0] - mnew1);
            float e01 = __expf(sv[j][1] - mnew1);
            float e10 = __expf(sv[j][2] - mnew2);
            float e11 = __expf(sv[j][3] - mnew2);
            ps1 += e00 + e01;
            ps2 += e10 + e11;
            uint32_t h0,l0,h1,l1;
            tf32_split(e00, h0, l0); tf32_split(e01, h1, l1);
            float2 hv, lv;
            hv.x = __uint_as_float(h0); hv.y = __uint_as_float(h1);
            lv.x = __uint_as_float(l0); lv.y = __uint_as_float(l1);
            *(float2*)&Phi[r1*68 + col] = hv;
            *(float2*)&Plo[r1*68 + col] = lv;
            tf32_split(e10, h0, l0); tf32_split(e11, h1, l1);
            hv.x = __uint_as_float(h0); hv.y = __uint_as_float(h1);
            lv.x = __uint_as_float(l0); lv.y = __uint_as_float(l1);
            *(float2*)&Phi[r2*68 + col] = hv;
            *(float2*)&Plo[r2*68 + col] = lv;
        }
        ps1 += __shfl_xor_sync(0xffffffffu, ps1, 1);
        ps1 += __shfl_xor_sync(0xffffffffu, ps1, 2);
        ps2 += __shfl_xor_sync(0xffffffffu, ps2, 1);
        ps2 += __shfl_xor_sync(0xffffffffu, ps2, 2);
        if (tig == 0) { Sp[r1*4 + nq] = ps1; Sp[r2*4 + nq] = ps2; }

        oacc[0][0] *= f1; oacc[0][1] *= f1; oacc[1][0] *= f1; oacc[1][1] *= f1;
        oacc[0][2] *= f2; oacc[0][3] *= f2; oacc[1][2] *= f2; oacc[1][3] *= f2;
        mrun1 = mnew1; mrun2 = mnew2;
        __syncthreads();   // S2b: P + Sp visible

        float4 s4a = *(const float4*)&Sp[r1*4];
        float4 s4b = *(const float4*)&Sp[r2*4];
        srun1 = srun1*f1 + (s4a.x + s4a.y + s4a.z + s4a.w);
        srun2 = srun2*f2 + (s4b.x + s4b.y + s4b.z + s4b.w);

        // ---- AV MMA (full 3-term, unnormalized) ----
        #pragma unroll
        for (int kc = 0; kc < 8; ++kc) {
            int pa1 = r1*68 + kc*8 + tig;
            int pa2 = r2*68 + kc*8 + tig;
            uint32_t ah0 = __float_as_uint(Phi[pa1]);
            uint32_t ah1 = __float_as_uint(Phi[pa2]);
            uint32_t ah2 = __float_as_uint(Phi[pa1 + 4]);
            uint32_t ah3 = __float_as_uint(Phi[pa2 + 4]);
            uint32_t al0 = __float_as_uint(Plo[pa1]);
            uint32_t al1 = __float_as_uint(Plo[pa2]);
            uint32_t al2 = __float_as_uint(Plo[pa1 + 4]);
            uint32_t al3 = __float_as_uint(Plo[pa2 + 4]);
            #pragma unroll
            for (int j = 0; j < 2; ++j) {
                int n0 = (nq*2 + j)*8;
                int vb0 = (kc*8 + tig    )*72 + n0 + gid;
                int vb1 = (kc*8 + tig + 4)*72 + n0 + gid;
                uint32_t bh0 = __float_as_uint(Vhi[vb0]);
                uint32_t bh1 = __float_as_uint(Vhi[vb1]);
                uint32_t bl0 = __float_as_uint(Vlo[vb0]);
                uint32_t bl1 = __float_as_uint(Vlo[vb1]);
                MMA_TF32(oacc[j], ah0, ah1, ah2, ah3, bl0, bl1);
                MMA_TF32(oacc[j], al0, al1, al2, al3, bh0, bh1);
                MMA_TF32(oacc[j], ah0, ah1, ah2, ah3, bh0, bh1);
            }
        }
    }

    float inv1 = 1.0f / srun1;
    float inv2 = 1.0f / srun2;
    #pragma unroll
    for (int j = 0; j < 2; ++j) {
        int col = (nq*2 + j)*8 + 2*tig;
        float2 o1; o1.x = oacc[j][0]*inv1; o1.y = oacc[j][1]*inv1;
        float2 o2; o2.x = oacc[j][2]*inv2; o2.y = oacc[j][3]*inv2;
        *(float2*)&Og[(size_t)(b*Tc + q0 + r1)*Dc + h*HDc + col] = o1;
        *(float2*)&Og[(size_t)(b*Tc + q0 + r2)*Dc + h*HDc + col] = o2;
    }
}

// ---------------- residual add + LayerNorm: warp-per-token -------------------
__global__ __launch_bounds__(256)
void add_ln_kernel(float* __restrict__ x, const float* __restrict__ r,
                   const float* __restrict__ g, const float* __restrict__ be)
{
    int w = threadIdx.x >> 5;
    int lane = threadIdx.x & 31;
    size_t tok = (size_t)blockIdx.x*8 + w;
    float* xr = x + tok*Dc;
    const float* rr = r + tok*Dc;

    float4 v[4];
    float s = 0.f, s2 = 0.f;
    #pragma unroll
    for (int i = 0; i < 4; ++i) {
        int c = (lane + i*32)*4;
        float4 xv = *(const float4*)&xr[c];
        float4 rv = *(const float4*)&rr[c];
        xv.x += rv.x; xv.y += rv.y; xv.z += rv.z; xv.w += rv.w;
        v[i] = xv;
        s  += xv.x + xv.y + xv.z + xv.w;
        s2 += xv.x*xv.x + xv.y*xv.y + xv.z*xv.z + xv.w*xv.w;
    }
    #pragma unroll
    for (int o = 16; o; o >>= 1) {
        s  += __shfl_xor_sync(0xffffffffu, s,  o);
        s2 += __shfl_xor_sync(0xffffffffu, s2, o);
    }
    float mu  = s * (1.0f/512.0f);
    float var = s2 * (1.0f/512.0f) - mu*mu;
    float rs  = rsqrtf(var + 1e-5f);
    #pragma unroll
    for (int i = 0; i < 4; ++i) {
        int c = (lane + i*32)*4;
        float4 gv = *(const float4*)&g[c];
        float4 bv = *(const float4*)&be[c];
        float4 y;
        y.x = (v[i].x - mu)*rs*gv.x + bv.x;
        y.y = (v[i].y - mu)*rs*gv.y + bv.y;
        y.z = (v[i].z - mu)*rs*gv.z + bv.z;
        y.w = (v[i].w - mu)*rs*gv.w + bv.w;
        *(float4*)&xr[c] = y;
    }
}

// ---------------- output head: out[b] = x[b, T-1] @ Wout + bout -------------
__global__ __launch_bounds__(512)
void out_kernel(const float* __restrict__ x, const float* __restrict__ Wout,
                const float* __restrict__ bout, float* __restrict__ out)
{
    int b = blockIdx.x;
    int n = threadIdx.x;
    __shared__ float xs[512];
    xs[n] = x[(size_t)(b*Tc + Tc - 1)*Dc + n];
    __syncthreads();
    float acc = bout[n];
    #pragma unroll 8
    for (int d = 0; d < Dc; ++d)
        acc += xs[d] * Wout[(size_t)d*Dc + n];
    out[b*Dc + n] = acc;
}

// ---------------- launcher ---------------------------------------------------
extern "C" void kernel_launch(void* const* d_in, const int* in_sizes, int n_in,
                              void* d_out, int out_size)
{
    const float* runs    = (const float*)d_in[0];
    const float* wickets = (const float*)d_in[1];
    const float* overs   = (const float*)d_in[2];
    const int*   batters = (const int*)  d_in[3];
    const int*   bowlers = (const int*)  d_in[4];
    const float* pemb    = (const float*)d_in[5];
    const float* Wf      = (const float*)d_in[6];
    const float* bf      = (const float*)d_in[7];
    const float* qtok    = (const float*)d_in[8];
    const float* Wq      = (const float*)d_in[9];
    const float* bq      = (const float*)d_in[10];
    const float* Wk      = (const float*)d_in[11];
    const float* bk      = (const float*)d_in[12];
    const float* Wv      = (const float*)d_in[13];
    const float* bv      = (const float*)d_in[14];
    const float* Wo      = (const float*)d_in[15];
    const float* bo      = (const float*)d_in[16];
    const float* rec_s   = (const float*)d_in[17];
    const float* bow_s   = (const float*)d_in[18];
    const float* bat_s   = (const float*)d_in[19];
    const float* W1      = (const float*)d_in[20];
    const float* b1      = (const float*)d_in[21];
    const float* W2      = (const float*)d_in[22];
    const float* b2      = (const float*)d_in[23];
    const float* g1      = (const float*)d_in[24];
    const float* be1     = (const float*)d_in[25];
    const float* g2      = (const float*)d_in[26];
    const float* be2     = (const float*)d_in[27];
    const float* Wout    = (const float*)d_in[28];
    const float* bout    = (const float*)d_in[29];
    float* out = (float*)d_out;

    float *x_, *att_, *tmp_, *ff_, *wqkv_, *bqkv_;
    cudaGetSymbolAddress((void**)&x_,    g_x);
    cudaGetSymbolAddress((void**)&att_,  g_att);
    cudaGetSymbolAddress((void**)&tmp_,  g_tmp);
    cudaGetSymbolAddress((void**)&ff_,   g_ff);
    cudaGetSymbolAddress((void**)&wqkv_, g_wqkv);
    cudaGetSymbolAddress((void**)&bqkv_, g_bqkv);

    cudaFuncSetAttribute(attn8_kernel,
                         cudaFuncAttributeMaxDynamicSharedMemorySize, ATTN8_SMEM);
    cudaFuncSetAttribute(tgemm_kernel<0>,
                         cudaFuncAttributeMaxDynamicSharedMemorySize, TGEMM_SMEM);
    cudaFuncSetAttribute(tgemm_kernel<1>,
                         cudaFuncAttributeMaxDynamicSharedMemorySize, TGEMM_SMEM);

    pack_qkv_kernel<<<Lc*Dc, 512>>>(Wq, Wk, Wv, wqkv_);
    pack_bqkv_kernel<<<Lc, 512>>>(bq, bk, bv, bqkv_);

    embed_kernel<<<Bc*Tc, 512>>>(runs, wickets, overs, batters, bowlers,
                                 pemb, Wf, bf, qtok, x_);

    dim3 g512 (Dc/TBN,   Mc/TBM);   // (4, 128)
    dim3 gQKV (QP/TBN,   Mc/TBM);   // (12, 128)
    dim3 g2048(DFFc/TBN, Mc/TBM);   // (16, 128)
    dim3 gattn(16, Hc, Bc);

    for (int l = 0; l < Lc; ++l) {
        tgemm_kernel<0><<<gQKV, 256, TGEMM_SMEM>>>(x_, wqkv_ + (size_t)l*Dc*QP,
                                                   bqkv_ + l*QP, ff_, Mc, QP, Dc);

        attn8_kernel<<<gattn, 256, ATTN8_SMEM>>>(ff_, batters, bowlers,
                                                 rec_s, bow_s, bat_s, l, att_);

        tgemm_kernel<0><<<g512, 256, TGEMM_SMEM>>>(att_, Wo + (size_t)l*Dc*Dc,
                                                   bo + l*Dc, tmp_, Mc, Dc, Dc);
        add_ln_kernel<<<Mc/8, 256>>>(x_, tmp_, g1 + l*Dc, be1 + l*Dc);

        tgemm_kernel<1><<<g2048, 256, TGEMM_SMEM>>>(x_, W1 + (size_t)l*Dc*DFFc,
                                                    b1 + l*DFFc, ff_, Mc, DFFc, Dc);
        tgemm_kernel<0><<<g512, 256, TGEMM_SMEM>>>(ff_, W2 + (size_t)l*DFFc*Dc,
                                                   b2 + l*Dc, tmp_, Mc, Dc, DFFc);
        add_ln_kernel<<<Mc/8, 256>>>(x_, tmp_, g2 + l*Dc, be2 + l*Dc);
    }

    out_kernel<<<Bc, 512>>>(x_, Wout, bout, out);
}

// round 14
// speedup vs baseline: 1.8031x; 1.7000x over previous
#include <cuda_runtime.h>
#include <cuda_fp16.h>
#include <math_constants.h>
#include <cstdint>

// Problem constants
#define Bc   32
#define Sc   511
#define Tc   512
#define Dc   512
#define Hc   8
#define HDc  64
#define Lc   4
#define PDc  32
#define FDc  448     // D - 2*PD
#define DFFc 2048
#define Mc   (Bc*Tc) // 16384 tokens
#define QP   1536    // qkv combined pitch

// ---------------- scratch (device globals; no allocation allowed) ----------
__device__ float  g_x    [Mc*Dc];
__device__ __half g_x16  [Mc*Dc];
__device__ __half g_att16[Mc*Dc];
__device__ float  g_tmp  [Mc*Dc];
__device__ __half g_qkv16[Mc*QP];
__device__ __half g_ff16 [Mc*DFFc];
__device__ __half g_wqkvT[(size_t)Lc*QP*Dc];    // [l][n=1536][k=512]
__device__ __half g_woT  [(size_t)Lc*Dc*Dc];    // [l][n=512][k=512]
__device__ __half g_w1T  [(size_t)Lc*DFFc*Dc];  // [l][n=2048][k=512]
__device__ __half g_w2T  [(size_t)Lc*Dc*DFFc];  // [l][n=512][k=2048]
__device__ float  g_bqkv [Lc*QP];

// ---------------- helpers -----------------------------------------------------
__device__ __forceinline__ uint32_t smem_u32(const void* p) {
    return (uint32_t)__cvta_generic_to_shared(p);
}
#define MMA_F16(ACC, A0,A1,A2,A3, B0,B1) \
    asm volatile( \
        "mma.sync.aligned.m16n8k16.row.col.f32.f16.f16.f32 " \
        "{%0,%1,%2,%3}, {%4,%5,%6,%7}, {%8,%9}, {%0,%1,%2,%3};\n" \
        : "+f"((ACC)[0]), "+f"((ACC)[1]), "+f"((ACC)[2]), "+f"((ACC)[3]) \
        : "r"(A0), "r"(A1), "r"(A2), "r"(A3), "r"(B0), "r"(B1))
#define MMA_TF32(ACC, A0,A1,A2,A3, B0,B1) \
    asm volatile( \
        "mma.sync.aligned.m16n8k8.row.col.f32.tf32.tf32.f32 " \
        "{%0,%1,%2,%3}, {%4,%5,%6,%7}, {%8,%9}, {%0,%1,%2,%3};\n" \
        : "+f"((ACC)[0]), "+f"((ACC)[1]), "+f"((ACC)[2]), "+f"((ACC)[3]) \
        : "r"(A0), "r"(A1), "r"(A2), "r"(A3), "r"(B0), "r"(B1))
__device__ __forceinline__ uint32_t tf32_hi(float v) {
    uint32_t r; asm("cvt.rna.tf32.f32 %0, %1;" : "=r"(r) : "f"(v)); return r;
}

// ---------------- weight transpose + fp16 convert ----------------------------
// Wt[n][k] = (half)W[k][n]; blockIdx.z picks layer via srcZ/dstZ strides.
__global__ __launch_bounds__(256)
void transpose_cvt_kernel(const float* __restrict__ W, __half* __restrict__ Wt,
                          int K, int N, size_t srcZ, size_t dstZ)
{
    __shared__ float t[32][33];
    const float* Ws = W  + (size_t)blockIdx.z*srcZ;
    __half*      Wd = Wt + (size_t)blockIdx.z*dstZ;
    int n0 = blockIdx.x*32, k0 = blockIdx.y*32;
    int tx = threadIdx.x & 31, ty = threadIdx.x >> 5;   // 32 x 8
    #pragma unroll
    for (int i = 0; i < 4; ++i)
        t[ty + i*8][tx] = Ws[(size_t)(k0 + ty + i*8)*N + n0 + tx];
    __syncthreads();
    #pragma unroll
    for (int i = 0; i < 4; ++i)
        Wd[(size_t)(n0 + ty + i*8)*K + k0 + tx] = __float2half(t[tx][ty + i*8]);
}

__global__ __launch_bounds__(512)
void pack_bqkv_kernel(const float* __restrict__ bq, const float* __restrict__ bk,
                      const float* __restrict__ bv, float* __restrict__ bqkv)
{
    int l = blockIdx.x;
    int j = threadIdx.x;
    bqkv[l*QP + j       ] = bq[l*Dc + j];
    bqkv[l*QP + j + Dc  ] = bk[l*Dc + j];
    bqkv[l*QP + j + 2*Dc] = bv[l*Dc + j];
}

// ---------------- embedding + positional encoding ---------------------------
__global__ void embed_kernel(const float* __restrict__ runs,
                             const float* __restrict__ wickets,
                             const float* __restrict__ overs,
                             const int*   __restrict__ batters,
                             const int*   __restrict__ bowlers,
                             const float* __restrict__ pemb,
                             const float* __restrict__ Wf,
                             const float* __restrict__ bf,
                             const float* __restrict__ qtok,
                             float* __restrict__ x, __half* __restrict__ x16)
{
    int bt = blockIdx.x;
    int b  = bt / Tc;
    int t  = bt % Tc;
    int j  = threadIdx.x;

    float val;
    if (t < Sc) {
        if (j < FDc) {
            float r = runs   [b*Sc + t];
            float w = wickets[b*Sc + t];
            float o = overs  [b*Sc + t];
            val = r*Wf[j] + w*Wf[FDc + j] + o*Wf[2*FDc + j] + bf[j];
        } else if (j < FDc + PDc) {
            val = pemb[batters[b*Sc + t]*PDc + (j - FDc)];
        } else {
            val = pemb[bowlers[b*Sc + t]*PDc + (j - FDc - PDc)];
        }
    } else {
        val = qtok[j];
    }
    int   i2  = j & ~1;
    float dv  = expf((float)i2 * -0.0179889460390111f);
    float ang = (float)t * dv;
    val += (j & 1) ? cosf(ang) : sinf(ang);
    size_t idx = (size_t)(b*Tc + t)*Dc + j;
    x[idx]   = val;
    x16[idx] = __float2half(val);
}

// ---------------- fp16 tensor-core GEMM --------------------------------------
// C[M,N] = A[M,K](fp16) @ Wt[N,K](fp16)^T + bias.  CTA 128x128, TBK=64.
// 256 threads, 8 warps (2x4), warp tile 64x32. 3-stage cp.async, 1 sync/chunk.
// smem: half2 tiles, pitch 36 half2 per row (conflict-free: gid*4+tig mod 32).
#define PW   36
#define TG16_STAGE (2*128*PW)            // uint32 words per stage (A+B)
#define TG16_SMEM  (3*TG16_STAGE*4)      // 110592 bytes

__device__ __forceinline__ void tg16_load(
    const __half* __restrict__ A, const __half* __restrict__ Wt,
    uint32_t* __restrict__ stage, int bm, int bn, int k0, int K, int tid)
{
    uint32_t* As = stage;
    uint32_t* Bs = stage + 128*PW;
    #pragma unroll
    for (int it = 0; it < 4; ++it) {
        int idx = tid + it*256;
        int r = idx >> 3, q = idx & 7;
        const __half* ap = A + (size_t)(bm*128 + r)*K + k0 + q*8;
        uint32_t ad = smem_u32(As + r*PW + q*4);
        asm volatile("cp.async.cg.shared.global [%0], [%1], 16;\n" :: "r"(ad), "l"(ap));
    }
    #pragma unroll
    for (int it = 0; it < 4; ++it) {
        int idx = tid + it*256;
        int r = idx >> 3, q = idx & 7;
        const __half* bp = Wt + (size_t)(bn*128 + r)*K + k0 + q*8;
        uint32_t bd = smem_u32(Bs + r*PW + q*4);
        asm volatile("cp.async.cg.shared.global [%0], [%1], 16;\n" :: "r"(bd), "l"(bp));
    }
    asm volatile("cp.async.commit_group;\n");
}

// OUT: 0 = fp32 C, 1 = fp16 C, 2 = fp16 C + exact GELU
template<int OUT>
__global__ __launch_bounds__(256, 2)
void tg16_kernel(const __half* __restrict__ A, const __half* __restrict__ Wt,
                 const float* __restrict__ bias, void* __restrict__ Cv,
                 int M, int N, int K)
{
    extern __shared__ uint32_t smw[];
    int tid = threadIdx.x;
    int bm = blockIdx.y, bn = blockIdx.x;
    int w = tid >> 5, lane = tid & 31;
    int gid = lane >> 2, tig = lane & 3;
    int wm = w >> 2, wn = w & 3;

    float acc[4][4][4];
    #pragma unroll
    for (int i = 0; i < 4; i++)
        #pragma unroll
        for (int j = 0; j < 4; j++)
            #pragma unroll
            for (int r = 0; r < 4; r++) acc[i][j][r] = 0.f;

    int nkt = K / 64;
    tg16_load(A, Wt, smw, bm, bn, 0, K, tid);
    if (nkt > 1) tg16_load(A, Wt, smw + TG16_STAGE, bm, bn, 64, K, tid);

    for (int kt = 0; kt < nkt; ++kt) {
        if (kt + 1 < nkt) asm volatile("cp.async.wait_group 1;\n");
        else              asm volatile("cp.async.wait_group 0;\n");
        __syncthreads();
        if (kt + 2 < nkt)
            tg16_load(A, Wt, smw + ((kt+2)%3)*TG16_STAGE, bm, bn, (kt+2)*64, K, tid);

        const uint32_t* As = smw + (kt%3)*TG16_STAGE;
        const uint32_t* Bs = As + 128*PW;

        #pragma unroll
        for (int kc = 0; kc < 4; ++kc) {
            uint32_t a[4][4], b[4][2];
            #pragma unroll
            for (int i = 0; i < 4; i++) {
                int r0 = wm*64 + 16*i + gid;
                int ra = r0*PW + kc*8 + tig;
                a[i][0] = As[ra];
                a[i][1] = As[ra + 8*PW];
                a[i][2] = As[ra + 4];
                a[i][3] = As[ra + 8*PW + 4];
            }
            #pragma unroll
            for (int j = 0; j < 4; j++) {
                int c0 = wn*32 + 8*j + gid;
                int rb = c0*PW + kc*8 + tig;
                b[j][0] = Bs[rb];
                b[j][1] = Bs[rb + 4];
            }
            #pragma unroll
            for (int i = 0; i < 4; i++)
                #pragma unroll
                for (int j = 0; j < 4; j++)
                    MMA_F16(acc[i][j], a[i][0], a[i][1], a[i][2], a[i][3],
                            b[j][0], b[j][1]);
        }
    }

    #pragma unroll
    for (int i = 0; i < 4; i++) {
        int r = bm*128 + wm*64 + 16*i + gid;
        #pragma unroll
        for (int j = 0; j < 4; j++) {
            int c = bn*128 + wn*32 + 8*j + 2*tig;
            float bx = bias[c], by = bias[c+1];
            float v0 = acc[i][j][0] + bx;
            float v1 = acc[i][j][1] + by;
            float v2 = acc[i][j][2] + bx;
            float v3 = acc[i][j][3] + by;
            if (OUT == 2) {
                v0 = 0.5f*v0*(1.0f + erff(v0*0.70710678118654752f));
                v1 = 0.5f*v1*(1.0f + erff(v1*0.70710678118654752f));
                v2 = 0.5f*v2*(1.0f + erff(v2*0.70710678118654752f));
                v3 = 0.5f*v3*(1.0f + erff(v3*0.70710678118654752f));
            }
            if (OUT == 0) {
                float* C = (float*)Cv;
                float2 p0; p0.x = v0; p0.y = v1;
                float2 p1; p1.x = v2; p1.y = v3;
                *(float2*)&C[(size_t)r*N + c]     = p0;
                *(float2*)&C[(size_t)(r+8)*N + c] = p1;
            } else {
                __half* C = (__half*)Cv;
                *(__half2*)&C[(size_t)r*N + c]     = __floats2half2_rn(v0, v1);
                *(__half2*)&C[(size_t)(r+8)*N + c] = __floats2half2_rn(v2, v3);
            }
        }
    }
}

// ---------------- fused attention v9: fp16 QK, tf32 single-term AV -----------
// 32 q rows/block, grid (16,H,B), 256 threads, 64-key chunks, online softmax.
// smem words: Qs(h2) 1152 | Ks(h2) 2304 | Vhi 4608 | Phi 2176 | Mp 128 | Sp 128 | ids 192
#define ATTN9_SMEM (10688*4)

__global__ __launch_bounds__(256)
void attn9_kernel(const __half* __restrict__ qkv,
                  const int* __restrict__ batters, const int* __restrict__ bowlers,
                  const float* __restrict__ rec_s, const float* __restrict__ bow_s,
                  const float* __restrict__ bat_s, int layer,
                  __half* __restrict__ Og)
{
    extern __shared__ float sm[];
    uint32_t* Qs = (uint32_t*)sm;            // [32][36] half2
    uint32_t* Ks = Qs + 1152;                // [64][36] half2
    float* Vhi = sm + 3456;                  // [64][72]
    float* Phi = sm + 8064;                  // [32][68]
    float* Mp  = sm + 10240;                 // [32][4]
    float* Sp  = sm + 10368;                 // [32][4]
    int*   ib  = (int*)(sm + 10496);
    int* bowQ = ib;       int* batQ = ib + 32;
    int* bowK = ib + 64;  int* batK = ib + 128;

    int qt = blockIdx.x, h = blockIdx.y, b = blockIdx.z;
    int tid = threadIdx.x;
    int q0 = qt*32;
    int w = tid >> 5, lane = tid & 31;
    int gid = lane >> 2, tig = lane & 3;
    int mi = w >> 2, nq = w & 3;
    int r1 = mi*16 + gid, r2 = r1 + 8;

    // stage Q (pure 16B copies): 32 rows x 8 chunks = 256 -> 1/thread
    {
        int r = tid >> 3, q = tid & 7;
        uint4 v = *(const uint4*)&qkv[(size_t)(b*Tc + q0 + r)*QP + h*HDc + q*8];
        *(uint4*)&Qs[r*36 + q*4] = v;
    }
    if (tid < 32) {
        int qg = q0 + tid;
        bowQ[tid] = (qg < Sc) ? bowlers[b*Sc + qg] : -1;
        batQ[tid] = (qg < Sc) ? batters[b*Sc + qg] : -1;
    }

    int ktmax = (q0 + 32 + 63) >> 6;
    const float scl  = 0.125f;
    const float recw = rec_s[layer];
    const float boww = bow_s[layer];
    const float batw = bat_s[layer];
    int qg1 = q0 + r1, qg2 = q0 + r2;

    float oacc[2][4] = {{0,0,0,0},{0,0,0,0}};
    float mrun1 = -1e30f, mrun2 = -1e30f;
    float srun1 = 0.f,    srun2 = 0.f;

    for (int kt = 0; kt < ktmax; ++kt) {
        int k0 = kt << 6;

        // ---- stage K (pure copies): 64 keys x 8 chunks = 512 -> 2/thread ----
        #pragma unroll
        for (int it = 0; it < 2; ++it) {
            int idx = tid + it*256;
            int kk = idx >> 3, q = idx & 7;
            uint4 v = *(const uint4*)&qkv[(size_t)(b*Tc + k0 + kk)*QP + Dc + h*HDc + q*8];
            *(uint4*)&Ks[kk*36 + q*4] = v;
        }
        if (tid < 64) {
            int kg = k0 + tid;
            bowK[tid] = (kg < Sc) ? bowlers[b*Sc + kg] : -2;
            batK[tid] = (kg < Sc) ? batters[b*Sc + kg] : -2;
        }
        __syncthreads();   // S1: Q/K staged; all warps past prev AV

        // ---- score MMA (fp16 single pass, 4 ksteps of k16) ----
        float acc[2][4] = {{0,0,0,0},{0,0,0,0}};
        #pragma unroll
        for (int kc = 0; kc < 4; ++kc) {
            int ra = r1*36 + kc*8 + tig;
            uint32_t a0 = Qs[ra];
            uint32_t a1 = Qs[ra + 8*36];
            uint32_t a2 = Qs[ra + 4];
            uint32_t a3 = Qs[ra + 8*36 + 4];
            #pragma unroll
            for (int j = 0; j < 2; ++j) {
                int rb = (nq*16 + j*8 + gid)*36 + kc*8 + tig;
                uint32_t b0 = Ks[rb];
                uint32_t b1 = Ks[rb + 4];
                MMA_F16(acc[j], a0, a1, a2, a3, b0, b1);
            }
        }

        // ---- stage V (cvt half->float, exact): 512 chunks of 8 halves ----
        #pragma unroll
        for (int it = 0; it < 2; ++it) {
            int idx = tid + it*256;
            int kk = idx >> 3, q = idx & 7;
            const __half2* vp = (const __half2*)&qkv[(size_t)(b*Tc + k0 + kk)*QP + 2*Dc + h*HDc + q*8];
            float2 f0 = __half22float2(vp[0]);
            float2 f1 = __half22float2(vp[1]);
            float2 f2 = __half22float2(vp[2]);
            float2 f3 = __half22float2(vp[3]);
            float4 o0; o0.x = f0.x; o0.y = f0.y; o0.z = f1.x; o0.w = f1.y;
            float4 o1; o1.x = f2.x; o1.y = f2.y; o1.z = f3.x; o1.w = f3.y;
            *(float4*)&Vhi[kk*72 + q*8]     = o0;
            *(float4*)&Vhi[kk*72 + q*8 + 4] = o1;
        }

        // ---- score epilogue: scale + bias + causal ----
        float sv[2][4];
        int bq1 = bowQ[r1], aq1 = batQ[r1];
        int bq2 = bowQ[r2], aq2 = batQ[r2];
        #pragma unroll
        for (int j = 0; j < 2; ++j) {
            int kl = nq*16 + j*8 + 2*tig;
            int kg = k0 + kl;
            float s00 = acc[j][0]*scl, s01 = acc[j][1]*scl;
            float s10 = acc[j][2]*scl, s11 = acc[j][3]*scl;
            if (h == 0) {
                s00 += recw * (float)kg     * (1.0f/512.0f);
                s01 += recw * (float)(kg+1) * (1.0f/512.0f);
                s10 += recw * (float)kg     * (1.0f/512.0f);
                s11 += recw * (float)(kg+1) * (1.0f/512.0f);
            } else if (h == 1) {
                int k1b = bowK[kl], k2b = bowK[kl+1];
                if (qg1 == Sc || kg   == Sc || bq1 == k1b) s00 += boww;
                if (qg1 == Sc || kg+1 == Sc || bq1 == k2b) s01 += boww;
                if (qg2 == Sc || kg   == Sc || bq2 == k1b) s10 += boww;
                if (qg2 == Sc || kg+1 == Sc || bq2 == k2b) s11 += boww;
            } else if (h == 2) {
                int k1a = batK[kl], k2a = batK[kl+1];
                if (qg1 == Sc || kg   == Sc || aq1 == k1a) s00 += batw;
                if (qg1 == Sc || kg+1 == Sc || aq1 == k2a) s01 += batw;
                if (qg2 == Sc || kg   == Sc || aq2 == k1a) s10 += batw;
                if (qg2 == Sc || kg+1 == Sc || aq2 == k2a) s11 += batw;
            }
            if (kg   > qg1) s00 = -1e30f;
            if (kg+1 > qg1) s01 = -1e30f;
            if (kg   > qg2) s10 = -1e30f;
            if (kg+1 > qg2) s11 = -1e30f;
            sv[j][0] = s00; sv[j][1] = s01; sv[j][2] = s10; sv[j][3] = s11;
        }

        // ---- chunk row-max ----
        float rm1 = fmaxf(fmaxf(sv[0][0], sv[0][1]), fmaxf(sv[1][0], sv[1][1]));
        float rm2 = fmaxf(fmaxf(sv[0][2], sv[0][3]), fmaxf(sv[1][2], sv[1][3]));
        rm1 = fmaxf(rm1, __shfl_xor_sync(0xffffffffu, rm1, 1));
        rm1 = fmaxf(rm1, __shfl_xor_sync(0xffffffffu, rm1, 2));
        rm2 = fmaxf(rm2, __shfl_xor_sync(0xffffffffu, rm2, 1));
        rm2 = fmaxf(rm2, __shfl_xor_sync(0xffffffffu, rm2, 2));
        if (tig == 0) { Mp[r1*4 + nq] = rm1; Mp[r2*4 + nq] = rm2; }
        __syncthreads();   // S2a: Mp visible + V staging complete

        float4 m4a = *(const float4*)&Mp[r1*4];
        float4 m4b = *(const float4*)&Mp[r2*4];
        float mc1 = fmaxf(fmaxf(m4a.x, m4a.y), fmaxf(m4a.z, m4a.w));
        float mc2 = fmaxf(fmaxf(m4b.x, m4b.y), fmaxf(m4b.z, m4b.w));
        float mnew1 = fmaxf(mrun1, mc1);
        float mnew2 = fmaxf(mrun2, mc2);
        float f1 = __expf(mrun1 - mnew1);
        float f2 = __expf(mrun2 - mnew2);

        // ---- exp, write Phi (tf32-hi), partial sums ----
        float ps1 = 0.f, ps2 = 0.f;
        #pragma unroll
        for (int j = 0; j < 2; ++j) {
            int col = nq*16 + j*8 + 2*tig;
            float e00 = __expf(sv[j][0] - mnew1);
            float e01 = __expf(sv[j][1] - mnew1);
            float e10 = __expf(sv[j][2] - mnew2);
            float e11 = __expf(sv[j][3] - mnew2);
            ps1 += e00 + e01;
            ps2 += e10 + e11;
            float2 hv;
            hv.x = __uint_as_float(tf32_hi(e00));
            hv.y = __uint_as_float(tf32_hi(e01));
            *(float2*)&Phi[r1*68 + col] = hv;
            hv.x = __uint_as_float(tf32_hi(e10));
            hv.y = __uint_as_float(tf32_hi(e11));
            *(float2*)&Phi[r2*68 + col] = hv;
        }
        ps1 += __shfl_xor_sync(0xffffffffu, ps1, 1);
        ps1 += __shfl_xor_sync(0xffffffffu, ps1, 2);
        ps2 += __shfl_xor_sync(0xffffffffu, ps2, 1);
        ps2 += __shfl_xor_sync(0xffffffffu, ps2, 2);
        if (tig == 0) { Sp[r1*4 + nq] = ps1; Sp[r2*4 + nq] = ps2; }

        oacc[0][0] *= f1; oacc[0][1] *= f1; oacc[1][0] *= f1; oacc[1][1] *= f1;
        oacc[0][2] *= f2; oacc[0][3] *= f2; oacc[1][2] *= f2; oacc[1][3] *= f2;
        mrun1 = mnew1; mrun2 = mnew2;
        __syncthreads();   // S2b: Phi + Sp visible

        float4 s4a = *(const float4*)&Sp[r1*4];
        float4 s4b = *(const float4*)&Sp[r2*4];
        srun1 = srun1*f1 + (s4a.x + s4a.y + s4a.z + s4a.w);
        srun2 = srun2*f2 + (s4b.x + s4b.y + s4b.z + s4b.w);

        // ---- AV MMA (tf32 single term, unnormalized) ----
        #pragma unroll
        for (int kc = 0; kc < 8; ++kc) {
            int pa1 = r1*68 + kc*8 + tig;
            int pa2 = r2*68 + kc*8 + tig;
            uint32_t ah0 = __float_as_uint(Phi[pa1]);
            uint32_t ah1 = __float_as_uint(Phi[pa2]);
            uint32_t ah2 = __float_as_uint(Phi[pa1 + 4]);
            uint32_t ah3 = __float_as_uint(Phi[pa2 + 4]);
            #pragma unroll
            for (int j = 0; j < 2; ++j) {
                int n0 = (nq*2 + j)*8;
                uint32_t vh0 = __float_as_uint(Vhi[(kc*8 + tig    )*72 + n0 + gid]);
                uint32_t vh1 = __float_as_uint(Vhi[(kc*8 + tig + 4)*72 + n0 + gid]);
                MMA_TF32(oacc[j], ah0, ah1, ah2, ah3, vh0, vh1);
            }
        }
    }

    float inv1 = 1.0f / srun1;
    float inv2 = 1.0f / srun2;
    #pragma unroll
    for (int j = 0; j < 2; ++j) {
        int col = (nq*2 + j)*8 + 2*tig;
        *(__half2*)&Og[(size_t)(b*Tc + q0 + r1)*Dc + h*HDc + col] =
            __floats2half2_rn(oacc[j][0]*inv1, oacc[j][1]*inv1);
        *(__half2*)&Og[(size_t)(b*Tc + q0 + r2)*Dc + h*HDc + col] =
            __floats2half2_rn(oacc[j][2]*inv2, oacc[j][3]*inv2);
    }
}

// ---------------- residual add + LayerNorm: warp-per-token -------------------
__global__ __launch_bounds__(256)
void add_ln_kernel(float* __restrict__ x, __half* __restrict__ x16,
                   const float* __restrict__ r,
                   const float* __restrict__ g, const float* __restrict__ be)
{
    int w = threadIdx.x >> 5;
    int lane = threadIdx.x & 31;
    size_t tok = (size_t)blockIdx.x*8 + w;
    float* xr = x + tok*Dc;
    const float* rr = r + tok*Dc;
    __half* xh = x16 + tok*Dc;

    float4 v[4];
    float s = 0.f, s2 = 0.f;
    #pragma unroll
    for (int i = 0; i < 4; ++i) {
        int c = (lane + i*32)*4;
        float4 xv = *(const float4*)&xr[c];
        float4 rv = *(const float4*)&rr[c];
        xv.x += rv.x; xv.y += rv.y; xv.z += rv.z; xv.w += rv.w;
        v[i] = xv;
        s  += xv.x + xv.y + xv.z + xv.w;
        s2 += xv.x*xv.x + xv.y*xv.y + xv.z*xv.z + xv.w*xv.w;
    }
    #pragma unroll
    for (int o = 16; o; o >>= 1) {
        s  += __shfl_xor_sync(0xffffffffu, s,  o);
        s2 += __shfl_xor_sync(0xffffffffu, s2, o);
    }
    float mu  = s * (1.0f/512.0f);
    float var = s2 * (1.0f/512.0f) - mu*mu;
    float rs  = rsqrtf(var + 1e-5f);
    #pragma unroll
    for (int i = 0; i < 4; ++i) {
        int c = (lane + i*32)*4;
        float4 gv = *(const float4*)&g[c];
        float4 bv = *(const float4*)&be[c];
        float4 y;
        y.x = (v[i].x - mu)*rs*gv.x + bv.x;
        y.y = (v[i].y - mu)*rs*gv.y + bv.y;
        y.z = (v[i].z - mu)*rs*gv.z + bv.z;
        y.w = (v[i].w - mu)*rs*gv.w + bv.w;
        *(float4*)&xr[c] = y;
        __half2* hp = (__half2*)&xh[c];
        hp[0] = __floats2half2_rn(y.x, y.y);
        hp[1] = __floats2half2_rn(y.z, y.w);
    }
}

// ---------------- output head: out[b] = x[b, T-1] @ Wout + bout -------------
__global__ __launch_bounds__(512)
void out_kernel(const float* __restrict__ x, const float* __restrict__ Wout,
                const float* __restrict__ bout, float* __restrict__ out)
{
    int b = blockIdx.x;
    int n = threadIdx.x;
    __shared__ float xs[512];
    xs[n] = x[(size_t)(b*Tc + Tc - 1)*Dc + n];
    __syncthreads();
    float acc = bout[n];
    #pragma unroll 8
    for (int d = 0; d < Dc; ++d)
        acc += xs[d] * Wout[(size_t)d*Dc + n];
    out[b*Dc + n] = acc;
}

// ---------------- launcher ---------------------------------------------------
extern "C" void kernel_launch(void* const* d_in, const int* in_sizes, int n_in,
                              void* d_out, int out_size)
{
    const float* runs    = (const float*)d_in[0];
    const float* wickets = (const float*)d_in[1];
    const float* overs   = (const float*)d_in[2];
    const int*   batters = (const int*)  d_in[3];
    const int*   bowlers = (const int*)  d_in[4];
    const float* pemb    = (const float*)d_in[5];
    const float* Wf      = (const float*)d_in[6];
    const float* bf      = (const float*)d_in[7];
    const float* qtok    = (const float*)d_in[8];
    const float* Wq      = (const float*)d_in[9];
    const float* bq      = (const float*)d_in[10];
    const float* Wk      = (const float*)d_in[11];
    const float* bk      = (const float*)d_in[12];
    const float* Wv      = (const float*)d_in[13];
    const float* bv      = (const float*)d_in[14];
    const float* Wo      = (const float*)d_in[15];
    const float* bo      = (const float*)d_in[16];
    const float* rec_s   = (const float*)d_in[17];
    const float* bow_s   = (const float*)d_in[18];
    const float* bat_s   = (const float*)d_in[19];
    const float* W1      = (const float*)d_in[20];
    const float* b1      = (const float*)d_in[21];
    const float* W2      = (const float*)d_in[22];
    const float* b2      = (const float*)d_in[23];
    const float* g1      = (const float*)d_in[24];
    const float* be1     = (const float*)d_in[25];
    const float* g2      = (const float*)d_in[26];
    const float* be2     = (const float*)d_in[27];
    const float* Wout    = (const float*)d_in[28];
    const float* bout    = (const float*)d_in[29];
    float* out = (float*)d_out;

    float *x_, *tmp_, *bqkv_;
    __half *x16_, *att16_, *qkv16_, *ff16_, *wqkvT_, *woT_, *w1T_, *w2T_;
    cudaGetSymbolAddress((void**)&x_,     g_x);
    cudaGetSymbolAddress((void**)&x16_,   g_x16);
    cudaGetSymbolAddress((void**)&att16_, g_att16);
    cudaGetSymbolAddress((void**)&tmp_,   g_tmp);
    cudaGetSymbolAddress((void**)&qkv16_, g_qkv16);
    cudaGetSymbolAddress((void**)&ff16_,  g_ff16);
    cudaGetSymbolAddress((void**)&wqkvT_, g_wqkvT);
    cudaGetSymbolAddress((void**)&woT_,   g_woT);
    cudaGetSymbolAddress((void**)&w1T_,   g_w1T);
    cudaGetSymbolAddress((void**)&w2T_,   g_w2T);
    cudaGetSymbolAddress((void**)&bqkv_,  g_bqkv);

    cudaFuncSetAttribute(attn9_kernel,
                         cudaFuncAttributeMaxDynamicSharedMemorySize, ATTN9_SMEM);
    cudaFuncSetAttribute(tg16_kernel<0>,
                         cudaFuncAttributeMaxDynamicSharedMemorySize, TG16_SMEM);
    cudaFuncSetAttribute(tg16_kernel<1>,
                         cudaFuncAttributeMaxDynamicSharedMemorySize, TG16_SMEM);
    cudaFuncSetAttribute(tg16_kernel<2>,
                         cudaFuncAttributeMaxDynamicSharedMemorySize, TG16_SMEM);

    // one-time weight packs: transpose + fp16
    transpose_cvt_kernel<<<dim3(Dc/32, Dc/32, Lc), 256>>>(
        Wq, wqkvT_,                     Dc, Dc, (size_t)Dc*Dc, (size_t)QP*Dc);
    transpose_cvt_kernel<<<dim3(Dc/32, Dc/32, Lc), 256>>>(
        Wk, wqkvT_ + (size_t)Dc*Dc,     Dc, Dc, (size_t)Dc*Dc, (size_t)QP*Dc);
    transpose_cvt_kernel<<<dim3(Dc/32, Dc/32, Lc), 256>>>(
        Wv, wqkvT_ + (size_t)2*Dc*Dc,   Dc, Dc, (size_t)Dc*Dc, (size_t)QP*Dc);
    transpose_cvt_kernel<<<dim3(Dc/32, Dc/32, Lc), 256>>>(
        Wo, woT_,                       Dc, Dc, (size_t)Dc*Dc, (size_t)Dc*Dc);
    transpose_cvt_kernel<<<dim3(DFFc/32, Dc/32, Lc), 256>>>(
        W1, w1T_,                       Dc, DFFc, (size_t)Dc*DFFc, (size_t)DFFc*Dc);
    transpose_cvt_kernel<<<dim3(Dc/32, DFFc/32, Lc), 256>>>(
        W2, w2T_,                       DFFc, Dc, (size_t)DFFc*Dc, (size_t)Dc*DFFc);
    pack_bqkv_kernel<<<Lc, 512>>>(bq, bk, bv, bqkv_);

    embed_kernel<<<Bc*Tc, 512>>>(runs, wickets, overs, batters, bowlers,
                                 pemb, Wf, bf, qtok, x_, x16_);

    dim3 g512 (Dc/128,   Mc/128);   // (4, 128)
    dim3 gQKV (QP/128,   Mc/128);   // (12, 128)
    dim3 g2048(DFFc/128, Mc/128);   // (16, 128)
    dim3 gattn(16, Hc, Bc);

    for (int l = 0; l < Lc; ++l) {
        tg16_kernel<1><<<gQKV, 256, TG16_SMEM>>>(
            x16_, wqkvT_ + (size_t)l*QP*Dc, bqkv_ + l*QP, qkv16_, Mc, QP, Dc);

        attn9_kernel<<<gattn, 256, ATTN9_SMEM>>>(qkv16_, batters, bowlers,
                                                 rec_s, bow_s, bat_s, l, att16_);

        tg16_kernel<0><<<g512, 256, TG16_SMEM>>>(
            att16_, woT_ + (size_t)l*Dc*Dc, bo + l*Dc, tmp_, Mc, Dc, Dc);
        add_ln_kernel<<<Mc/8, 256>>>(x_, x16_, tmp_, g1 + l*Dc, be1 + l*Dc);

        tg16_kernel<2><<<g2048, 256, TG16_SMEM>>>(
            x16_, w1T_ + (size_t)l*DFFc*Dc, b1 + l*DFFc, ff16_, Mc, DFFc, Dc);
        tg16_kernel<0><<<g512, 256, TG16_SMEM>>>(
            ff16_, w2T_ + (size_t)l*Dc*DFFc, b2 + l*Dc, tmp_, Mc, Dc, DFFc);
        add_ln_kernel<<<Mc/8, 256>>>(x_, x16_, tmp_, g2 + l*Dc, be2 + l*Dc);
    }

    out_kernel<<<Bc, 512>>>(x_, Wout, bout, out);
}

// round 15
// speedup vs baseline: 1.8422x; 1.0217x over previous
#include <cuda_runtime.h>
#include <cuda_fp16.h>
#include <math_constants.h>
#include <cstdint>

// Problem constants
#define Bc   32
#define Sc   511
#define Tc   512
#define Dc   512
#define Hc   8
#define HDc  64
#define Lc   4
#define PDc  32
#define FDc  448     // D - 2*PD
#define DFFc 2048
#define Mc   (Bc*Tc) // 16384 tokens
#define QP   1536    // qkv combined pitch

// ---------------- scratch (device globals; no allocation allowed) ----------
__device__ float  g_x    [Mc*Dc];
__device__ __half g_x16  [Mc*Dc];
__device__ __half g_att16[Mc*Dc];
__device__ float  g_tmp  [Mc*Dc];
__device__ __half g_qkv16[Mc*QP];
__device__ __half g_ff16 [Mc*DFFc];
__device__ __half g_wqkvT[(size_t)Lc*QP*Dc];
__device__ __half g_woT  [(size_t)Lc*Dc*Dc];
__device__ __half g_w1T  [(size_t)Lc*DFFc*Dc];
__device__ __half g_w2T  [(size_t)Lc*Dc*DFFc];
__device__ float  g_bqkv [Lc*QP];

// ---------------- helpers -----------------------------------------------------
__device__ __forceinline__ uint32_t smem_u32(const void* p) {
    return (uint32_t)__cvta_generic_to_shared(p);
}
#define MMA_F16(ACC, A0,A1,A2,A3, B0,B1) \
    asm volatile( \
        "mma.sync.aligned.m16n8k16.row.col.f32.f16.f16.f32 " \
        "{%0,%1,%2,%3}, {%4,%5,%6,%7}, {%8,%9}, {%0,%1,%2,%3};\n" \
        : "+f"((ACC)[0]), "+f"((ACC)[1]), "+f"((ACC)[2]), "+f"((ACC)[3]) \
        : "r"(A0), "r"(A1), "r"(A2), "r"(A3), "r"(B0), "r"(B1))
#define MMA_TF32(ACC, A0,A1,A2,A3, B0,B1) \
    asm volatile( \
        "mma.sync.aligned.m16n8k8.row.col.f32.tf32.tf32.f32 " \
        "{%0,%1,%2,%3}, {%4,%5,%6,%7}, {%8,%9}, {%0,%1,%2,%3};\n" \
        : "+f"((ACC)[0]), "+f"((ACC)[1]), "+f"((ACC)[2]), "+f"((ACC)[3]) \
        : "r"(A0), "r"(A1), "r"(A2), "r"(A3), "r"(B0), "r"(B1))
__device__ __forceinline__ uint32_t tf32_hi(float v) {
    uint32_t r; asm("cvt.rna.tf32.f32 %0, %1;" : "=r"(r) : "f"(v)); return r;
}

// ---------------- weight transpose + fp16 convert ----------------------------
__global__ __launch_bounds__(256)
void transpose_cvt_kernel(const float* __restrict__ W, __half* __restrict__ Wt,
                          int K, int N, size_t srcZ, size_t dstZ)
{
    __shared__ float t[32][33];
    const float* Ws = W  + (size_t)blockIdx.z*srcZ;
    __half*      Wd = Wt + (size_t)blockIdx.z*dstZ;
    int n0 = blockIdx.x*32, k0 = blockIdx.y*32;
    int tx = threadIdx.x & 31, ty = threadIdx.x >> 5;
    #pragma unroll
    for (int i = 0; i < 4; ++i)
        t[ty + i*8][tx] = Ws[(size_t)(k0 + ty + i*8)*N + n0 + tx];
    __syncthreads();
    #pragma unroll
    for (int i = 0; i < 4; ++i)
        Wd[(size_t)(n0 + ty + i*8)*K + k0 + tx] = __float2half(t[tx][ty + i*8]);
}

__global__ __launch_bounds__(512)
void pack_bqkv_kernel(const float* __restrict__ bq, const float* __restrict__ bk,
                      const float* __restrict__ bv, float* __restrict__ bqkv)
{
    int l = blockIdx.x;
    int j = threadIdx.x;
    bqkv[l*QP + j       ] = bq[l*Dc + j];
    bqkv[l*QP + j + Dc  ] = bk[l*Dc + j];
    bqkv[l*QP + j + 2*Dc] = bv[l*Dc + j];
}

// ---------------- embedding + positional encoding ---------------------------
__global__ void embed_kernel(const float* __restrict__ runs,
                             const float* __restrict__ wickets,
                             const float* __restrict__ overs,
                             const int*   __restrict__ batters,
                             const int*   __restrict__ bowlers,
                             const float* __restrict__ pemb,
                             const float* __restrict__ Wf,
                             const float* __restrict__ bf,
                             const float* __restrict__ qtok,
                             float* __restrict__ x, __half* __restrict__ x16)
{
    int bt = blockIdx.x;
    int b  = bt / Tc;
    int t  = bt % Tc;
    int j  = threadIdx.x;

    float val;
    if (t < Sc) {
        if (j < FDc) {
            float r = runs   [b*Sc + t];
            float w = wickets[b*Sc + t];
            float o = overs  [b*Sc + t];
            val = r*Wf[j] + w*Wf[FDc + j] + o*Wf[2*FDc + j] + bf[j];
        } else if (j < FDc + PDc) {
            val = pemb[batters[b*Sc + t]*PDc + (j - FDc)];
        } else {
            val = pemb[bowlers[b*Sc + t]*PDc + (j - FDc - PDc)];
        }
    } else {
        val = qtok[j];
    }
    int   i2  = j & ~1;
    float dv  = expf((float)i2 * -0.0179889460390111f);
    float ang = (float)t * dv;
    val += (j & 1) ? cosf(ang) : sinf(ang);
    size_t idx = (size_t)(b*Tc + t)*Dc + j;
    x[idx]   = val;
    x16[idx] = __float2half(val);
}

// ---------------- fp16 tensor-core GEMM --------------------------------------
// OUT: 0 = fp32 C (+ optional residual add), 1 = fp16 C, 2 = fp16 C + GELU
#define PW   36
#define TG16_STAGE (2*128*PW)
#define TG16_SMEM  (3*TG16_STAGE*4)

__device__ __forceinline__ void tg16_load(
    const __half* __restrict__ A, const __half* __restrict__ Wt,
    uint32_t* __restrict__ stage, int bm, int bn, int k0, int K, int tid)
{
    uint32_t* As = stage;
    uint32_t* Bs = stage + 128*PW;
    #pragma unroll
    for (int it = 0; it < 4; ++it) {
        int idx = tid + it*256;
        int r = idx >> 3, q = idx & 7;
        const __half* ap = A + (size_t)(bm*128 + r)*K + k0 + q*8;
        uint32_t ad = smem_u32(As + r*PW + q*4);
        asm volatile("cp.async.cg.shared.global [%0], [%1], 16;\n" :: "r"(ad), "l"(ap));
    }
    #pragma unroll
    for (int it = 0; it < 4; ++it) {
        int idx = tid + it*256;
        int r = idx >> 3, q = idx & 7;
        const __half* bp = Wt + (size_t)(bn*128 + r)*K + k0 + q*8;
        uint32_t bd = smem_u32(Bs + r*PW + q*4);
        asm volatile("cp.async.cg.shared.global [%0], [%1], 16;\n" :: "r"(bd), "l"(bp));
    }
    asm volatile("cp.async.commit_group;\n");
}

template<int OUT>
__global__ __launch_bounds__(256, 2)
void tg16_kernel(const __half* __restrict__ A, const __half* __restrict__ Wt,
                 const float* __restrict__ bias, void* __restrict__ Cv,
                 int M, int N, int K, const float* __restrict__ res)
{
    extern __shared__ uint32_t smw[];
    int tid = threadIdx.x;
    int bm = blockIdx.y, bn = blockIdx.x;
    int w = tid >> 5, lane = tid & 31;
    int gid = lane >> 2, tig = lane & 3;
    int wm = w >> 2, wn = w & 3;

    float acc[4][4][4];
    #pragma unroll
    for (int i = 0; i < 4; i++)
        #pragma unroll
        for (int j = 0; j < 4; j++)
            #pragma unroll
            for (int r = 0; r < 4; r++) acc[i][j][r] = 0.f;

    int nkt = K / 64;
    tg16_load(A, Wt, smw, bm, bn, 0, K, tid);
    if (nkt > 1) tg16_load(A, Wt, smw + TG16_STAGE, bm, bn, 64, K, tid);

    for (int kt = 0; kt < nkt; ++kt) {
        if (kt + 1 < nkt) asm volatile("cp.async.wait_group 1;\n");
        else              asm volatile("cp.async.wait_group 0;\n");
        __syncthreads();
        if (kt + 2 < nkt)
            tg16_load(A, Wt, smw + ((kt+2)%3)*TG16_STAGE, bm, bn, (kt+2)*64, K, tid);

        const uint32_t* As = smw + (kt%3)*TG16_STAGE;
        const uint32_t* Bs = As + 128*PW;

        #pragma unroll
        for (int kc = 0; kc < 4; ++kc) {
            uint32_t a[4][4], b[4][2];
            #pragma unroll
            for (int i = 0; i < 4; i++) {
                int r0 = wm*64 + 16*i + gid;
                int ra = r0*PW + kc*8 + tig;
                a[i][0] = As[ra];
                a[i][1] = As[ra + 8*PW];
                a[i][2] = As[ra + 4];
                a[i][3] = As[ra + 8*PW + 4];
            }
            #pragma unroll
            for (int j = 0; j < 4; j++) {
                int c0 = wn*32 + 8*j + gid;
                int rb = c0*PW + kc*8 + tig;
                b[j][0] = Bs[rb];
                b[j][1] = Bs[rb + 4];
            }
            #pragma unroll
            for (int i = 0; i < 4; i++)
                #pragma unroll
                for (int j = 0; j < 4; j++)
                    MMA_F16(acc[i][j], a[i][0], a[i][1], a[i][2], a[i][3],
                            b[j][0], b[j][1]);
        }
    }

    #pragma unroll
    for (int i = 0; i < 4; i++) {
        int r = bm*128 + wm*64 + 16*i + gid;
        #pragma unroll
        for (int j = 0; j < 4; j++) {
            int c = bn*128 + wn*32 + 8*j + 2*tig;
            float bx = bias[c], by = bias[c+1];
            float v0 = acc[i][j][0] + bx;
            float v1 = acc[i][j][1] + by;
            float v2 = acc[i][j][2] + bx;
            float v3 = acc[i][j][3] + by;
            if (OUT == 2) {
                v0 = 0.5f*v0*(1.0f + erff(v0*0.70710678118654752f));
                v1 = 0.5f*v1*(1.0f + erff(v1*0.70710678118654752f));
                v2 = 0.5f*v2*(1.0f + erff(v2*0.70710678118654752f));
                v3 = 0.5f*v3*(1.0f + erff(v3*0.70710678118654752f));
            }
            if (OUT == 0) {
                float* C = (float*)Cv;
                float2 r0 = *(const float2*)&res[(size_t)r*N + c];
                float2 r1 = *(const float2*)&res[(size_t)(r+8)*N + c];
                float2 p0; p0.x = v0 + r0.x; p0.y = v1 + r0.y;
                float2 p1; p1.x = v2 + r1.x; p1.y = v3 + r1.y;
                *(float2*)&C[(size_t)r*N + c]     = p0;
                *(float2*)&C[(size_t)(r+8)*N + c] = p1;
            } else {
                __half* C = (__half*)Cv;
                *(__half2*)&C[(size_t)r*N + c]     = __floats2half2_rn(v0, v1);
                *(__half2*)&C[(size_t)(r+8)*N + c] = __floats2half2_rn(v2, v3);
            }
        }
    }
}

// ---------------- fused attention v10: 64 q rows, fp16 QK, tf32 AV -----------
// grid (8,H,B), 256 threads. Warp: wm in {0,1} -> 32 rows (2 m16 tiles), nq 0..3.
// smem words: Qs 2304 | Ks 2304 | Vhi 4608 | Phi 4352 | Mp 256 | Sp 256 | ids 256
#define ATTN10_SMEM (14336*4)

__global__ __launch_bounds__(256, 2)
void attn10_kernel(const __half* __restrict__ qkv,
                   const int* __restrict__ batters, const int* __restrict__ bowlers,
                   const float* __restrict__ rec_s, const float* __restrict__ bow_s,
                   const float* __restrict__ bat_s, int layer,
                   __half* __restrict__ Og)
{
    extern __shared__ float sm[];
    uint32_t* Qs = (uint32_t*)sm;            // [64][36] half2
    uint32_t* Ks = Qs + 2304;                // [64][36] half2
    float* Vhi = sm + 4608;                  // [64][72]
    float* Phi = sm + 9216;                  // [64][68]
    float* Mp  = sm + 13568;                 // [64][4]
    float* Sp  = sm + 13824;                 // [64][4]
    int*   ib  = (int*)(sm + 14080);
    int* bowQ = ib;        int* batQ = ib + 64;
    int* bowK = ib + 128;  int* batK = ib + 192;

    int qt = blockIdx.x, h = blockIdx.y, b = blockIdx.z;
    int tid = threadIdx.x;
    int q0 = qt*64;
    int w = tid >> 5, lane = tid & 31;
    int gid = lane >> 2, tig = lane & 3;
    int wm = w >> 2, nq = w & 3;
    int rb0 = wm*32 + gid;   // rows: rb0, +8, +16, +24

    // stage Q (pure copies): 64 rows x 8 uint4 -> 2/thread
    #pragma unroll
    for (int it = 0; it < 2; ++it) {
        int idx = tid + it*256;
        int r = idx >> 3, q = idx & 7;
        uint4 v = *(const uint4*)&qkv[(size_t)(b*Tc + q0 + r)*QP + h*HDc + q*8];
        *(uint4*)&Qs[r*36 + q*4] = v;
    }
    if (tid < 64) {
        int qg = q0 + tid;
        bowQ[tid] = (qg < Sc) ? bowlers[b*Sc + qg] : -1;
        batQ[tid] = (qg < Sc) ? batters[b*Sc + qg] : -1;
    }

    int ktmax = qt + 1;
    const float scl  = 0.125f;
    const float recw = rec_s[layer];
    const float boww = bow_s[layer];
    const float batw = bat_s[layer];

    int qg4[4];
    #pragma unroll
    for (int t = 0; t < 4; ++t) qg4[t] = q0 + rb0 + t*8;
    int bq4[4], aq4[4];

    float oacc[2][2][4];
    #pragma unroll
    for (int t = 0; t < 2; ++t)
        #pragma unroll
        for (int j = 0; j < 2; ++j)
            #pragma unroll
            for (int r = 0; r < 4; ++r) oacc[t][j][r] = 0.f;
    float mrun[4] = {-1e30f, -1e30f, -1e30f, -1e30f};
    float srun[4] = {0.f, 0.f, 0.f, 0.f};

    for (int kt = 0; kt < ktmax; ++kt) {
        int k0 = kt << 6;

        // ---- stage K (pure copies) ----
        #pragma unroll
        for (int it = 0; it < 2; ++it) {
            int idx = tid + it*256;
            int kk = idx >> 3, q = idx & 7;
            uint4 v = *(const uint4*)&qkv[(size_t)(b*Tc + k0 + kk)*QP + Dc + h*HDc + q*8];
            *(uint4*)&Ks[kk*36 + q*4] = v;
        }
        if (tid < 64) {
            int kg = k0 + tid;
            bowK[tid] = (kg < Sc) ? bowlers[b*Sc + kg] : -2;
            batK[tid] = (kg < Sc) ? batters[b*Sc + kg] : -2;
        }
        __syncthreads();   // S1

        if (kt == 0 && tid < 64) { /* ids loaded */ }
        #pragma unroll
        for (int t = 0; t < 4; ++t) {
            bq4[t] = bowQ[rb0 + t*8];
            aq4[t] = batQ[rb0 + t*8];
        }

        // ---- score MMA: fp16, 2 m-tiles x 2 j x 4 ksteps ----
        float acc[2][2][4];
        #pragma unroll
        for (int t = 0; t < 2; ++t)
            #pragma unroll
            for (int j = 0; j < 2; ++j)
                #pragma unroll
                for (int r = 0; r < 4; ++r) acc[t][j][r] = 0.f;
        #pragma unroll
        for (int kc = 0; kc < 4; ++kc) {
            uint32_t bfr[2][2];
            #pragma unroll
            for (int j = 0; j < 2; ++j) {
                int rb = (nq*16 + j*8 + gid)*36 + kc*8 + tig;
                bfr[j][0] = Ks[rb];
                bfr[j][1] = Ks[rb + 4];
            }
            #pragma unroll
            for (int t = 0; t < 2; ++t) {
                int ra = (rb0 + t*16)*36 + kc*8 + tig;
                uint32_t a0 = Qs[ra];
                uint32_t a1 = Qs[ra + 8*36];
                uint32_t a2 = Qs[ra + 4];
                uint32_t a3 = Qs[ra + 8*36 + 4];
                #pragma unroll
                for (int j = 0; j < 2; ++j)
                    MMA_F16(acc[t][j], a0, a1, a2, a3, bfr[j][0], bfr[j][1]);
            }
        }

        // ---- stage V (cvt half->float) ----
        #pragma unroll
        for (int it = 0; it < 2; ++it) {
            int idx = tid + it*256;
            int kk = idx >> 3, q = idx & 7;
            const __half2* vp = (const __half2*)&qkv[(size_t)(b*Tc + k0 + kk)*QP + 2*Dc + h*HDc + q*8];
            float2 f0 = __half22float2(vp[0]);
            float2 f1 = __half22float2(vp[1]);
            float2 f2 = __half22float2(vp[2]);
            float2 f3 = __half22float2(vp[3]);
            float4 o0; o0.x = f0.x; o0.y = f0.y; o0.z = f1.x; o0.w = f1.y;
            float4 o1; o1.x = f2.x; o1.y = f2.y; o1.z = f3.x; o1.w = f3.y;
            *(float4*)&Vhi[kk*72 + q*8]     = o0;
            *(float4*)&Vhi[kk*72 + q*8 + 4] = o1;
        }

        // ---- score epilogue ----
        float sv[2][2][4];  // [tile][j][{r0c0,r0c1,r1c0,r1c1}]
        float rm[4] = {-1e30f, -1e30f, -1e30f, -1e30f};
        #pragma unroll
        for (int t = 0; t < 2; ++t) {
            #pragma unroll
            for (int j = 0; j < 2; ++j) {
                int kl = nq*16 + j*8 + 2*tig;
                int kg = k0 + kl;
                int row0 = 2*t, row1 = 2*t + 1;
                float s00 = acc[t][j][0]*scl, s01 = acc[t][j][1]*scl;
                float s10 = acc[t][j][2]*scl, s11 = acc[t][j][3]*scl;
                if (h == 0) {
                    float r0b = recw * (float)kg     * (1.0f/512.0f);
                    float r1b = recw * (float)(kg+1) * (1.0f/512.0f);
                    s00 += r0b; s01 += r1b; s10 += r0b; s11 += r1b;
                } else if (h == 1) {
                    int k1b = bowK[kl], k2b = bowK[kl+1];
                    if (qg4[row0] == Sc || kg   == Sc || bq4[row0] == k1b) s00 += boww;
                    if (qg4[row0] == Sc || kg+1 == Sc || bq4[row0] == k2b) s01 += boww;
                    if (qg4[row1] == Sc || kg   == Sc || bq4[row1] == k1b) s10 += boww;
                    if (qg4[row1] == Sc || kg+1 == Sc || bq4[row1] == k2b) s11 += boww;
                } else if (h == 2) {
                    int k1a = batK[kl], k2a = batK[kl+1];
                    if (qg4[row0] == Sc || kg   == Sc || aq4[row0] == k1a) s00 += batw;
                    if (qg4[row0] == Sc || kg+1 == Sc || aq4[row0] == k2a) s01 += batw;
                    if (qg4[row1] == Sc || kg   == Sc || aq4[row1] == k1a) s10 += batw;
                    if (qg4[row1] == Sc || kg+1 == Sc || aq4[row1] == k2a) s11 += batw;
                }
                if (kg   > qg4[row0]) s00 = -1e30f;
                if (kg+1 > qg4[row0]) s01 = -1e30f;
                if (kg   > qg4[row1]) s10 = -1e30f;
                if (kg+1 > qg4[row1]) s11 = -1e30f;
                sv[t][j][0] = s00; sv[t][j][1] = s01;
                sv[t][j][2] = s10; sv[t][j][3] = s11;
                rm[row0] = fmaxf(rm[row0], fmaxf(s00, s01));
                rm[row1] = fmaxf(rm[row1], fmaxf(s10, s11));
            }
        }
        #pragma unroll
        for (int t = 0; t < 4; ++t) {
            rm[t] = fmaxf(rm[t], __shfl_xor_sync(0xffffffffu, rm[t], 1));
            rm[t] = fmaxf(rm[t], __shfl_xor_sync(0xffffffffu, rm[t], 2));
        }
        if (tig == 0) {
            #pragma unroll
            for (int t = 0; t < 4; ++t) Mp[(rb0 + t*8)*4 + nq] = rm[t];
        }
        __syncthreads();   // S2a: Mp visible + V staged

        float mnew[4], f[4];
        #pragma unroll
        for (int t = 0; t < 4; ++t) {
            float4 m4 = *(const float4*)&Mp[(rb0 + t*8)*4];
            float mc = fmaxf(fmaxf(m4.x, m4.y), fmaxf(m4.z, m4.w));
            mnew[t] = fmaxf(mrun[t], mc);
            f[t] = __expf(mrun[t] - mnew[t]);
            mrun[t] = mnew[t];
        }

        // ---- exp, write Phi (tf32-hi), partial sums ----
        float ps[4] = {0.f, 0.f, 0.f, 0.f};
        #pragma unroll
        for (int t = 0; t < 2; ++t) {
            #pragma unroll
            for (int j = 0; j < 2; ++j) {
                int col = nq*16 + j*8 + 2*tig;
                int row0 = 2*t, row1 = 2*t + 1;
                float e00 = __expf(sv[t][j][0] - mnew[row0]);
                float e01 = __expf(sv[t][j][1] - mnew[row0]);
                float e10 = __expf(sv[t][j][2] - mnew[row1]);
                float e11 = __expf(sv[t][j][3] - mnew[row1]);
                ps[row0] += e00 + e01;
                ps[row1] += e10 + e11;
                float2 hv;
                hv.x = __uint_as_float(tf32_hi(e00));
                hv.y = __uint_as_float(tf32_hi(e01));
                *(float2*)&Phi[(rb0 + t*16)*68 + col] = hv;
                hv.x = __uint_as_float(tf32_hi(e10));
                hv.y = __uint_as_float(tf32_hi(e11));
                *(float2*)&Phi[(rb0 + t*16 + 8)*68 + col] = hv;
            }
        }
        #pragma unroll
        for (int t = 0; t < 4; ++t) {
            ps[t] += __shfl_xor_sync(0xffffffffu, ps[t], 1);
            ps[t] += __shfl_xor_sync(0xffffffffu, ps[t], 2);
        }
        if (tig == 0) {
            #pragma unroll
            for (int t = 0; t < 4; ++t) Sp[(rb0 + t*8)*4 + nq] = ps[t];
        }

        // rescale running accumulators
        #pragma unroll
        for (int t = 0; t < 2; ++t)
            #pragma unroll
            for (int j = 0; j < 2; ++j) {
                oacc[t][j][0] *= f[2*t];   oacc[t][j][1] *= f[2*t];
                oacc[t][j][2] *= f[2*t+1]; oacc[t][j][3] *= f[2*t+1];
            }
        __syncthreads();   // S2b: Phi + Sp visible

        #pragma unroll
        for (int t = 0; t < 4; ++t) {
            float4 s4 = *(const float4*)&Sp[(rb0 + t*8)*4];
            srun[t] = srun[t]*f[t] + (s4.x + s4.y + s4.z + s4.w);
        }

        // ---- AV MMA (tf32 single term) ----
        #pragma unroll
        for (int kc = 0; kc < 8; ++kc) {
            uint32_t vfr[2][2];
            #pragma unroll
            for (int j = 0; j < 2; ++j) {
                int n0 = (nq*2 + j)*8;
                vfr[j][0] = __float_as_uint(Vhi[(kc*8 + tig    )*72 + n0 + gid]);
                vfr[j][1] = __float_as_uint(Vhi[(kc*8 + tig + 4)*72 + n0 + gid]);
            }
            #pragma unroll
            for (int t = 0; t < 2; ++t) {
                int pa = (rb0 + t*16)*68 + kc*8 + tig;
                uint32_t a0 = __float_as_uint(Phi[pa]);
                uint32_t a1 = __float_as_uint(Phi[pa + 8*68]);
                uint32_t a2 = __float_as_uint(Phi[pa + 4]);
                uint32_t a3 = __float_as_uint(Phi[pa + 8*68 + 4]);
                #pragma unroll
                for (int j = 0; j < 2; ++j)
                    MMA_TF32(oacc[t][j], a0, a1, a2, a3, vfr[j][0], vfr[j][1]);
            }
        }
    }

    float inv[4];
    #pragma unroll
    for (int t = 0; t < 4; ++t) inv[t] = 1.0f / srun[t];
    #pragma unroll
    for (int t = 0; t < 2; ++t) {
        #pragma unroll
        for (int j = 0; j < 2; ++j) {
            int col = (nq*2 + j)*8 + 2*tig;
            int row0 = q0 + rb0 + t*16, row1 = row0 + 8;
            *(__half2*)&Og[(size_t)(b*Tc + row0)*Dc + h*HDc + col] =
                __floats2half2_rn(oacc[t][j][0]*inv[2*t], oacc[t][j][1]*inv[2*t]);
            *(__half2*)&Og[(size_t)(b*Tc + row1)*Dc + h*HDc + col] =
                __floats2half2_rn(oacc[t][j][2]*inv[2*t+1], oacc[t][j][3]*inv[2*t+1]);
        }
    }
}

// ---------------- LayerNorm (input pre-summed): x = LN(tmp) ------------------
__global__ __launch_bounds__(256)
void ln_kernel(float* __restrict__ x, __half* __restrict__ x16,
               const float* __restrict__ tmp,
               const float* __restrict__ g, const float* __restrict__ be)
{
    int w = threadIdx.x >> 5;
    int lane = threadIdx.x & 31;
    size_t tok = (size_t)blockIdx.x*8 + w;
    const float* tr = tmp + tok*Dc;
    float* xr = x + tok*Dc;
    __half* xh = x16 + tok*Dc;

    float4 v[4];
    float s = 0.f, s2 = 0.f;
    #pragma unroll
    for (int i = 0; i < 4; ++i) {
        int c = (lane + i*32)*4;
        float4 xv = *(const float4*)&tr[c];
        v[i] = xv;
        s  += xv.x + xv.y + xv.z + xv.w;
        s2 += xv.x*xv.x + xv.y*xv.y + xv.z*xv.z + xv.w*xv.w;
    }
    #pragma unroll
    for (int o = 16; o; o >>= 1) {
        s  += __shfl_xor_sync(0xffffffffu, s,  o);
        s2 += __shfl_xor_sync(0xffffffffu, s2, o);
    }
    float mu  = s * (1.0f/512.0f);
    float var = s2 * (1.0f/512.0f) - mu*mu;
    float rs  = rsqrtf(var + 1e-5f);
    #pragma unroll
    for (int i = 0; i < 4; ++i) {
        int c = (lane + i*32)*4;
        float4 gv = *(const float4*)&g[c];
        float4 bv = *(const float4*)&be[c];
        float4 y;
        y.x = (v[i].x - mu)*rs*gv.x + bv.x;
        y.y = (v[i].y - mu)*rs*gv.y + bv.y;
        y.z = (v[i].z - mu)*rs*gv.z + bv.z;
        y.w = (v[i].w - mu)*rs*gv.w + bv.w;
        *(float4*)&xr[c] = y;
        __half2* hp = (__half2*)&xh[c];
        hp[0] = __floats2half2_rn(y.x, y.y);
        hp[1] = __floats2half2_rn(y.z, y.w);
    }
}

// ---------------- output head: out[b] = x[b, T-1] @ Wout + bout -------------
__global__ __launch_bounds__(512)
void out_kernel(const float* __restrict__ x, const float* __restrict__ Wout,
                const float* __restrict__ bout, float* __restrict__ out)
{
    int b = blockIdx.x;
    int n = threadIdx.x;
    __shared__ float xs[512];
    xs[n] = x[(size_t)(b*Tc + Tc - 1)*Dc + n];
    __syncthreads();
    float acc = bout[n];
    #pragma unroll 8
    for (int d = 0; d < Dc; ++d)
        acc += xs[d] * Wout[(size_t)d*Dc + n];
    out[b*Dc + n] = acc;
}

// ---------------- launcher ---------------------------------------------------
extern "C" void kernel_launch(void* const* d_in, const int* in_sizes, int n_in,
                              void* d_out, int out_size)
{
    const float* runs    = (const float*)d_in[0];
    const float* wickets = (const float*)d_in[1];
    const float* overs   = (const float*)d_in[2];
    const int*   batters = (const int*)  d_in[3];
    const int*   bowlers = (const int*)  d_in[4];
    const float* pemb    = (const float*)d_in[5];
    const float* Wf      = (const float*)d_in[6];
    const float* bf      = (const float*)d_in[7];
    const float* qtok    = (const float*)d_in[8];
    const float* Wq      = (const float*)d_in[9];
    const float* bq      = (const float*)d_in[10];
    const float* Wk      = (const float*)d_in[11];
    const float* bk      = (const float*)d_in[12];
    const float* Wv      = (const float*)d_in[13];
    const float* bv      = (const float*)d_in[14];
    const float* Wo      = (const float*)d_in[15];
    const float* bo      = (const float*)d_in[16];
    const float* rec_s   = (const float*)d_in[17];
    const float* bow_s   = (const float*)d_in[18];
    const float* bat_s   = (const float*)d_in[19];
    const float* W1      = (const float*)d_in[20];
    const float* b1      = (const float*)d_in[21];
    const float* W2      = (const float*)d_in[22];
    const float* b2      = (const float*)d_in[23];
    const float* g1      = (const float*)d_in[24];
    const float* be1     = (const float*)d_in[25];
    const float* g2      = (const float*)d_in[26];
    const float* be2     = (const float*)d_in[27];
    const float* Wout    = (const float*)d_in[28];
    const float* bout    = (const float*)d_in[29];
    float* out = (float*)d_out;

    float *x_, *tmp_, *bqkv_;
    __half *x16_, *att16_, *qkv16_, *ff16_, *wqkvT_, *woT_, *w1T_, *w2T_;
    cudaGetSymbolAddress((void**)&x_,     g_x);
    cudaGetSymbolAddress((void**)&x16_,   g_x16);
    cudaGetSymbolAddress((void**)&att16_, g_att16);
    cudaGetSymbolAddress((void**)&tmp_,   g_tmp);
    cudaGetSymbolAddress((void**)&qkv16_, g_qkv16);
    cudaGetSymbolAddress((void**)&ff16_,  g_ff16);
    cudaGetSymbolAddress((void**)&wqkvT_, g_wqkvT);
    cudaGetSymbolAddress((void**)&woT_,   g_woT);
    cudaGetSymbolAddress((void**)&w1T_,   g_w1T);
    cudaGetSymbolAddress((void**)&w2T_,   g_w2T);
    cudaGetSymbolAddress((void**)&bqkv_,  g_bqkv);

    cudaFuncSetAttribute(attn10_kernel,
                         cudaFuncAttributeMaxDynamicSharedMemorySize, ATTN10_SMEM);
    cudaFuncSetAttribute(tg16_kernel<0>,
                         cudaFuncAttributeMaxDynamicSharedMemorySize, TG16_SMEM);
    cudaFuncSetAttribute(tg16_kernel<1>,
                         cudaFuncAttributeMaxDynamicSharedMemorySize, TG16_SMEM);
    cudaFuncSetAttribute(tg16_kernel<2>,
                         cudaFuncAttributeMaxDynamicSharedMemorySize, TG16_SMEM);

    transpose_cvt_kernel<<<dim3(Dc/32, Dc/32, Lc), 256>>>(
        Wq, wqkvT_,                     Dc, Dc, (size_t)Dc*Dc, (size_t)QP*Dc);
    transpose_cvt_kernel<<<dim3(Dc/32, Dc/32, Lc), 256>>>(
        Wk, wqkvT_ + (size_t)Dc*Dc,     Dc, Dc, (size_t)Dc*Dc, (size_t)QP*Dc);
    transpose_cvt_kernel<<<dim3(Dc/32, Dc/32, Lc), 256>>>(
        Wv, wqkvT_ + (size_t)2*Dc*Dc,   Dc, Dc, (size_t)Dc*Dc, (size_t)QP*Dc);
    transpose_cvt_kernel<<<dim3(Dc/32, Dc/32, Lc), 256>>>(
        Wo, woT_,                       Dc, Dc, (size_t)Dc*Dc, (size_t)Dc*Dc);
    transpose_cvt_kernel<<<dim3(DFFc/32, Dc/32, Lc), 256>>>(
        W1, w1T_,                       Dc, DFFc, (size_t)Dc*DFFc, (size_t)DFFc*Dc);
    transpose_cvt_kernel<<<dim3(Dc/32, DFFc/32, Lc), 256>>>(
        W2, w2T_,                       DFFc, Dc, (size_t)DFFc*Dc, (size_t)Dc*DFFc);
    pack_bqkv_kernel<<<Lc, 512>>>(bq, bk, bv, bqkv_);

    embed_kernel<<<Bc*Tc, 512>>>(runs, wickets, overs, batters, bowlers,
                                 pemb, Wf, bf, qtok, x_, x16_);

    dim3 g512 (Dc/128,   Mc/128);   // (4, 128)
    dim3 gQKV (QP/128,   Mc/128);   // (12, 128)
    dim3 g2048(DFFc/128, Mc/128);   // (16, 128)
    dim3 gattn(8, Hc, Bc);

    for (int l = 0; l < Lc; ++l) {
        tg16_kernel<1><<<gQKV, 256, TG16_SMEM>>>(
            x16_, wqkvT_ + (size_t)l*QP*Dc, bqkv_ + l*QP, qkv16_, Mc, QP, Dc, nullptr);

        attn10_kernel<<<gattn, 256, ATTN10_SMEM>>>(qkv16_, batters, bowlers,
                                                   rec_s, bow_s, bat_s, l, att16_);

        tg16_kernel<0><<<g512, 256, TG16_SMEM>>>(
            att16_, woT_ + (size_t)l*Dc*Dc, bo + l*Dc, tmp_, Mc, Dc, Dc, x_);
        ln_kernel<<<Mc/8, 256>>>(x_, x16_, tmp_, g1 + l*Dc, be1 + l*Dc);

        tg16_kernel<2><<<g2048, 256, TG16_SMEM>>>(
            x16_, w1T_ + (size_t)l*DFFc*Dc, b1 + l*DFFc, ff16_, Mc, DFFc, Dc, nullptr);
        tg16_kernel<0><<<g512, 256, TG16_SMEM>>>(
            ff16_, w2T_ + (size_t)l*Dc*DFFc, b2 + l*Dc, tmp_, Mc, Dc, DFFc, x_);
        ln_kernel<<<Mc/8, 256>>>(x_, x16_, tmp_, g2 + l*Dc, be2 + l*Dc);
    }

    out_kernel<<<Bc, 512>>>(x_, Wout, bout, out);
}

// round 17
// speedup vs baseline: 1.8741x; 1.0173x over previous
#include <cuda_runtime.h>
#include <cuda_fp16.h>
#include <math_constants.h>
#include <cstdint>

// Problem constants
#define Bc   32
#define Sc   511
#define Tc   512
#define Dc   512
#define Hc   8
#define HDc  64
#define Lc   4
#define PDc  32
#define FDc  448     // D - 2*PD
#define DFFc 2048
#define Mc   (Bc*Tc) // 16384 tokens
#define QP   1536    // qkv combined pitch

// ---------------- scratch (device globals; no allocation allowed) ----------
__device__ float  g_x    [Mc*Dc];
__device__ __half g_x16  [Mc*Dc];
__device__ __half g_att16[Mc*Dc];
__device__ float  g_tmp  [Mc*Dc];
__device__ __half g_qkv16[Mc*QP];
__device__ __half g_ff16 [Mc*DFFc];
__device__ __half g_wqkvT[(size_t)Lc*QP*Dc];
__device__ __half g_woT  [(size_t)Lc*Dc*Dc];
__device__ __half g_w1T  [(size_t)Lc*DFFc*Dc];
__device__ __half g_w2T  [(size_t)Lc*Dc*DFFc];
__device__ float  g_bqkv [Lc*QP];

// ---------------- helpers -----------------------------------------------------
__device__ __forceinline__ uint32_t smem_u32(const void* p) {
    return (uint32_t)__cvta_generic_to_shared(p);
}
__device__ __forceinline__ uint32_t h2_as_u32(__half2 h) {
    return *reinterpret_cast<uint32_t*>(&h);
}
#define MMA_F16(ACC, A0,A1,A2,A3, B0,B1) \
    asm volatile( \
        "mma.sync.aligned.m16n8k16.row.col.f32.f16.f16.f32 " \
        "{%0,%1,%2,%3}, {%4,%5,%6,%7}, {%8,%9}, {%0,%1,%2,%3};\n" \
        : "+f"((ACC)[0]), "+f"((ACC)[1]), "+f"((ACC)[2]), "+f"((ACC)[3]) \
        : "r"(A0), "r"(A1), "r"(A2), "r"(A3), "r"(B0), "r"(B1))

// ---------------- weight transpose + fp16 convert ----------------------------
__global__ __launch_bounds__(256)
void transpose_cvt_kernel(const float* __restrict__ W, __half* __restrict__ Wt,
                          int K, int N, size_t srcZ, size_t dstZ)
{
    __shared__ float t[32][33];
    const float* Ws = W  + (size_t)blockIdx.z*srcZ;
    __half*      Wd = Wt + (size_t)blockIdx.z*dstZ;
    int n0 = blockIdx.x*32, k0 = blockIdx.y*32;
    int tx = threadIdx.x & 31, ty = threadIdx.x >> 5;
    #pragma unroll
    for (int i = 0; i < 4; ++i)
        t[ty + i*8][tx] = Ws[(size_t)(k0 + ty + i*8)*N + n0 + tx];
    __syncthreads();
    #pragma unroll
    for (int i = 0; i < 4; ++i)
        Wd[(size_t)(n0 + ty + i*8)*K + k0 + tx] = __float2half(t[tx][ty + i*8]);
}

__global__ __launch_bounds__(512)
void pack_bqkv_kernel(const float* __restrict__ bq, const float* __restrict__ bk,
                      const float* __restrict__ bv, float* __restrict__ bqkv)
{
    int l = blockIdx.x;
    int j = threadIdx.x;
    bqkv[l*QP + j       ] = bq[l*Dc + j];
    bqkv[l*QP + j + Dc  ] = bk[l*Dc + j];
    bqkv[l*QP + j + 2*Dc] = bv[l*Dc + j];
}

// ---------------- embedding + positional encoding ---------------------------
__global__ void embed_kernel(const float* __restrict__ runs,
                             const float* __restrict__ wickets,
                             const float* __restrict__ overs,
                             const int*   __restrict__ batters,
                             const int*   __restrict__ bowlers,
                             const float* __restrict__ pemb,
                             const float* __restrict__ Wf,
                             const float* __restrict__ bf,
                             const float* __restrict__ qtok,
                             float* __restrict__ x, __half* __restrict__ x16)
{
    int bt = blockIdx.x;
    int b  = bt / Tc;
    int t  = bt % Tc;
    int j  = threadIdx.x;

    float val;
    if (t < Sc) {
        if (j < FDc) {
            float r = runs   [b*Sc + t];
            float w = wickets[b*Sc + t];
            float o = overs  [b*Sc + t];
            val = r*Wf[j] + w*Wf[FDc + j] + o*Wf[2*FDc + j] + bf[j];
        } else if (j < FDc + PDc) {
            val = pemb[batters[b*Sc + t]*PDc + (j - FDc)];
        } else {
            val = pemb[bowlers[b*Sc + t]*PDc + (j - FDc - PDc)];
        }
    } else {
        val = qtok[j];
    }
    int   i2  = j & ~1;
    float dv  = expf((float)i2 * -0.0179889460390111f);
    float ang = (float)t * dv;
    val += (j & 1) ? cosf(ang) : sinf(ang);
    size_t idx = (size_t)(b*Tc + t)*Dc + j;
    x[idx]   = val;
    x16[idx] = __float2half(val);
}

// ---------------- fp16 tensor-core GEMM --------------------------------------
// OUT: 0 = fp32 C + residual add, 1 = fp16 C, 2 = fp16 C + GELU
#define PW   36
#define TG16_STAGE (2*128*PW)
#define TG16_SMEM  (3*TG16_STAGE*4)

__device__ __forceinline__ void tg16_load(
    const __half* __restrict__ A, const __half* __restrict__ Wt,
    uint32_t* __restrict__ stage, int bm, int bn, int k0, int K, int tid)
{
    uint32_t* As = stage;
    uint32_t* Bs = stage + 128*PW;
    #pragma unroll
    for (int it = 0; it < 4; ++it) {
        int idx = tid + it*256;
        int r = idx >> 3, q = idx & 7;
        const __half* ap = A + (size_t)(bm*128 + r)*K + k0 + q*8;
        uint32_t ad = smem_u32(As + r*PW + q*4);
        asm volatile("cp.async.cg.shared.global [%0], [%1], 16;\n" :: "r"(ad), "l"(ap));
    }
    #pragma unroll
    for (int it = 0; it < 4; ++it) {
        int idx = tid + it*256;
        int r = idx >> 3, q = idx & 7;
        const __half* bp = Wt + (size_t)(bn*128 + r)*K + k0 + q*8;
        uint32_t bd = smem_u32(Bs + r*PW + q*4);
        asm volatile("cp.async.cg.shared.global [%0], [%1], 16;\n" :: "r"(bd), "l"(bp));
    }
    asm volatile("cp.async.commit_group;\n");
}

template<int OUT>
__global__ __launch_bounds__(256, 2)
void tg16_kernel(const __half* __restrict__ A, const __half* __restrict__ Wt,
                 const float* __restrict__ bias, void* __restrict__ Cv,
                 int M, int N, int K, const float* __restrict__ res)
{
    extern __shared__ uint32_t smw[];
    int tid = threadIdx.x;
    int bm = blockIdx.y, bn = blockIdx.x;
    int w = tid >> 5, lane = tid & 31;
    int gid = lane >> 2, tig = lane & 3;
    int wm = w >> 2, wn = w & 3;

    float acc[4][4][4];
    #pragma unroll
    for (int i = 0; i < 4; i++)
        #pragma unroll
        for (int j = 0; j < 4; j++)
            #pragma unroll
            for (int r = 0; r < 4; r++) acc[i][j][r] = 0.f;

    int nkt = K / 64;
    tg16_load(A, Wt, smw, bm, bn, 0, K, tid);
    if (nkt > 1) tg16_load(A, Wt, smw + TG16_STAGE, bm, bn, 64, K, tid);

    for (int kt = 0; kt < nkt; ++kt) {
        if (kt + 1 < nkt) asm volatile("cp.async.wait_group 1;\n");
        else              asm volatile("cp.async.wait_group 0;\n");
        __syncthreads();
        if (kt + 2 < nkt)
            tg16_load(A, Wt, smw + ((kt+2)%3)*TG16_STAGE, bm, bn, (kt+2)*64, K, tid);

        const uint32_t* As = smw + (kt%3)*TG16_STAGE;
        const uint32_t* Bs = As + 128*PW;

        #pragma unroll
        for (int kc = 0; kc < 4; ++kc) {
            uint32_t a[4][4], b[4][2];
            #pragma unroll
            for (int i = 0; i < 4; i++) {
                int r0 = wm*64 + 16*i + gid;
                int ra = r0*PW + kc*8 + tig;
                a[i][0] = As[ra];
                a[i][1] = As[ra + 8*PW];
                a[i][2] = As[ra + 4];
                a[i][3] = As[ra + 8*PW + 4];
            }
            #pragma unroll
            for (int j = 0; j < 4; j++) {
                int c0 = wn*32 + 8*j + gid;
                int rb = c0*PW + kc*8 + tig;
                b[j][0] = Bs[rb];
                b[j][1] = Bs[rb + 4];
            }
            #pragma unroll
            for (int i = 0; i < 4; i++)
                #pragma unroll
                for (int j = 0; j < 4; j++)
                    MMA_F16(acc[i][j], a[i][0], a[i][1], a[i][2], a[i][3],
                            b[j][0], b[j][1]);
        }
    }

    #pragma unroll
    for (int i = 0; i < 4; i++) {
        int r = bm*128 + wm*64 + 16*i + gid;
        #pragma unroll
        for (int j = 0; j < 4; j++) {
            int c = bn*128 + wn*32 + 8*j + 2*tig;
            float bx = bias[c], by = bias[c+1];
            float v0 = acc[i][j][0] + bx;
            float v1 = acc[i][j][1] + by;
            float v2 = acc[i][j][2] + bx;
            float v3 = acc[i][j][3] + by;
            if (OUT == 2) {
                v0 = 0.5f*v0*(1.0f + erff(v0*0.70710678118654752f));
                v1 = 0.5f*v1*(1.0f + erff(v1*0.70710678118654752f));
                v2 = 0.5f*v2*(1.0f + erff(v2*0.70710678118654752f));
                v3 = 0.5f*v3*(1.0f + erff(v3*0.70710678118654752f));
            }
            if (OUT == 0) {
                float* C = (float*)Cv;
                float2 r0 = *(const float2*)&res[(size_t)r*N + c];
                float2 r1 = *(const float2*)&res[(size_t)(r+8)*N + c];
                float2 p0; p0.x = v0 + r0.x; p0.y = v1 + r0.y;
                float2 p1; p1.x = v2 + r1.x; p1.y = v3 + r1.y;
                *(float2*)&C[(size_t)r*N + c]     = p0;
                *(float2*)&C[(size_t)(r+8)*N + c] = p1;
            } else {
                __half* C = (__half*)Cv;
                *(__half2*)&C[(size_t)r*N + c]     = __floats2half2_rn(v0, v1);
                *(__half2*)&C[(size_t)(r+8)*N + c] = __floats2half2_rn(v2, v3);
            }
        }
    }
}

// ---------------- fused attention v11: all-fp16 MMA --------------------------
// 64 q rows/block, grid (8,H,B), 256 threads, 64-key chunks, online softmax.
// Scores: Q(fp16) x K(fp16). AV: P(fp16) x Vt(fp16, staged transposed [d][k]).
#define ATTN11_SMEM (9984*4)

__global__ __launch_bounds__(256, 2)
void attn11_kernel(const __half* __restrict__ qkv,
                   const int* __restrict__ batters, const int* __restrict__ bowlers,
                   const float* __restrict__ rec_s, const float* __restrict__ bow_s,
                   const float* __restrict__ bat_s, int layer,
                   __half* __restrict__ Og)
{
    extern __shared__ uint32_t smu[];
    uint32_t* Qs = smu;                  // [64][36] half2 (q row, k=d)
    uint32_t* Ks = smu + 2304;           // [64][36] half2 (k row, k=d)
    uint32_t* Vt = smu + 4608;           // [64 d][36] half2 (col-major V: [d][key])
    uint32_t* Ph = smu + 6912;           // [64 q][36] half2 (P row, k=key)
    float*    Mp = (float*)(smu + 9216); // [64][4]
    float*    Sp = (float*)(smu + 9472); // [64][4]
    int*      ib = (int*)(smu + 9728);
    int* bowQ = ib;        int* batQ = ib + 64;
    int* bowK = ib + 128;  int* batK = ib + 192;

    int qt = blockIdx.x, h = blockIdx.y, b = blockIdx.z;
    int tid = threadIdx.x;
    int q0 = qt*64;
    int w = tid >> 5, lane = tid & 31;
    int gid = lane >> 2, tig = lane & 3;
    int wm = w >> 2, nq = w & 3;
    int rb0 = wm*32 + gid;   // rows rb0, +8, +16, +24

    // stage Q (pure copies)
    #pragma unroll
    for (int it = 0; it < 2; ++it) {
        int idx = tid + it*256;
        int r = idx >> 3, q = idx & 7;
        uint4 v = *(const uint4*)&qkv[(size_t)(b*Tc + q0 + r)*QP + h*HDc + q*8];
        *(uint4*)&Qs[r*36 + q*4] = v;
    }
    if (tid < 64) {
        int qg = q0 + tid;
        bowQ[tid] = (qg < Sc) ? bowlers[b*Sc + qg] : -1;
        batQ[tid] = (qg < Sc) ? batters[b*Sc + qg] : -1;
    }

    int ktmax = qt + 1;
    const float scl  = 0.125f;
    const float recw = rec_s[layer];
    const float boww = bow_s[layer];
    const float batw = bat_s[layer];

    int qg4[4];
    #pragma unroll
    for (int t = 0; t < 4; ++t) qg4[t] = q0 + rb0 + t*8;
    int bq4[4], aq4[4];

    float oacc[2][2][4];
    #pragma unroll
    for (int t = 0; t < 2; ++t)
        #pragma unroll
        for (int j = 0; j < 2; ++j)
            #pragma unroll
            for (int r = 0; r < 4; ++r) oacc[t][j][r] = 0.f;
    float mrun[4] = {-1e30f, -1e30f, -1e30f, -1e30f};
    float srun[4] = {0.f, 0.f, 0.f, 0.f};

    for (int kt = 0; kt < ktmax; ++kt) {
        int k0 = kt << 6;

        // ---- stage K (pure copies) ----
        #pragma unroll
        for (int it = 0; it < 2; ++it) {
            int idx = tid + it*256;
            int kk = idx >> 3, q = idx & 7;
            uint4 v = *(const uint4*)&qkv[(size_t)(b*Tc + k0 + kk)*QP + Dc + h*HDc + q*8];
            *(uint4*)&Ks[kk*36 + q*4] = v;
        }
        if (tid < 64) {
            int kg = k0 + tid;
            bowK[tid] = (kg < Sc) ? bowlers[b*Sc + kg] : -2;
            batK[tid] = (kg < Sc) ? batters[b*Sc + kg] : -2;
        }
        __syncthreads();   // S1

        #pragma unroll
        for (int t = 0; t < 4; ++t) {
            bq4[t] = bowQ[rb0 + t*8];
            aq4[t] = batQ[rb0 + t*8];
        }

        // ---- score MMA: fp16 ----
        float acc[2][2][4];
        #pragma unroll
        for (int t = 0; t < 2; ++t)
            #pragma unroll
            for (int j = 0; j < 2; ++j)
                #pragma unroll
                for (int r = 0; r < 4; ++r) acc[t][j][r] = 0.f;
        #pragma unroll
        for (int kc = 0; kc < 4; ++kc) {
            uint32_t bfr[2][2];
            #pragma unroll
            for (int j = 0; j < 2; ++j) {
                int rb = (nq*16 + j*8 + gid)*36 + kc*8 + tig;
                bfr[j][0] = Ks[rb];
                bfr[j][1] = Ks[rb + 4];
            }
            #pragma unroll
            for (int t = 0; t < 2; ++t) {
                int ra = (rb0 + t*16)*36 + kc*8 + tig;
                uint32_t a0 = Qs[ra];
                uint32_t a1 = Qs[ra + 8*36];
                uint32_t a2 = Qs[ra + 4];
                uint32_t a3 = Qs[ra + 8*36 + 4];
                #pragma unroll
                for (int j = 0; j < 2; ++j)
                    MMA_F16(acc[t][j], a0, a1, a2, a3, bfr[j][0], bfr[j][1]);
            }
        }

        // ---- stage V transposed: Vt[d][key] half2 pairs of adjacent keys ----
        {
            int m    = tid & 31;   // key pair 0..31
            int dgrp = tid >> 5;   // 8 groups of 8 d
            const uint32_t* r0 = (const uint32_t*)&qkv[(size_t)(b*Tc + k0 + 2*m    )*QP + 2*Dc + h*HDc + dgrp*8];
            const uint32_t* r1 = (const uint32_t*)&qkv[(size_t)(b*Tc + k0 + 2*m + 1)*QP + 2*Dc + h*HDc + dgrp*8];
            uint4 u0 = *(const uint4*)r0;
            uint4 u1 = *(const uint4*)r1;
            uint32_t u0a[4] = {u0.x, u0.y, u0.z, u0.w};
            uint32_t u1a[4] = {u1.x, u1.y, u1.z, u1.w};
            #pragma unroll
            for (int i = 0; i < 4; ++i) {
                uint32_t lo = __byte_perm(u0a[i], u1a[i], 0x5410); // (k0.lo, k1.lo)
                uint32_t hi = __byte_perm(u0a[i], u1a[i], 0x7632); // (k0.hi, k1.hi)
                int d = dgrp*8 + 2*i;
                Vt[(d    )*36 + m] = lo;
                Vt[(d + 1)*36 + m] = hi;
            }
        }

        // ---- score epilogue ----
        float sv[2][2][4];
        float rm[4] = {-1e30f, -1e30f, -1e30f, -1e30f};
        #pragma unroll
        for (int t = 0; t < 2; ++t) {
            #pragma unroll
            for (int j = 0; j < 2; ++j) {
                int kl = nq*16 + j*8 + 2*tig;
                int kg = k0 + kl;
                int row0 = 2*t, row1 = 2*t + 1;
                float s00 = acc[t][j][0]*scl, s01 = acc[t][j][1]*scl;
                float s10 = acc[t][j][2]*scl, s11 = acc[t][j][3]*scl;
                if (h == 0) {
                    float r0b = recw * (float)kg     * (1.0f/512.0f);
                    float r1b = recw * (float)(kg+1) * (1.0f/512.0f);
                    s00 += r0b; s01 += r1b; s10 += r0b; s11 += r1b;
                } else if (h == 1) {
                    int k1b = bowK[kl], k2b = bowK[kl+1];
                    if (qg4[row0] == Sc || kg   == Sc || bq4[row0] == k1b) s00 += boww;
                    if (qg4[row0] == Sc || kg+1 == Sc || bq4[row0] == k2b) s01 += boww;
                    if (qg4[row1] == Sc || kg   == Sc || bq4[row1] == k1b) s10 += boww;
                    if (qg4[row1] == Sc || kg+1 == Sc || bq4[row1] == k2b) s11 += boww;
                } else if (h == 2) {
                    int k1a = batK[kl], k2a = batK[kl+1];
                    if (qg4[row0] == Sc || kg   == Sc || aq4[row0] == k1a) s00 += batw;
                    if (qg4[row0] == Sc || kg+1 == Sc || aq4[row0] == k2a) s01 += batw;
                    if (qg4[row1] == Sc || kg   == Sc || aq4[row1] == k1a) s10 += batw;
                    if (qg4[row1] == Sc || kg+1 == Sc || aq4[row1] == k2a) s11 += batw;
                }
                if (kg   > qg4[row0]) s00 = -1e30f;
                if (kg+1 > qg4[row0]) s01 = -1e30f;
                if (kg   > qg4[row1]) s10 = -1e30f;
                if (kg+1 > qg4[row1]) s11 = -1e30f;
                sv[t][j][0] = s00; sv[t][j][1] = s01;
                sv[t][j][2] = s10; sv[t][j][3] = s11;
                rm[row0] = fmaxf(rm[row0], fmaxf(s00, s01));
                rm[row1] = fmaxf(rm[row1], fmaxf(s10, s11));
            }
        }
        #pragma unroll
        for (int t = 0; t < 4; ++t) {
            rm[t] = fmaxf(rm[t], __shfl_xor_sync(0xffffffffu, rm[t], 1));
            rm[t] = fmaxf(rm[t], __shfl_xor_sync(0xffffffffu, rm[t], 2));
        }
        if (tig == 0) {
            #pragma unroll
            for (int t = 0; t < 4; ++t) Mp[(rb0 + t*8)*4 + nq] = rm[t];
        }
        __syncthreads();   // S2a: Mp visible + Vt staged

        float mnew[4], f[4];
        #pragma unroll
        for (int t = 0; t < 4; ++t) {
            float4 m4 = *(const float4*)&Mp[(rb0 + t*8)*4];
            float mc = fmaxf(fmaxf(m4.x, m4.y), fmaxf(m4.z, m4.w));
            mnew[t] = fmaxf(mrun[t], mc);
            f[t] = __expf(mrun[t] - mnew[t]);
            mrun[t] = mnew[t];
        }

        // ---- exp, write P as half2, partial sums ----
        float ps[4] = {0.f, 0.f, 0.f, 0.f};
        #pragma unroll
        for (int t = 0; t < 2; ++t) {
            #pragma unroll
            for (int j = 0; j < 2; ++j) {
                int kp = nq*8 + j*4 + tig;   // key-pair index (kl/2)
                int row0 = 2*t, row1 = 2*t + 1;
                float e00 = __expf(sv[t][j][0] - mnew[row0]);
                float e01 = __expf(sv[t][j][1] - mnew[row0]);
                float e10 = __expf(sv[t][j][2] - mnew[row1]);
                float e11 = __expf(sv[t][j][3] - mnew[row1]);
                ps[row0] += e00 + e01;
                ps[row1] += e10 + e11;
                Ph[(rb0 + t*16    )*36 + kp] = h2_as_u32(__floats2half2_rn(e00, e01));
                Ph[(rb0 + t*16 + 8)*36 + kp] = h2_as_u32(__floats2half2_rn(e10, e11));
            }
        }
        #pragma unroll
        for (int t = 0; t < 4; ++t) {
            ps[t] += __shfl_xor_sync(0xffffffffu, ps[t], 1);
            ps[t] += __shfl_xor_sync(0xffffffffu, ps[t], 2);
        }
        if (tig == 0) {
            #pragma unroll
            for (int t = 0; t < 4; ++t) Sp[(rb0 + t*8)*4 + nq] = ps[t];
        }

        // rescale running accumulators
        #pragma unroll
        for (int t = 0; t < 2; ++t)
            #pragma unroll
            for (int j = 0; j < 2; ++j) {
                oacc[t][j][0] *= f[2*t];   oacc[t][j][1] *= f[2*t];
                oacc[t][j][2] *= f[2*t+1]; oacc[t][j][3] *= f[2*t+1];
            }
        __syncthreads();   // S2b: Ph + Sp visible

        #pragma unroll
        for (int t = 0; t < 4; ++t) {
            float4 s4 = *(const float4*)&Sp[(rb0 + t*8)*4];
            srun[t] = srun[t]*f[t] + (s4.x + s4.y + s4.z + s4.w);
        }

        // ---- AV MMA: fp16, P[q][key] x Vt[d][key]^T ----
        #pragma unroll
        for (int kc = 0; kc < 4; ++kc) {
            uint32_t vfr[2][2];
            #pragma unroll
            for (int j = 0; j < 2; ++j) {
                int n0 = (nq*2 + j)*8;
                int rv = (n0 + gid)*36 + kc*8 + tig;
                vfr[j][0] = Vt[rv];
                vfr[j][1] = Vt[rv + 4];
            }
            #pragma unroll
            for (int t = 0; t < 2; ++t) {
                int pa = (rb0 + t*16)*36 + kc*8 + tig;
                uint32_t a0 = Ph[pa];
                uint32_t a1 = Ph[pa + 8*36];
                uint32_t a2 = Ph[pa + 4];
                uint32_t a3 = Ph[pa + 8*36 + 4];
                #pragma unroll
                for (int j = 0; j < 2; ++j)
                    MMA_F16(oacc[t][j], a0, a1, a2, a3, vfr[j][0], vfr[j][1]);
            }
        }
    }

    float inv[4];
    #pragma unroll
    for (int t = 0; t < 4; ++t) inv[t] = 1.0f / srun[t];
    #pragma unroll
    for (int t = 0; t < 2; ++t) {
        #pragma unroll
        for (int j = 0; j < 2; ++j) {
            int col = (nq*2 + j)*8 + 2*tig;
            int row0 = q0 + rb0 + t*16, row1 = row0 + 8;
            *(__half2*)&Og[(size_t)(b*Tc + row0)*Dc + h*HDc + col] =
                __floats2half2_rn(oacc[t][j][0]*inv[2*t], oacc[t][j][1]*inv[2*t]);
            *(__half2*)&Og[(size_t)(b*Tc + row1)*Dc + h*HDc + col] =
                __floats2half2_rn(oacc[t][j][2]*inv[2*t+1], oacc[t][j][3]*inv[2*t+1]);
        }
    }
}

// ---------------- LayerNorm (input pre-summed): x = LN(tmp) ------------------
__global__ __launch_bounds__(256)
void ln_kernel(float* __restrict__ x, __half* __restrict__ x16,
               const float* __restrict__ tmp,
               const float* __restrict__ g, const float* __restrict__ be)
{
    int w = threadIdx.x >> 5;
    int lane = threadIdx.x & 31;
    size_t tok = (size_t)blockIdx.x*8 + w;
    const float* tr = tmp + tok*Dc;
    float* xr = x + tok*Dc;
    __half* xh = x16 + tok*Dc;

    float4 v[4];
    float s = 0.f, s2 = 0.f;
    #pragma unroll
    for (int i = 0; i < 4; ++i) {
        int c = (lane + i*32)*4;
        float4 xv = *(const float4*)&tr[c];
        v[i] = xv;
        s  += xv.x + xv.y + xv.z + xv.w;
        s2 += xv.x*xv.x + xv.y*xv.y + xv.z*xv.z + xv.w*xv.w;
    }
    #pragma unroll
    for (int o = 16; o; o >>= 1) {
        s  += __shfl_xor_sync(0xffffffffu, s,  o);
        s2 += __shfl_xor_sync(0xffffffffu, s2, o);
    }
    float mu  = s * (1.0f/512.0f);
    float var = s2 * (1.0f/512.0f) - mu*mu;
    float rs  = rsqrtf(var + 1e-5f);
    #pragma unroll
    for (int i = 0; i < 4; ++i) {
        int c = (lane + i*32)*4;
        float4 gv = *(const float4*)&g[c];
        float4 bv = *(const float4*)&be[c];
        float4 y;
        y.x = (v[i].x - mu)*rs*gv.x + bv.x;
        y.y = (v[i].y - mu)*rs*gv.y + bv.y;
        y.z = (v[i].z - mu)*rs*gv.z + bv.z;
        y.w = (v[i].w - mu)*rs*gv.w + bv.w;
        *(float4*)&xr[c] = y;
        __half2* hp = (__half2*)&xh[c];
        hp[0] = __floats2half2_rn(y.x, y.y);
        hp[1] = __floats2half2_rn(y.z, y.w);
    }
}

// ---------------- output head: out[b] = x[b, T-1] @ Wout + bout -------------
__global__ __launch_bounds__(512)
void out_kernel(const float* __restrict__ x, const float* __restrict__ Wout,
                const float* __restrict__ bout, float* __restrict__ out)
{
    int b = blockIdx.x;
    int n = threadIdx.x;
    __shared__ float xs[512];
    xs[n] = x[(size_t)(b*Tc + Tc - 1)*Dc + n];
    __syncthreads();
    float acc = bout[n];
    #pragma unroll 8
    for (int d = 0; d < Dc; ++d)
        acc += xs[d] * Wout[(size_t)d*Dc + n];
    out[b*Dc + n] = acc;
}

// ---------------- launcher ---------------------------------------------------
extern "C" void kernel_launch(void* const* d_in, const int* in_sizes, int n_in,
                              void* d_out, int out_size)
{
    const float* runs    = (const float*)d_in[0];
    const float* wickets = (const float*)d_in[1];
    const float* overs   = (const float*)d_in[2];
    const int*   batters = (const int*)  d_in[3];
    const int*   bowlers = (const int*)  d_in[4];
    const float* pemb    = (const float*)d_in[5];
    const float* Wf      = (const float*)d_in[6];
    const float* bf      = (const float*)d_in[7];
    const float* qtok    = (const float*)d_in[8];
    const float* Wq      = (const float*)d_in[9];
    const float* bq      = (const float*)d_in[10];
    const float* Wk      = (const float*)d_in[11];
    const float* bk      = (const float*)d_in[12];
    const float* Wv      = (const float*)d_in[13];
    const float* bv      = (const float*)d_in[14];
    const float* Wo      = (const float*)d_in[15];
    const float* bo      = (const float*)d_in[16];
    const float* rec_s   = (const float*)d_in[17];
    const float* bow_s   = (const float*)d_in[18];
    const float* bat_s   = (const float*)d_in[19];
    const float* W1      = (const float*)d_in[20];
    const float* b1      = (const float*)d_in[21];
    const float* W2      = (const float*)d_in[22];
    const float* b2      = (const float*)d_in[23];
    const float* g1      = (const float*)d_in[24];
    const float* be1     = (const float*)d_in[25];
    const float* g2      = (const float*)d_in[26];
    const float* be2     = (const float*)d_in[27];
    const float* Wout    = (const float*)d_in[28];
    const float* bout    = (const float*)d_in[29];
    float* out = (float*)d_out;

    float *x_, *tmp_, *bqkv_;
    __half *x16_, *att16_, *qkv16_, *ff16_, *wqkvT_, *woT_, *w1T_, *w2T_;
    cudaGetSymbolAddress((void**)&x_,     g_x);
    cudaGetSymbolAddress((void**)&x16_,   g_x16);
    cudaGetSymbolAddress((void**)&att16_, g_att16);
    cudaGetSymbolAddress((void**)&tmp_,   g_tmp);
    cudaGetSymbolAddress((void**)&qkv16_, g_qkv16);
    cudaGetSymbolAddress((void**)&ff16_,  g_ff16);
    cudaGetSymbolAddress((void**)&wqkvT_, g_wqkvT);
    cudaGetSymbolAddress((void**)&woT_,   g_woT);
    cudaGetSymbolAddress((void**)&w1T_,   g_w1T);
    cudaGetSymbolAddress((void**)&w2T_,   g_w2T);
    cudaGetSymbolAddress((void**)&bqkv_,  g_bqkv);

    cudaFuncSetAttribute(attn11_kernel,
                         cudaFuncAttributeMaxDynamicSharedMemorySize, ATTN11_SMEM);
    cudaFuncSetAttribute(tg16_kernel<0>,
                         cudaFuncAttributeMaxDynamicSharedMemorySize, TG16_SMEM);
    cudaFuncSetAttribute(tg16_kernel<1>,
                         cudaFuncAttributeMaxDynamicSharedMemorySize, TG16_SMEM);
    cudaFuncSetAttribute(tg16_kernel<2>,
                         cudaFuncAttributeMaxDynamicSharedMemorySize, TG16_SMEM);

    transpose_cvt_kernel<<<dim3(Dc/32, Dc/32, Lc), 256>>>(
        Wq, wqkvT_,                     Dc, Dc, (size_t)Dc*Dc, (size_t)QP*Dc);
    transpose_cvt_kernel<<<dim3(Dc/32, Dc/32, Lc), 256>>>(
        Wk, wqkvT_ + (size_t)Dc*Dc,     Dc, Dc, (size_t)Dc*Dc, (size_t)QP*Dc);
    transpose_cvt_kernel<<<dim3(Dc/32, Dc/32, Lc), 256>>>(
        Wv, wqkvT_ + (size_t)2*Dc*Dc,   Dc, Dc, (size_t)Dc*Dc, (size_t)QP*Dc);
    transpose_cvt_kernel<<<dim3(Dc/32, Dc/32, Lc), 256>>>(
        Wo, woT_,                       Dc, Dc, (size_t)Dc*Dc, (size_t)Dc*Dc);
    transpose_cvt_kernel<<<dim3(DFFc/32, Dc/32, Lc), 256>>>(
        W1, w1T_,                       Dc, DFFc, (size_t)Dc*DFFc, (size_t)DFFc*Dc);
    transpose_cvt_kernel<<<dim3(Dc/32, DFFc/32, Lc), 256>>>(
        W2, w2T_,                       DFFc, Dc, (size_t)DFFc*Dc, (size_t)Dc*DFFc);
    pack_bqkv_kernel<<<Lc, 512>>>(bq, bk, bv, bqkv_);

    embed_kernel<<<Bc*Tc, 512>>>(runs, wickets, overs, batters, bowlers,
                                 pemb, Wf, bf, qtok, x_, x16_);

    dim3 g512 (Dc/128,   Mc/128);
    dim3 gQKV (QP/128,   Mc/128);
    dim3 g2048(DFFc/128, Mc/128);
    dim3 gattn(8, Hc, Bc);

    for (int l = 0; l < Lc; ++l) {
        tg16_kernel<1><<<gQKV, 256, TG16_SMEM>>>(
            x16_, wqkvT_ + (size_t)l*QP*Dc, bqkv_ + l*QP, qkv16_, Mc, QP, Dc, nullptr);

        attn11_kernel<<<gattn, 256, ATTN11_SMEM>>>(qkv16_, batters, bowlers,
                                                   rec_s, bow_s, bat_s, l, att16_);

        tg16_kernel<0><<<g512, 256, TG16_SMEM>>>(
            att16_, woT_ + (size_t)l*Dc*Dc, bo + l*Dc, tmp_, Mc, Dc, Dc, x_);
        ln_kernel<<<Mc/8, 256>>>(x_, x16_, tmp_, g1 + l*Dc, be1 + l*Dc);

        tg16_kernel<2><<<g2048, 256, TG16_SMEM>>>(
            x16_, w1T_ + (size_t)l*DFFc*Dc, b1 + l*DFFc, ff16_, Mc, DFFc, Dc, nullptr);
        tg16_kernel<0><<<g512, 256, TG16_SMEM>>>(
            ff16_, w2T_ + (size_t)l*Dc*DFFc, b2 + l*Dc, tmp_, Mc, Dc, DFFc, x_);
        ln_kernel<<<Mc/8, 256>>>(x_, x16_, tmp_, g2 + l*Dc, be2 + l*Dc);
    }

    out_kernel<<<Bc, 512>>>(x_, Wout, bout, out);
}